// round 3
// baseline (speedup 1.0000x reference)
#include <cuda_runtime.h>
#include <cuda_bf16.h>
#include <math.h>
#include <stdint.h>

#define NBATCH 16
#define NPRI   119130
#define TOPK   2000
#define KEEPK  750
#define CAP    8192
#define NBINS  65536

// Level layout (IMG 1920x1080, steps {8,16,32,64}):
// L0: off 0      cnt 97200  fw 240 step 8  nms 3  sizes {10,16,24}
// L1: off 97200  cnt 16320  fw 120 step 16 nms 2  sizes {32,48}
// L2: off 113520 cnt 4080   fw 60  step 32 nms 2  sizes {64,96}
// L3: off 117600 cnt 1530   fw 30  step 64 nms 3  sizes {128,192,256}

__device__ float              g_scores[NBATCH * NPRI];
__device__ unsigned int       g_hist[NBATCH * NBINS];
__device__ int                g_pivot[NBATCH];
__device__ int                g_selcnt[NBATCH];
__device__ unsigned long long g_sel[NBATCH * CAP];

// Correctly-rounded expf: double exp (<=1 double-ulp) rounded once to float.
// Matches CPU (glibc double-internal expf) bit-for-bit w.h.p.
__device__ __forceinline__ float expf_cr(float x) {
    return (float)exp((double)x);
}

// ---------------------------------------------------------------------------
// K1: fused score computation + per-batch histogram of top-16 float bits.
// Bit-exact to CPU: softmax(conf)[...,1] (stable, CR exp), clip, sqrt, >=0.3.
// ---------------------------------------------------------------------------
__global__ void k_scores(const float* __restrict__ conf,
                         const float* __restrict__ iou) {
    int i = blockIdx.x * blockDim.x + threadIdx.x;
    int total = NBATCH * NPRI;
    if (i >= total) return;

    float u = iou[i];
    u = fminf(fmaxf(u, 0.0f), 1.0f);

    float s = 0.0f;
    if (u > 0.0f) {
        float c0 = conf[2 * i];
        float c1 = conf[2 * i + 1];
        // cheap conservative prefilter (__expf rel err ~1e-6 << 3% margin)
        float pf = 1.0f / (1.0f + __expf(c0 - c1));
        float sf = sqrtf(pf * u);
        if (sf >= 0.29f) {
            // exact path, bit-identical to stable softmax on CPU:
            // mx = max(c0,c1); e_i = expf(c_i - mx); p = e1/(e0+e1)
            // one of the exps is exp(0) == 1.0 exactly.
            float p;
            if (c1 >= c0) {
                float e0 = expf_cr(__fsub_rn(c0, c1));
                p = __fdiv_rn(1.0f, __fadd_rn(e0, 1.0f));
            } else {
                float e1 = expf_cr(__fsub_rn(c1, c0));
                p = __fdiv_rn(e1, __fadd_rn(1.0f, e1));
            }
            float sv = __fsqrt_rn(__fmul_rn(p, u));
            s = (sv >= 0.3f) ? sv : 0.0f;
        }
    }
    g_scores[i] = s;
    if (s > 0.0f) {
        int b = i / NPRI;
        unsigned bin = __float_as_uint(s) >> 16;
        atomicAdd(&g_hist[b * NBINS + bin], 1u);
    }
}

// ---------------------------------------------------------------------------
// K2: per-batch radix-select pivot bin. Also resets the selection counter.
// ---------------------------------------------------------------------------
__global__ void k_pivot() {
    int b = blockIdx.x;
    int t = threadIdx.x;
    __shared__ unsigned cs[1024];
    unsigned s = 0;
    const unsigned* h = g_hist + b * NBINS + t * 64;
#pragma unroll 8
    for (int k = 0; k < 64; k++) s += h[k];
    cs[t] = s;
    __syncthreads();
    if (t == 0) {
        g_selcnt[b] = 0;
        unsigned acc = 0;
        for (int c = 1023; c >= 0; c--) {
            unsigned na = acc + cs[c];
            if (na >= TOPK) {
                unsigned a2 = acc;
                const unsigned* hh = g_hist + b * NBINS + c * 64;
                int pivot = 0;
                for (int k2 = 63; k2 >= 0; k2--) {
                    a2 += hh[k2];
                    if (a2 >= TOPK) { pivot = c * 64 + k2; break; }
                }
                g_pivot[b] = pivot;
                return;
            }
            acc = na;
        }
        g_pivot[b] = 0;  // fewer than TOPK candidates: take all
    }
}

// ---------------------------------------------------------------------------
// K3: compact candidates with bin >= pivot into per-batch buffers.
//     Key = (score_bits << 32) | (0x7FFFFFFF - idx): descending sort on key
//     == score desc, index asc (jax.lax.top_k tie order).
// ---------------------------------------------------------------------------
__global__ void k_compact() {
    int i = blockIdx.x * blockDim.x + threadIdx.x;
    int total = NBATCH * NPRI;
    if (i >= total) return;
    float s = g_scores[i];
    if (s <= 0.0f) return;
    int b = i / NPRI;
    unsigned bin = __float_as_uint(s) >> 16;
    if ((int)bin < g_pivot[b]) return;
    int pos = atomicAdd(&g_selcnt[b], 1);
    if (pos < CAP) {
        int idx = i - b * NPRI;
        unsigned long long key =
            ((unsigned long long)__float_as_uint(s) << 32) |
            (unsigned)(0x7FFFFFFF - idx);
        g_sel[b * CAP + pos] = key;
    }
}

// ---------------------------------------------------------------------------
// Prior from flat index (double math matches numpy f64 -> f32 cast)
// ---------------------------------------------------------------------------
__device__ __forceinline__ void prior_of(int idx, float& pcx, float& pcy,
                                         float& pw, float& ph) {
    int off, fw, step, nm;
    double ms;
    if (idx < 97200) {
        off = 0; fw = 240; step = 8; nm = 3;
        int mi = (idx - off) % 3;
        ms = (mi == 0) ? 10.0 : (mi == 1) ? 16.0 : 24.0;
    } else if (idx < 113520) {
        off = 97200; fw = 120; step = 16; nm = 2;
        int mi = (idx - off) % 2;
        ms = (mi == 0) ? 32.0 : 48.0;
    } else if (idx < 117600) {
        off = 113520; fw = 60; step = 32; nm = 2;
        int mi = (idx - off) % 2;
        ms = (mi == 0) ? 64.0 : 96.0;
    } else {
        off = 117600; fw = 30; step = 64; nm = 3;
        int mi = (idx - off) % 3;
        ms = (mi == 0) ? 128.0 : (mi == 1) ? 192.0 : 256.0;
    }
    int r = idx - off;
    int cell = r / nm;
    int row = cell / fw;
    int col = cell - row * fw;
    pcx = (float)(((double)col + 0.5) * (double)step / 1920.0);
    pcy = (float)(((double)row + 0.5) * (double)step / 1080.0);
    pw  = (float)(ms / 1920.0);
    ph  = (float)(ms / 1080.0);
}

// ---------------------------------------------------------------------------
// K4: per-batch: bitonic sort (8192 keys) -> top-2000 -> decode (bit-exact,
//     CR exp, no FMA) -> greedy NMS (IEEE rn) -> keep<=750 cumsum -> scores.
// Dynamic smem layout:
//   [0, 65536)        : ull keys[8192]   (later aliased by SoA boxes 4x2000)
//   [65536, 73728)    : float ss[2048]
//   [73728, 81920)    : int   act[2048]
// ---------------------------------------------------------------------------
__global__ void k_final(const float* __restrict__ loc, float* __restrict__ out) {
    extern __shared__ unsigned char smem[];
    unsigned long long* keys = (unsigned long long*)smem;
    float* ss  = (float*)(smem + 65536);
    int*   act = (int*)(smem + 65536 + 8192);
    float* bxx1 = (float*)smem;          // alias keys after extraction
    float* bxy1 = bxx1 + 2000;
    float* bxx2 = bxx1 + 4000;
    float* bxy2 = bxx1 + 6000;
    __shared__ int wtot[33];

    int b = blockIdx.x;
    int tid = threadIdx.x;

    int m = g_selcnt[b];
    if (m > CAP) m = CAP;
    for (int i = tid; i < CAP; i += 1024)
        keys[i] = (i < m) ? g_sel[b * CAP + i] : 0ULL;

    // bitonic sort, descending
    for (int k = 2; k <= CAP; k <<= 1) {
        for (int j = k >> 1; j > 0; j >>= 1) {
            __syncthreads();
            for (int i = tid; i < CAP; i += 1024) {
                int l = i ^ j;
                if (l > i) {
                    unsigned long long a = keys[i], bb = keys[l];
                    bool up = ((i & k) == 0);
                    if (up ? (a < bb) : (a > bb)) { keys[i] = bb; keys[l] = a; }
                }
            }
        }
    }
    __syncthreads();

    // extract top-2000 (score, idx); pad to 2048
    for (int r = tid; r < 2048; r += 1024) {
        if (r < TOPK) {
            unsigned long long kk = keys[r];
            float sc = __uint_as_float((unsigned)(kk >> 32));
            int idx = 0x7FFFFFFF - (int)(unsigned)(kk & 0xFFFFFFFFu);
            if (idx < 0 || idx >= NPRI) idx = 0;
            ss[r] = sc;
            act[r] = idx;
        } else {
            ss[r] = 0.0f;
            act[r] = 0;
        }
    }
    __syncthreads();

    // decode + write box/landmarks (all ops IEEE rn, CR exp, no contraction)
    for (int r = tid; r < TOPK; r += 1024) {
        int idx = act[r];
        float pcx, pcy, pw, ph;
        prior_of(idx, pcx, pcy, pw, ph);
        const float* lp = loc + ((size_t)b * NPRI + (size_t)idx) * 14;
        float l[14];
#pragma unroll
        for (int c = 0; c < 14; c++) l[c] = lp[c];

        float cx = __fadd_rn(pcx, __fmul_rn(__fmul_rn(l[0], 0.1f), pw));
        float cy = __fadd_rn(pcy, __fmul_rn(__fmul_rn(l[1], 0.1f), ph));
        float w  = __fmul_rn(pw, expf_cr(__fmul_rn(l[2], 0.1f)));
        float h  = __fmul_rn(ph, expf_cr(__fmul_rn(l[3], 0.2f)));
        float x1 = __fsub_rn(cx, __fmul_rn(w, 0.5f));
        float y1 = __fsub_rn(cy, __fmul_rn(h, 0.5f));
        float x2 = __fadd_rn(x1, w);
        float y2 = __fadd_rn(y1, h);

        float* op = out + ((size_t)b * TOPK + (size_t)r) * 15;
        float X1 = __fmul_rn(x1, 1920.0f), Y1 = __fmul_rn(y1, 1080.0f);
        float X2 = __fmul_rn(x2, 1920.0f), Y2 = __fmul_rn(y2, 1080.0f);
        op[0] = X1; op[1] = Y1; op[2] = X2; op[3] = Y2;
#pragma unroll
        for (int kk2 = 0; kk2 < 5; kk2++) {
            float lx = __fadd_rn(pcx, __fmul_rn(__fmul_rn(l[4 + 2 * kk2], 0.1f), pw));
            float ly = __fadd_rn(pcy, __fmul_rn(__fmul_rn(l[5 + 2 * kk2], 0.1f), ph));
            op[4 + 2 * kk2] = __fmul_rn(lx, 1920.0f);
            op[5 + 2 * kk2] = __fmul_rn(ly, 1080.0f);
        }
        bxx1[r] = X1; bxy1[r] = Y1; bxx2[r] = X2; bxy2[r] = Y2;
        act[r] = (ss[r] > 0.0f) ? 1 : 0;
    }
    __syncthreads();

    // greedy NMS, sequential over sorted ranks (IEEE rn math)
    for (int i = 0; i < TOPK; i++) {
        if (act[i]) {
            float xi1 = bxx1[i], yi1 = bxy1[i], xi2 = bxx2[i], yi2 = bxy2[i];
            float ai = __fmul_rn(fmaxf(__fsub_rn(xi2, xi1), 0.0f),
                                 fmaxf(__fsub_rn(yi2, yi1), 0.0f));
            for (int j = i + 1 + tid; j < TOPK; j += 1024) {
                if (act[j]) {
                    float xj1 = bxx1[j], yj1 = bxy1[j];
                    float xj2 = bxx2[j], yj2 = bxy2[j];
                    float aj = __fmul_rn(fmaxf(__fsub_rn(xj2, xj1), 0.0f),
                                         fmaxf(__fsub_rn(yj2, yj1), 0.0f));
                    float lx = fmaxf(xi1, xj1), ly = fmaxf(yi1, yj1);
                    float rx = fminf(xi2, xj2), ry = fminf(yi2, yj2);
                    float iw = fmaxf(__fsub_rn(rx, lx), 0.0f);
                    float ih = fmaxf(__fsub_rn(ry, ly), 0.0f);
                    float inter = __fmul_rn(iw, ih);
                    float denom = __fadd_rn(
                        __fsub_rn(__fadd_rn(ai, aj), inter), 1e-9f);
                    float iouv = __fdiv_rn(inter, denom);
                    if (iouv > 0.3f) act[j] = 0;
                }
            }
        }
        __syncthreads();
    }

    // inclusive cumsum over keep flags; KEEP_TOP_K cap; write col 14
    int lane = tid & 31, warp = tid >> 5;
    int a0 = act[2 * tid];
    int a1 = act[2 * tid + 1];
    int ps = a0 + a1;
    int v = ps;
#pragma unroll
    for (int o = 1; o < 32; o <<= 1) {
        int u = __shfl_up_sync(0xffffffffu, v, o);
        if (lane >= o) v += u;
    }
    if (lane == 31) wtot[warp] = v;
    __syncthreads();
    if (warp == 0) {
        int w = wtot[lane];
#pragma unroll
        for (int o = 1; o < 32; o <<= 1) {
            int u = __shfl_up_sync(0xffffffffu, w, o);
            if (lane >= o) w += u;
        }
        wtot[lane] = w;
    }
    __syncthreads();
    int base = (warp ? wtot[warp - 1] : 0) + v - ps;  // exclusive before pair
    int c0 = base + a0;
    int c1 = c0 + a1;
    int e0 = 2 * tid, e1 = 2 * tid + 1;
    if (e0 < TOPK)
        out[((size_t)b * TOPK + e0) * 15 + 14] =
            ss[e0] * ((a0 && c0 <= KEEPK) ? 1.0f : 0.0f);
    if (e1 < TOPK)
        out[((size_t)b * TOPK + e1) * 15 + 14] =
            ss[e1] * ((a1 && c1 <= KEEPK) ? 1.0f : 0.0f);
}

// ---------------------------------------------------------------------------
extern "C" void kernel_launch(void* const* d_in, const int* in_sizes, int n_in,
                              void* d_out, int out_size) {
    const float* loc = nullptr;
    const float* conf = nullptr;
    const float* iou = nullptr;
    for (int i = 0; i < n_in; i++) {
        if (in_sizes[i] == NBATCH * NPRI * 14) loc = (const float*)d_in[i];
        else if (in_sizes[i] == NBATCH * NPRI * 2) conf = (const float*)d_in[i];
        else if (in_sizes[i] == NBATCH * NPRI) iou = (const float*)d_in[i];
    }
    float* out = (float*)d_out;

    void* hist_ptr = nullptr;
    cudaGetSymbolAddress(&hist_ptr, g_hist);
    cudaMemsetAsync(hist_ptr, 0, sizeof(unsigned) * NBATCH * NBINS, 0);

    int total = NBATCH * NPRI;
    int blocks = (total + 255) / 256;
    k_scores<<<blocks, 256>>>(conf, iou);
    k_pivot<<<NBATCH, 1024>>>();
    k_compact<<<blocks, 256>>>();

    static_assert(65536 + 8192 + 8192 == 81920, "smem layout");
    cudaFuncSetAttribute(k_final, cudaFuncAttributeMaxDynamicSharedMemorySize,
                         98304);
    k_final<<<NBATCH, 1024, 81920>>>(loc, out);
}

// round 4
// speedup vs baseline: 1.1252x; 1.1252x over previous
#include <cuda_runtime.h>
#include <cuda_bf16.h>
#include <math.h>
#include <stdint.h>

#define NBATCH 16
#define NPRI   119130
#define TOPK   2000
#define KEEPK  750
#define CAP    8192
#define NBINS  65536
#define TARGET 2300   // pivot margin over TOPK (absorbs 1e-6 approx error)

// Level layout (IMG 1920x1080, steps {8,16,32,64}):
// L0: off 0      cnt 97200  fw 240 step 8  nms 3  sizes {10,16,24}
// L1: off 97200  cnt 16320  fw 120 step 16 nms 2  sizes {32,48}
// L2: off 113520 cnt 4080   fw 60  step 32 nms 2  sizes {64,96}
// L3: off 117600 cnt 1530   fw 30  step 64 nms 3  sizes {128,192,256}

__device__ float              g_sapprox[NBATCH * NPRI];
__device__ unsigned int       g_hist[NBATCH * NBINS];
__device__ int                g_pivot[NBATCH];
__device__ int                g_selcnt[NBATCH];
__device__ int                g_selidx[NBATCH * CAP];
__device__ unsigned long long g_sel[NBATCH * CAP];
__device__ unsigned long long g_top[NBATCH * 2048];
__device__ float              g_boxes[NBATCH * 4 * 2048];

// ---------------------------------------------------------------------------
// Fast fp64 exp, error ~2^-51 (CR float result w.p. 1-2^-27 per call).
// ~17 fp64 ops vs libdevice ~35.
// ---------------------------------------------------------------------------
__device__ __forceinline__ double exp_pd(double x) {
    double t = x * 1.4426950408889634073599246810019;  // log2(e)
    int ni = __double2int_rn(t);
    double nd = (double)ni;
    double r = fma(nd, -6.93147180369123816490e-01, x);  // ln2_hi (20 low 0s)
    r = fma(nd, -1.90821492927058770002e-10, r);         // ln2_lo
    double p = 1.0 / 6227020800.0;                       // 1/13!
    p = fma(p, r, 1.0 / 479001600.0);
    p = fma(p, r, 1.0 / 39916800.0);
    p = fma(p, r, 1.0 / 3628800.0);
    p = fma(p, r, 1.0 / 362880.0);
    p = fma(p, r, 1.0 / 40320.0);
    p = fma(p, r, 1.0 / 5040.0);
    p = fma(p, r, 1.0 / 720.0);
    p = fma(p, r, 1.0 / 120.0);
    p = fma(p, r, 1.0 / 24.0);
    p = fma(p, r, 1.0 / 6.0);
    p = fma(p, r, 0.5);
    p = fma(p, r, 1.0);
    p = fma(p, r, 1.0);
    double sc = __longlong_as_double((long long)(ni + 1023) << 52);
    return p * sc;
}

// exact float softmax prob of class1 (stable, CR exp), matches CPU reference
__device__ __forceinline__ float softmax1_exact(float c0, float c1) {
    if (c1 >= c0) {
        float e0 = (float)exp_pd((double)__fsub_rn(c0, c1));
        return __fdiv_rn(1.0f, __fadd_rn(e0, 1.0f));
    } else {
        float e1 = (float)exp_pd((double)__fsub_rn(c1, c0));
        return __fdiv_rn(e1, __fadd_rn(1.0f, e1));
    }
}

// ---------------------------------------------------------------------------
// K1: approximate scores (pure fp32) + per-batch histogram (float bits >> 16)
// ---------------------------------------------------------------------------
__global__ void k_scores(const float2* __restrict__ conf,
                         const float* __restrict__ iou) {
    int i = blockIdx.x * blockDim.x + threadIdx.x;
    if (i >= NBATCH * NPRI) return;
    float u = iou[i];
    u = fminf(fmaxf(u, 0.0f), 1.0f);
    float s = 0.0f;
    if (u > 0.0f) {
        float2 c = conf[i];
        float pf = 1.0f / (1.0f + __expf(c.x - c.y));  // rel err ~1e-6
        float sf = sqrtf(pf * u);
        if (sf >= 0.299f) s = sf;                       // guard band
    }
    g_sapprox[i] = s;
    if (s > 0.0f) {
        int b = i / NPRI;
        unsigned bin = __float_as_uint(s) >> 16;
        atomicAdd(&g_hist[b * NBINS + bin], 1u);
    }
}

// ---------------------------------------------------------------------------
// K2: per-batch radix-select pivot bin (cum count >= TARGET); reset counter
// ---------------------------------------------------------------------------
__global__ void k_pivot() {
    int b = blockIdx.x;
    int t = threadIdx.x;
    __shared__ unsigned cs[1024];
    unsigned s = 0;
    const unsigned* h = g_hist + b * NBINS + t * 64;
#pragma unroll 8
    for (int k = 0; k < 64; k++) s += h[k];
    cs[t] = s;
    __syncthreads();
    if (t == 0) {
        g_selcnt[b] = 0;
        unsigned acc = 0;
        for (int c = 1023; c >= 0; c--) {
            unsigned na = acc + cs[c];
            if (na >= TARGET) {
                unsigned a2 = acc;
                const unsigned* hh = g_hist + b * NBINS + c * 64;
                int pivot = 0;
                for (int k2 = 63; k2 >= 0; k2--) {
                    a2 += hh[k2];
                    if (a2 >= TARGET) { pivot = c * 64 + k2; break; }
                }
                g_pivot[b] = pivot;
                return;
            }
            acc = na;
        }
        g_pivot[b] = 0;
    }
}

// ---------------------------------------------------------------------------
// K3a: compact candidate INDICES (approx bin >= pivot)
// ---------------------------------------------------------------------------
__global__ void k_compact() {
    int i = blockIdx.x * blockDim.x + threadIdx.x;
    if (i >= NBATCH * NPRI) return;
    float s = g_sapprox[i];
    if (s <= 0.0f) return;
    int b = i / NPRI;
    unsigned bin = __float_as_uint(s) >> 16;
    if ((int)bin < g_pivot[b]) return;
    int pos = atomicAdd(&g_selcnt[b], 1);
    if (pos < CAP) g_selidx[b * CAP + pos] = i - b * NPRI;
}

// ---------------------------------------------------------------------------
// K3b: dense exact rescore of compacted candidates (CR score).
//      Key = (score_bits << 32) | (0x7FFFFFFF - idx) : desc sort on key ==
//      score desc, idx asc (jax.lax.top_k tie order). Zero-fills padding.
// ---------------------------------------------------------------------------
__global__ void k_rescore(const float2* __restrict__ conf,
                          const float* __restrict__ iou) {
    int gid = blockIdx.x * blockDim.x + threadIdx.x;
    if (gid >= NBATCH * CAP) return;
    int b = gid / CAP;
    int pos = gid - b * CAP;
    unsigned long long key = 0ULL;
    int m = g_selcnt[b];
    if (m > CAP) m = CAP;
    if (pos < m) {
        int idx = g_selidx[b * CAP + pos];
        size_t e = (size_t)b * NPRI + (size_t)idx;
        float2 c = conf[e];
        float u = iou[e];
        u = fminf(fmaxf(u, 0.0f), 1.0f);
        float p = softmax1_exact(c.x, c.y);
        float s = __fsqrt_rn(__fmul_rn(p, u));
        if (s >= 0.3f)
            key = ((unsigned long long)__float_as_uint(s) << 32) |
                  (unsigned)(0x7FFFFFFF - idx);
    }
    g_sel[gid] = key;
}

// ---------------------------------------------------------------------------
// K4: per-batch bitonic sort (desc) of candidate keys; emit top-2048
// ---------------------------------------------------------------------------
__global__ void k_sort() {
    extern __shared__ unsigned long long keys[];
    int b = blockIdx.x;
    int tid = threadIdx.x;
    int m = g_selcnt[b];
    if (m > CAP) m = CAP;
    int nk = (m <= 2048) ? 2048 : ((m <= 4096) ? 4096 : 8192);
    for (int i = tid; i < nk; i += 1024)
        keys[i] = g_sel[b * CAP + i];   // zero-padded by k_rescore
    for (int k = 2; k <= nk; k <<= 1) {
        for (int j = k >> 1; j > 0; j >>= 1) {
            __syncthreads();
            for (int i = tid; i < nk; i += 1024) {
                int l = i ^ j;
                if (l > i) {
                    unsigned long long a = keys[i], bb = keys[l];
                    bool up = ((i & k) == 0);
                    if (up ? (a < bb) : (a > bb)) { keys[i] = bb; keys[l] = a; }
                }
            }
        }
    }
    __syncthreads();
    for (int r = tid; r < 2048; r += 1024)
        g_top[b * 2048 + r] = (r < nk) ? keys[r] : 0ULL;
}

// min_size tables: level offsets {0,3,5,7}
__constant__ float PW[10] = {
    (float)(10.0/1920.0),(float)(16.0/1920.0),(float)(24.0/1920.0),
    (float)(32.0/1920.0),(float)(48.0/1920.0),
    (float)(64.0/1920.0),(float)(96.0/1920.0),
    (float)(128.0/1920.0),(float)(192.0/1920.0),(float)(256.0/1920.0)};
__constant__ float PH[10] = {
    (float)(10.0/1080.0),(float)(16.0/1080.0),(float)(24.0/1080.0),
    (float)(32.0/1080.0),(float)(48.0/1080.0),
    (float)(64.0/1080.0),(float)(96.0/1080.0),
    (float)(128.0/1080.0),(float)(192.0/1080.0),(float)(256.0/1080.0)};

__device__ __forceinline__ void prior_of(int idx, float& pcx, float& pcy,
                                         float& pw, float& ph) {
    int off, fw, step, nm, msoff;
    if (idx < 97200)       { off = 0;      fw = 240; step = 8;  nm = 3; msoff = 0; }
    else if (idx < 113520) { off = 97200;  fw = 120; step = 16; nm = 2; msoff = 3; }
    else if (idx < 117600) { off = 113520; fw = 60;  step = 32; nm = 2; msoff = 5; }
    else                   { off = 117600; fw = 30;  step = 64; nm = 3; msoff = 7; }
    int r = idx - off;
    int cell = r / nm;
    int mi = r - cell * nm;
    int row = cell / fw;
    int col = cell - row * fw;
    // ((col+0.5)*step) exact in double; * CR reciprocal == true division
    // at float precision w.p. 1-2^-29 per value
    double tx = ((double)col + 0.5) * (double)step;
    double ty = ((double)row + 0.5) * (double)step;
    pcx = (float)(tx * (1.0 / 1920.0));
    pcy = (float)(ty * (1.0 / 1080.0));
    pw = PW[msoff + mi];
    ph = PH[msoff + mi];
}

// ---------------------------------------------------------------------------
// K5: full-chip decode of top-2000 rows: out cols 0..13 + box SoA for NMS
// ---------------------------------------------------------------------------
__global__ void k_decode(const float* __restrict__ loc,
                         float* __restrict__ out) {
    int row = blockIdx.x * blockDim.x + threadIdx.x;
    if (row >= NBATCH * TOPK) return;
    int b = row / TOPK;
    int r = row - b * TOPK;
    unsigned long long kk = g_top[b * 2048 + r];
    int idx = 0x7FFFFFFF - (int)(unsigned)(kk & 0xFFFFFFFFu);
    if (idx < 0 || idx >= NPRI) idx = 0;

    float pcx, pcy, pw, ph;
    prior_of(idx, pcx, pcy, pw, ph);
    const float* lp = loc + ((size_t)b * NPRI + (size_t)idx) * 14;
    float l[14];
#pragma unroll
    for (int c = 0; c < 14; c++) l[c] = lp[c];

    float cx = __fadd_rn(pcx, __fmul_rn(__fmul_rn(l[0], 0.1f), pw));
    float cy = __fadd_rn(pcy, __fmul_rn(__fmul_rn(l[1], 0.1f), ph));
    float w  = __fmul_rn(pw, (float)exp_pd((double)__fmul_rn(l[2], 0.1f)));
    float h  = __fmul_rn(ph, (float)exp_pd((double)__fmul_rn(l[3], 0.2f)));
    float x1 = __fsub_rn(cx, __fmul_rn(w, 0.5f));
    float y1 = __fsub_rn(cy, __fmul_rn(h, 0.5f));
    float x2 = __fadd_rn(x1, w);
    float y2 = __fadd_rn(y1, h);

    float* op = out + (size_t)row * 15;
    float X1 = __fmul_rn(x1, 1920.0f), Y1 = __fmul_rn(y1, 1080.0f);
    float X2 = __fmul_rn(x2, 1920.0f), Y2 = __fmul_rn(y2, 1080.0f);
    op[0] = X1; op[1] = Y1; op[2] = X2; op[3] = Y2;
#pragma unroll
    for (int k = 0; k < 5; k++) {
        float lx = __fadd_rn(pcx, __fmul_rn(__fmul_rn(l[4 + 2 * k], 0.1f), pw));
        float ly = __fadd_rn(pcy, __fmul_rn(__fmul_rn(l[5 + 2 * k], 0.1f), ph));
        op[4 + 2 * k] = __fmul_rn(lx, 1920.0f);
        op[5 + 2 * k] = __fmul_rn(ly, 1080.0f);
    }
    g_boxes[b * 8192 + 0 * 2048 + r] = X1;
    g_boxes[b * 8192 + 1 * 2048 + r] = Y1;
    g_boxes[b * 8192 + 2 * 2048 + r] = X2;
    g_boxes[b * 8192 + 3 * 2048 + r] = Y2;
}

// ---------------------------------------------------------------------------
// K6: per-batch greedy NMS (smem) + KEEP_TOP_K cumsum -> out col 14
// Dynamic smem: bxx1/bxy1/bxx2/bxy2 [2000] each, ss[2048], act[2048]
// ---------------------------------------------------------------------------
__global__ void k_nms(float* __restrict__ out) {
    extern __shared__ unsigned char smem[];
    float* bxx1 = (float*)smem;
    float* bxy1 = bxx1 + 2000;
    float* bxx2 = bxx1 + 4000;
    float* bxy2 = bxx1 + 6000;
    float* ss   = bxx1 + 8000;            // [2048]
    int*   act  = (int*)(bxx1 + 10048);   // [2048]
    __shared__ int wtot[33];

    int b = blockIdx.x;
    int tid = threadIdx.x;

    for (int r = tid; r < 2048; r += 1024) {
        if (r < TOPK) {
            unsigned long long kk = g_top[b * 2048 + r];
            float sc = __uint_as_float((unsigned)(kk >> 32));
            ss[r] = sc;
            act[r] = (sc > 0.0f) ? 1 : 0;
            bxx1[r] = g_boxes[b * 8192 + 0 * 2048 + r];
            bxy1[r] = g_boxes[b * 8192 + 1 * 2048 + r];
            bxx2[r] = g_boxes[b * 8192 + 2 * 2048 + r];
            bxy2[r] = g_boxes[b * 8192 + 3 * 2048 + r];
        } else {
            ss[r] = 0.0f;
            act[r] = 0;
        }
    }
    __syncthreads();

    for (int i = 0; i < TOPK; i++) {
        if (act[i]) {
            float xi1 = bxx1[i], yi1 = bxy1[i], xi2 = bxx2[i], yi2 = bxy2[i];
            float ai = __fmul_rn(fmaxf(__fsub_rn(xi2, xi1), 0.0f),
                                 fmaxf(__fsub_rn(yi2, yi1), 0.0f));
            for (int j = i + 1 + tid; j < TOPK; j += 1024) {
                if (act[j]) {
                    float xj1 = bxx1[j], yj1 = bxy1[j];
                    float xj2 = bxx2[j], yj2 = bxy2[j];
                    float aj = __fmul_rn(fmaxf(__fsub_rn(xj2, xj1), 0.0f),
                                         fmaxf(__fsub_rn(yj2, yj1), 0.0f));
                    float lx = fmaxf(xi1, xj1), ly = fmaxf(yi1, yj1);
                    float rx = fminf(xi2, xj2), ry = fminf(yi2, yj2);
                    float iw = fmaxf(__fsub_rn(rx, lx), 0.0f);
                    float ih = fmaxf(__fsub_rn(ry, ly), 0.0f);
                    float inter = __fmul_rn(iw, ih);
                    float denom = __fadd_rn(
                        __fsub_rn(__fadd_rn(ai, aj), inter), 1e-9f);
                    if (__fdiv_rn(inter, denom) > 0.3f) act[j] = 0;
                }
            }
        }
        __syncthreads();
    }

    // cumsum of keep flags; KEEP_TOP_K cap; write col 14
    int lane = tid & 31, warp = tid >> 5;
    int a0 = act[2 * tid];
    int a1 = act[2 * tid + 1];
    int ps = a0 + a1;
    int v = ps;
#pragma unroll
    for (int o = 1; o < 32; o <<= 1) {
        int u = __shfl_up_sync(0xffffffffu, v, o);
        if (lane >= o) v += u;
    }
    if (lane == 31) wtot[warp] = v;
    __syncthreads();
    if (warp == 0) {
        int w = wtot[lane];
#pragma unroll
        for (int o = 1; o < 32; o <<= 1) {
            int u = __shfl_up_sync(0xffffffffu, w, o);
            if (lane >= o) w += u;
        }
        wtot[lane] = w;
    }
    __syncthreads();
    int base = (warp ? wtot[warp - 1] : 0) + v - ps;
    int c0 = base + a0;
    int c1 = c0 + a1;
    int e0 = 2 * tid, e1 = 2 * tid + 1;
    if (e0 < TOPK)
        out[((size_t)b * TOPK + e0) * 15 + 14] =
            ss[e0] * ((a0 && c0 <= KEEPK) ? 1.0f : 0.0f);
    if (e1 < TOPK)
        out[((size_t)b * TOPK + e1) * 15 + 14] =
            ss[e1] * ((a1 && c1 <= KEEPK) ? 1.0f : 0.0f);
}

// ---------------------------------------------------------------------------
extern "C" void kernel_launch(void* const* d_in, const int* in_sizes, int n_in,
                              void* d_out, int out_size) {
    const float* loc = nullptr;
    const float* conf = nullptr;
    const float* iou = nullptr;
    for (int i = 0; i < n_in; i++) {
        if (in_sizes[i] == NBATCH * NPRI * 14) loc = (const float*)d_in[i];
        else if (in_sizes[i] == NBATCH * NPRI * 2) conf = (const float*)d_in[i];
        else if (in_sizes[i] == NBATCH * NPRI) iou = (const float*)d_in[i];
    }
    float* out = (float*)d_out;

    void* hist_ptr = nullptr;
    cudaGetSymbolAddress(&hist_ptr, g_hist);
    cudaMemsetAsync(hist_ptr, 0, sizeof(unsigned) * NBATCH * NBINS, 0);

    int total = NBATCH * NPRI;
    int blocks = (total + 255) / 256;
    k_scores<<<blocks, 256>>>((const float2*)conf, iou);
    k_pivot<<<NBATCH, 1024>>>();
    k_compact<<<blocks, 256>>>();
    k_rescore<<<(NBATCH * CAP + 255) / 256, 256>>>((const float2*)conf, iou);

    cudaFuncSetAttribute(k_sort, cudaFuncAttributeMaxDynamicSharedMemorySize,
                         CAP * sizeof(unsigned long long));
    k_sort<<<NBATCH, 1024, CAP * sizeof(unsigned long long)>>>();

    k_decode<<<(NBATCH * TOPK + 127) / 128, 128>>>(loc, out);

    // 4*2000 + 2048 floats + 2048 ints = 48384 bytes
    cudaFuncSetAttribute(k_nms, cudaFuncAttributeMaxDynamicSharedMemorySize,
                         49152);
    k_nms<<<NBATCH, 1024, 49152>>>(out);
}

// round 6
// speedup vs baseline: 3.7012x; 3.2895x over previous
#include <cuda_runtime.h>
#include <cuda_bf16.h>
#include <math.h>
#include <stdint.h>

#define NBATCH 16
#define NPRI   119130
#define TOPK   2000
#define KEEPK  750
#define CAP    8192
#define NBINS  65536
#define TARGET 2300   // pivot margin over TOPK (absorbs 1e-6 approx error)

// Level layout (IMG 1920x1080, steps {8,16,32,64}):
// L0: off 0      cnt 97200  fw 240 step 8  nms 3  sizes {10,16,24}
// L1: off 97200  cnt 16320  fw 120 step 16 nms 2  sizes {32,48}
// L2: off 113520 cnt 4080   fw 60  step 32 nms 2  sizes {64,96}
// L3: off 117600 cnt 1530   fw 30  step 64 nms 3  sizes {128,192,256}

__device__ float              g_sapprox[NBATCH * NPRI];
__device__ unsigned int       g_hist[NBATCH * NBINS];
__device__ int                g_pivot[NBATCH];
__device__ int                g_selcnt[NBATCH];
__device__ int                g_selidx[NBATCH * CAP];
__device__ unsigned long long g_sel[NBATCH * CAP];
__device__ unsigned long long g_top[NBATCH * 2048];
__device__ float              g_boxes[NBATCH * 4 * 2048];
// suppression bitmask: [batch][row rank 0..2047][32 x 64-bit col words] = 8MB
__device__ unsigned long long g_mask[(size_t)NBATCH * 2048 * 32];

// ---------------------------------------------------------------------------
// Fast fp64 exp, error ~2^-51 (CR float result w.p. 1-2^-27 per call).
// ---------------------------------------------------------------------------
__device__ __forceinline__ double exp_pd(double x) {
    double t = x * 1.4426950408889634073599246810019;  // log2(e)
    int ni = __double2int_rn(t);
    double nd = (double)ni;
    double r = fma(nd, -6.93147180369123816490e-01, x);  // ln2_hi
    r = fma(nd, -1.90821492927058770002e-10, r);         // ln2_lo
    double p = 1.0 / 6227020800.0;                       // 1/13!
    p = fma(p, r, 1.0 / 479001600.0);
    p = fma(p, r, 1.0 / 39916800.0);
    p = fma(p, r, 1.0 / 3628800.0);
    p = fma(p, r, 1.0 / 362880.0);
    p = fma(p, r, 1.0 / 40320.0);
    p = fma(p, r, 1.0 / 5040.0);
    p = fma(p, r, 1.0 / 720.0);
    p = fma(p, r, 1.0 / 120.0);
    p = fma(p, r, 1.0 / 24.0);
    p = fma(p, r, 1.0 / 6.0);
    p = fma(p, r, 0.5);
    p = fma(p, r, 1.0);
    p = fma(p, r, 1.0);
    double sc = __longlong_as_double((long long)(ni + 1023) << 52);
    return p * sc;
}

__device__ __forceinline__ float softmax1_exact(float c0, float c1) {
    if (c1 >= c0) {
        float e0 = (float)exp_pd((double)__fsub_rn(c0, c1));
        return __fdiv_rn(1.0f, __fadd_rn(e0, 1.0f));
    } else {
        float e1 = (float)exp_pd((double)__fsub_rn(c1, c0));
        return __fdiv_rn(e1, __fadd_rn(1.0f, e1));
    }
}

// ---------------------------------------------------------------------------
// K1: approximate scores (pure fp32) + per-batch histogram (float bits >> 16)
// ---------------------------------------------------------------------------
__global__ void k_scores(const float2* __restrict__ conf,
                         const float* __restrict__ iou) {
    int i = blockIdx.x * blockDim.x + threadIdx.x;
    if (i >= NBATCH * NPRI) return;
    float u = iou[i];
    u = fminf(fmaxf(u, 0.0f), 1.0f);
    float s = 0.0f;
    if (u > 0.0f) {
        float2 c = conf[i];
        float pf = 1.0f / (1.0f + __expf(c.x - c.y));  // rel err ~1e-6
        float sf = sqrtf(pf * u);
        if (sf >= 0.299f) s = sf;                       // guard band
    }
    g_sapprox[i] = s;
    if (s > 0.0f) {
        int b = i / NPRI;
        unsigned bin = __float_as_uint(s) >> 16;
        atomicAdd(&g_hist[b * NBINS + bin], 1u);
    }
}

// ---------------------------------------------------------------------------
// K2: per-batch radix-select pivot bin (cum count >= TARGET); reset counter
// ---------------------------------------------------------------------------
__global__ void k_pivot() {
    int b = blockIdx.x;
    int t = threadIdx.x;
    __shared__ unsigned cs[1024];
    unsigned s = 0;
    const unsigned* h = g_hist + b * NBINS + t * 64;
#pragma unroll 8
    for (int k = 0; k < 64; k++) s += h[k];
    cs[t] = s;
    __syncthreads();
    if (t == 0) {
        g_selcnt[b] = 0;
        unsigned acc = 0;
        for (int c = 1023; c >= 0; c--) {
            unsigned na = acc + cs[c];
            if (na >= TARGET) {
                unsigned a2 = acc;
                const unsigned* hh = g_hist + b * NBINS + c * 64;
                int pivot = 0;
                for (int k2 = 63; k2 >= 0; k2--) {
                    a2 += hh[k2];
                    if (a2 >= TARGET) { pivot = c * 64 + k2; break; }
                }
                g_pivot[b] = pivot;
                return;
            }
            acc = na;
        }
        g_pivot[b] = 0;
    }
}

// ---------------------------------------------------------------------------
// K3a: compact candidate INDICES (approx bin >= pivot)
// ---------------------------------------------------------------------------
__global__ void k_compact() {
    int i = blockIdx.x * blockDim.x + threadIdx.x;
    if (i >= NBATCH * NPRI) return;
    float s = g_sapprox[i];
    if (s <= 0.0f) return;
    int b = i / NPRI;
    unsigned bin = __float_as_uint(s) >> 16;
    if ((int)bin < g_pivot[b]) return;
    int pos = atomicAdd(&g_selcnt[b], 1);
    if (pos < CAP) g_selidx[b * CAP + pos] = i - b * NPRI;
}

// ---------------------------------------------------------------------------
// K3b: dense exact rescore of compacted candidates (CR score).
// ---------------------------------------------------------------------------
__global__ void k_rescore(const float2* __restrict__ conf,
                          const float* __restrict__ iou) {
    int gid = blockIdx.x * blockDim.x + threadIdx.x;
    if (gid >= NBATCH * CAP) return;
    int b = gid / CAP;
    int pos = gid - b * CAP;
    unsigned long long key = 0ULL;
    int m = g_selcnt[b];
    if (m > CAP) m = CAP;
    if (pos < m) {
        int idx = g_selidx[b * CAP + pos];
        size_t e = (size_t)b * NPRI + (size_t)idx;
        float2 c = conf[e];
        float u = iou[e];
        u = fminf(fmaxf(u, 0.0f), 1.0f);
        float p = softmax1_exact(c.x, c.y);
        float s = __fsqrt_rn(__fmul_rn(p, u));
        if (s >= 0.3f)
            key = ((unsigned long long)__float_as_uint(s) << 32) |
                  (unsigned)(0x7FFFFFFF - idx);
    }
    g_sel[gid] = key;
}

// ---------------------------------------------------------------------------
// K4: per-batch bitonic sort (desc); emit top-2048 keys
// ---------------------------------------------------------------------------
__global__ void k_sort() {
    extern __shared__ unsigned long long keys[];
    int b = blockIdx.x;
    int tid = threadIdx.x;
    int m = g_selcnt[b];
    if (m > CAP) m = CAP;
    int nk = (m <= 2048) ? 2048 : ((m <= 4096) ? 4096 : 8192);
    for (int i = tid; i < nk; i += 1024)
        keys[i] = g_sel[b * CAP + i];
    for (int k = 2; k <= nk; k <<= 1) {
        for (int j = k >> 1; j > 0; j >>= 1) {
            __syncthreads();
            for (int i = tid; i < nk; i += 1024) {
                int l = i ^ j;
                if (l > i) {
                    unsigned long long a = keys[i], bb = keys[l];
                    bool up = ((i & k) == 0);
                    if (up ? (a < bb) : (a > bb)) { keys[i] = bb; keys[l] = a; }
                }
            }
        }
    }
    __syncthreads();
    for (int r = tid; r < 2048; r += 1024)
        g_top[b * 2048 + r] = (r < nk) ? keys[r] : 0ULL;
}

__constant__ float PW[10] = {
    (float)(10.0/1920.0),(float)(16.0/1920.0),(float)(24.0/1920.0),
    (float)(32.0/1920.0),(float)(48.0/1920.0),
    (float)(64.0/1920.0),(float)(96.0/1920.0),
    (float)(128.0/1920.0),(float)(192.0/1920.0),(float)(256.0/1920.0)};
__constant__ float PH[10] = {
    (float)(10.0/1080.0),(float)(16.0/1080.0),(float)(24.0/1080.0),
    (float)(32.0/1080.0),(float)(48.0/1080.0),
    (float)(64.0/1080.0),(float)(96.0/1080.0),
    (float)(128.0/1080.0),(float)(192.0/1080.0),(float)(256.0/1080.0)};

__device__ __forceinline__ void prior_of(int idx, float& pcx, float& pcy,
                                         float& pw, float& ph) {
    int off, fw, step, nm, msoff;
    if (idx < 97200)       { off = 0;      fw = 240; step = 8;  nm = 3; msoff = 0; }
    else if (idx < 113520) { off = 97200;  fw = 120; step = 16; nm = 2; msoff = 3; }
    else if (idx < 117600) { off = 113520; fw = 60;  step = 32; nm = 2; msoff = 5; }
    else                   { off = 117600; fw = 30;  step = 64; nm = 3; msoff = 7; }
    int r = idx - off;
    int cell = r / nm;
    int mi = r - cell * nm;
    int row = cell / fw;
    int col = cell - row * fw;
    double tx = ((double)col + 0.5) * (double)step;
    double ty = ((double)row + 0.5) * (double)step;
    pcx = (float)(tx * (1.0 / 1920.0));
    pcy = (float)(ty * (1.0 / 1080.0));
    pw = PW[msoff + mi];
    ph = PH[msoff + mi];
}

// ---------------------------------------------------------------------------
// K5: full-chip decode of top-2000 rows: out cols 0..13 + box SoA for NMS
// ---------------------------------------------------------------------------
__global__ void k_decode(const float* __restrict__ loc,
                         float* __restrict__ out) {
    int row = blockIdx.x * blockDim.x + threadIdx.x;
    if (row >= NBATCH * TOPK) return;
    int b = row / TOPK;
    int r = row - b * TOPK;
    unsigned long long kk = g_top[b * 2048 + r];
    int idx = 0x7FFFFFFF - (int)(unsigned)(kk & 0xFFFFFFFFu);
    if (idx < 0 || idx >= NPRI) idx = 0;

    float pcx, pcy, pw, ph;
    prior_of(idx, pcx, pcy, pw, ph);
    const float* lp = loc + ((size_t)b * NPRI + (size_t)idx) * 14;
    float l[14];
#pragma unroll
    for (int c = 0; c < 14; c++) l[c] = lp[c];

    float cx = __fadd_rn(pcx, __fmul_rn(__fmul_rn(l[0], 0.1f), pw));
    float cy = __fadd_rn(pcy, __fmul_rn(__fmul_rn(l[1], 0.1f), ph));
    float w  = __fmul_rn(pw, (float)exp_pd((double)__fmul_rn(l[2], 0.1f)));
    float h  = __fmul_rn(ph, (float)exp_pd((double)__fmul_rn(l[3], 0.2f)));
    float x1 = __fsub_rn(cx, __fmul_rn(w, 0.5f));
    float y1 = __fsub_rn(cy, __fmul_rn(h, 0.5f));
    float x2 = __fadd_rn(x1, w);
    float y2 = __fadd_rn(y1, h);

    float* op = out + (size_t)row * 15;
    float X1 = __fmul_rn(x1, 1920.0f), Y1 = __fmul_rn(y1, 1080.0f);
    float X2 = __fmul_rn(x2, 1920.0f), Y2 = __fmul_rn(y2, 1080.0f);
    op[0] = X1; op[1] = Y1; op[2] = X2; op[3] = Y2;
#pragma unroll
    for (int k = 0; k < 5; k++) {
        float lx = __fadd_rn(pcx, __fmul_rn(__fmul_rn(l[4 + 2 * k], 0.1f), pw));
        float ly = __fadd_rn(pcy, __fmul_rn(__fmul_rn(l[5 + 2 * k], 0.1f), ph));
        op[4 + 2 * k] = __fmul_rn(lx, 1920.0f);
        op[5 + 2 * k] = __fmul_rn(ly, 1080.0f);
    }
    g_boxes[b * 8192 + 0 * 2048 + r] = X1;
    g_boxes[b * 8192 + 1 * 2048 + r] = Y1;
    g_boxes[b * 8192 + 2 * 2048 + r] = X2;
    g_boxes[b * 8192 + 3 * 2048 + r] = Y2;
}

// ---------------------------------------------------------------------------
// K6a: suppression bitmask build (full chip). 64x64 rank tiles, upper tri.
// mask[b][i][jt] bit jj set iff IoU(i, jt*64+jj) > 0.3 and j > i.
// Words with jt < it are never written and stay 0 (static zero-init).
// ---------------------------------------------------------------------------
__global__ void k_mask() {
    int jt = blockIdx.x, it = blockIdx.y, b = blockIdx.z;
    if (jt < it) return;
    __shared__ float cx1[64], cy1[64], cx2[64], cy2[64], ca[64];
    int t = threadIdx.x;
    int j0 = jt * 64;
    {
        float x1 = g_boxes[b * 8192 + 0 * 2048 + j0 + t];
        float y1 = g_boxes[b * 8192 + 1 * 2048 + j0 + t];
        float x2 = g_boxes[b * 8192 + 2 * 2048 + j0 + t];
        float y2 = g_boxes[b * 8192 + 3 * 2048 + j0 + t];
        cx1[t] = x1; cy1[t] = y1; cx2[t] = x2; cy2[t] = y2;
        ca[t] = __fmul_rn(fmaxf(__fsub_rn(x2, x1), 0.0f),
                          fmaxf(__fsub_rn(y2, y1), 0.0f));
    }
    __syncthreads();
    int i = it * 64 + t;
    float xi1 = g_boxes[b * 8192 + 0 * 2048 + i];
    float yi1 = g_boxes[b * 8192 + 1 * 2048 + i];
    float xi2 = g_boxes[b * 8192 + 2 * 2048 + i];
    float yi2 = g_boxes[b * 8192 + 3 * 2048 + i];
    float ai = __fmul_rn(fmaxf(__fsub_rn(xi2, xi1), 0.0f),
                         fmaxf(__fsub_rn(yi2, yi1), 0.0f));
    unsigned long long word = 0ULL;
    int jj0 = (jt == it) ? (t + 1) : 0;
    for (int jj = jj0; jj < 64; jj++) {
        float lx = fmaxf(xi1, cx1[jj]), ly = fmaxf(yi1, cy1[jj]);
        float rx = fminf(xi2, cx2[jj]), ry = fminf(yi2, cy2[jj]);
        float iw = fmaxf(__fsub_rn(rx, lx), 0.0f);
        float ih = fmaxf(__fsub_rn(ry, ly), 0.0f);
        float inter = __fmul_rn(iw, ih);
        if (inter > 0.0f) {  // division only when boxes overlap (~4% of pairs)
            float denom = __fadd_rn(
                __fsub_rn(__fadd_rn(ai, ca[jj]), inter), 1e-9f);
            if (__fdiv_rn(inter, denom) > 0.3f) word |= (1ULL << jj);
        }
    }
    g_mask[((size_t)b * 2048 + i) * 32 + jt] = word;
}

// ---------------------------------------------------------------------------
// K6b: per-batch serial scan over the bitmask (warp 0, no per-iter barriers)
//      + KEEP_TOP_K cumsum + write out col 14.
// ---------------------------------------------------------------------------
__global__ void k_serial(float* __restrict__ out) {
    __shared__ unsigned long long initm[32];
    __shared__ unsigned long long keepm[32];
    __shared__ float ss[2048];
    __shared__ int wtot[33];
    int b = blockIdx.x;
    int tid = threadIdx.x;
    int warp = tid >> 5, lane = tid & 31;

    for (int r = tid; r < 2048; r += 1024) {
        unsigned long long kk = g_top[b * 2048 + r];
        float sc = __uint_as_float((unsigned)(kk >> 32));
        ss[r] = (r < TOPK) ? sc : 0.0f;
    }
    __syncthreads();

    // initial-active bits: warp w covers ranks [w*64, w*64+64)
    unsigned lo = __ballot_sync(0xffffffffu, ss[warp * 64 + lane] > 0.0f);
    unsigned hi = __ballot_sync(0xffffffffu, ss[warp * 64 + 32 + lane] > 0.0f);
    if (lane == 0) initm[warp] = ((unsigned long long)hi << 32) | lo;
    __syncthreads();

    if (warp == 0) {
        unsigned long long removed = ~initm[lane];  // bit set = inactive
        const unsigned long long* mrow = g_mask + (size_t)b * 2048 * 32;
        unsigned long long pf[8];
#pragma unroll
        for (int k = 0; k < 8; k++) pf[k] = mrow[(size_t)k * 32 + lane];
        unsigned long long rm_w = __shfl_sync(0xffffffffu, removed, 0);
        for (int i0 = 0; i0 < 2048; i0 += 8) {
#pragma unroll
            for (int k = 0; k < 8; k++) {
                int i = i0 + k;
                int w = i >> 6;
                int bit = i & 63;
                if (bit == 0) rm_w = __shfl_sync(0xffffffffu, removed, w);
                unsigned long long cur = pf[k];
                unsigned long long bc = __shfl_sync(0xffffffffu, cur, w);
                unsigned long long msk =
                    ((rm_w >> bit) & 1ULL) ? 0ULL : ~0ULL;  // active?
                removed |= cur & msk;
                rm_w |= bc & msk;
                int nx = i + 8;
                pf[k] = (nx < 2048) ? mrow[(size_t)nx * 32 + lane] : 0ULL;
            }
        }
        keepm[lane] = ~removed;  // keep == still active when processed
    }
    __syncthreads();

    // cumsum of keep flags; KEEP_TOP_K cap; write col 14
    int e0 = 2 * tid, e1 = 2 * tid + 1;
    int a0 = (int)((keepm[e0 >> 6] >> (e0 & 63)) & 1ULL);
    int a1 = (int)((keepm[e1 >> 6] >> (e1 & 63)) & 1ULL);
    int ps = a0 + a1;
    int v = ps;
#pragma unroll
    for (int o = 1; o < 32; o <<= 1) {
        int u = __shfl_up_sync(0xffffffffu, v, o);
        if (lane >= o) v += u;
    }
    if (lane == 31) wtot[warp] = v;
    __syncthreads();
    if (warp == 0) {
        int w = wtot[lane];
#pragma unroll
        for (int o = 1; o < 32; o <<= 1) {
            int u = __shfl_up_sync(0xffffffffu, w, o);
            if (lane >= o) w += u;
        }
        wtot[lane] = w;
    }
    __syncthreads();
    int base = (warp ? wtot[warp - 1] : 0) + v - ps;
    int c0 = base + a0;
    int c1 = c0 + a1;
    if (e0 < TOPK)
        out[((size_t)b * TOPK + e0) * 15 + 14] =
            ss[e0] * ((a0 && c0 <= KEEPK) ? 1.0f : 0.0f);
    if (e1 < TOPK)
        out[((size_t)b * TOPK + e1) * 15 + 14] =
            ss[e1] * ((a1 && c1 <= KEEPK) ? 1.0f : 0.0f);
}

// ---------------------------------------------------------------------------
extern "C" void kernel_launch(void* const* d_in, const int* in_sizes, int n_in,
                              void* d_out, int out_size) {
    const float* loc = nullptr;
    const float* conf = nullptr;
    const float* iou = nullptr;
    for (int i = 0; i < n_in; i++) {
        if (in_sizes[i] == NBATCH * NPRI * 14) loc = (const float*)d_in[i];
        else if (in_sizes[i] == NBATCH * NPRI * 2) conf = (const float*)d_in[i];
        else if (in_sizes[i] == NBATCH * NPRI) iou = (const float*)d_in[i];
    }
    float* out = (float*)d_out;

    void* hist_ptr = nullptr;
    cudaGetSymbolAddress(&hist_ptr, g_hist);
    cudaMemsetAsync(hist_ptr, 0, sizeof(unsigned) * NBATCH * NBINS, 0);

    int total = NBATCH * NPRI;
    int blocks = (total + 255) / 256;
    k_scores<<<blocks, 256>>>((const float2*)conf, iou);
    k_pivot<<<NBATCH, 1024>>>();
    k_compact<<<blocks, 256>>>();
    k_rescore<<<(NBATCH * CAP + 255) / 256, 256>>>((const float2*)conf, iou);

    cudaFuncSetAttribute(k_sort, cudaFuncAttributeMaxDynamicSharedMemorySize,
                         CAP * sizeof(unsigned long long));
    k_sort<<<NBATCH, 1024, CAP * sizeof(unsigned long long)>>>();

    k_decode<<<(NBATCH * TOPK + 127) / 128, 128>>>(loc, out);

    k_mask<<<dim3(32, 32, NBATCH), 64>>>();
    k_serial<<<NBATCH, 1024>>>(out);
}

// round 7
// speedup vs baseline: 3.7073x; 1.0016x over previous
#include <cuda_runtime.h>
#include <cuda_bf16.h>
#include <math.h>
#include <stdint.h>

#define NBATCH 16
#define NPRI   119130
#define TOPK   2000
#define KEEPK  750
#define CAP    8192
#define NBINS  65536
#define TARGET 2300   // pivot margin over TOPK (absorbs 1e-6 approx error)

// Level layout (IMG 1920x1080, steps {8,16,32,64}):
// L0: off 0      cnt 97200  fw 240 step 8  nms 3  sizes {10,16,24}
// L1: off 97200  cnt 16320  fw 120 step 16 nms 2  sizes {32,48}
// L2: off 113520 cnt 4080   fw 60  step 32 nms 2  sizes {64,96}
// L3: off 117600 cnt 1530   fw 30  step 64 nms 3  sizes {128,192,256}

__device__ float              g_sapprox[NBATCH * NPRI];
__device__ unsigned int       g_hist[NBATCH * NBINS];
__device__ int                g_pivot[NBATCH];
__device__ int                g_selcnt[NBATCH];
__device__ int                g_selidx[NBATCH * CAP];
__device__ unsigned long long g_sel[NBATCH * CAP];
__device__ unsigned long long g_top[NBATCH * 2048];
__device__ float              g_boxes[NBATCH * 4 * 2048];
// suppression bitmask: [batch][row rank 0..2047][32 x 64-bit col words] = 8MB
__device__ unsigned long long g_mask[(size_t)NBATCH * 2048 * 32];

// ---------------------------------------------------------------------------
// Fast fp64 exp, error ~2^-51 (CR float result w.p. 1-2^-27 per call).
// ---------------------------------------------------------------------------
__device__ __forceinline__ double exp_pd(double x) {
    double t = x * 1.4426950408889634073599246810019;  // log2(e)
    int ni = __double2int_rn(t);
    double nd = (double)ni;
    double r = fma(nd, -6.93147180369123816490e-01, x);  // ln2_hi
    r = fma(nd, -1.90821492927058770002e-10, r);         // ln2_lo
    double p = 1.0 / 6227020800.0;                       // 1/13!
    p = fma(p, r, 1.0 / 479001600.0);
    p = fma(p, r, 1.0 / 39916800.0);
    p = fma(p, r, 1.0 / 3628800.0);
    p = fma(p, r, 1.0 / 362880.0);
    p = fma(p, r, 1.0 / 40320.0);
    p = fma(p, r, 1.0 / 5040.0);
    p = fma(p, r, 1.0 / 720.0);
    p = fma(p, r, 1.0 / 120.0);
    p = fma(p, r, 1.0 / 24.0);
    p = fma(p, r, 1.0 / 6.0);
    p = fma(p, r, 0.5);
    p = fma(p, r, 1.0);
    p = fma(p, r, 1.0);
    double sc = __longlong_as_double((long long)(ni + 1023) << 52);
    return p * sc;
}

__device__ __forceinline__ float softmax1_exact(float c0, float c1) {
    if (c1 >= c0) {
        float e0 = (float)exp_pd((double)__fsub_rn(c0, c1));
        return __fdiv_rn(1.0f, __fadd_rn(e0, 1.0f));
    } else {
        float e1 = (float)exp_pd((double)__fsub_rn(c1, c0));
        return __fdiv_rn(e1, __fadd_rn(1.0f, e1));
    }
}

// ---------------------------------------------------------------------------
// K1: approximate scores (pure fp32) + per-batch histogram (float bits >> 16)
// ---------------------------------------------------------------------------
__global__ void k_scores(const float2* __restrict__ conf,
                         const float* __restrict__ iou) {
    int i = blockIdx.x * blockDim.x + threadIdx.x;
    if (i >= NBATCH * NPRI) return;
    float u = iou[i];
    u = fminf(fmaxf(u, 0.0f), 1.0f);
    float s = 0.0f;
    if (u > 0.0f) {
        float2 c = conf[i];
        float pf = 1.0f / (1.0f + __expf(c.x - c.y));  // rel err ~1e-6
        float sf = sqrtf(pf * u);
        if (sf >= 0.299f) s = sf;                       // guard band
    }
    g_sapprox[i] = s;
    if (s > 0.0f) {
        int b = i / NPRI;
        unsigned bin = __float_as_uint(s) >> 16;
        atomicAdd(&g_hist[b * NBINS + bin], 1u);
    }
}

// ---------------------------------------------------------------------------
// K2: per-batch radix-select pivot bin (cum count >= TARGET); reset counter
// ---------------------------------------------------------------------------
__global__ void k_pivot() {
    int b = blockIdx.x;
    int t = threadIdx.x;
    __shared__ unsigned cs[1024];
    unsigned s = 0;
    const unsigned* h = g_hist + b * NBINS + t * 64;
#pragma unroll 8
    for (int k = 0; k < 64; k++) s += h[k];
    cs[t] = s;
    __syncthreads();
    if (t == 0) {
        g_selcnt[b] = 0;
        unsigned acc = 0;
        for (int c = 1023; c >= 0; c--) {
            unsigned na = acc + cs[c];
            if (na >= TARGET) {
                unsigned a2 = acc;
                const unsigned* hh = g_hist + b * NBINS + c * 64;
                int pivot = 0;
                for (int k2 = 63; k2 >= 0; k2--) {
                    a2 += hh[k2];
                    if (a2 >= TARGET) { pivot = c * 64 + k2; break; }
                }
                g_pivot[b] = pivot;
                return;
            }
            acc = na;
        }
        g_pivot[b] = 0;
    }
}

// ---------------------------------------------------------------------------
// K3a: compact candidate INDICES (approx bin >= pivot)
// ---------------------------------------------------------------------------
__global__ void k_compact() {
    int i = blockIdx.x * blockDim.x + threadIdx.x;
    if (i >= NBATCH * NPRI) return;
    float s = g_sapprox[i];
    if (s <= 0.0f) return;
    int b = i / NPRI;
    unsigned bin = __float_as_uint(s) >> 16;
    if ((int)bin < g_pivot[b]) return;
    int pos = atomicAdd(&g_selcnt[b], 1);
    if (pos < CAP) g_selidx[b * CAP + pos] = i - b * NPRI;
}

// ---------------------------------------------------------------------------
// K3b: dense exact rescore of compacted candidates (CR score).
// ---------------------------------------------------------------------------
__global__ void k_rescore(const float2* __restrict__ conf,
                          const float* __restrict__ iou) {
    int gid = blockIdx.x * blockDim.x + threadIdx.x;
    if (gid >= NBATCH * CAP) return;
    int b = gid / CAP;
    int pos = gid - b * CAP;
    unsigned long long key = 0ULL;
    int m = g_selcnt[b];
    if (m > CAP) m = CAP;
    if (pos < m) {
        int idx = g_selidx[b * CAP + pos];
        size_t e = (size_t)b * NPRI + (size_t)idx;
        float2 c = conf[e];
        float u = iou[e];
        u = fminf(fmaxf(u, 0.0f), 1.0f);
        float p = softmax1_exact(c.x, c.y);
        float s = __fsqrt_rn(__fmul_rn(p, u));
        if (s >= 0.3f)
            key = ((unsigned long long)__float_as_uint(s) << 32) |
                  (unsigned)(0x7FFFFFFF - idx);
    }
    g_sel[gid] = key;
}

// ---------------------------------------------------------------------------
// K4: per-batch bitonic sort (desc); emit top-2048 keys
// ---------------------------------------------------------------------------
__global__ void k_sort() {
    extern __shared__ unsigned long long keys[];
    int b = blockIdx.x;
    int tid = threadIdx.x;
    int m = g_selcnt[b];
    if (m > CAP) m = CAP;
    int nk = (m <= 2048) ? 2048 : ((m <= 4096) ? 4096 : 8192);
    for (int i = tid; i < nk; i += 1024)
        keys[i] = g_sel[b * CAP + i];
    for (int k = 2; k <= nk; k <<= 1) {
        for (int j = k >> 1; j > 0; j >>= 1) {
            __syncthreads();
            for (int i = tid; i < nk; i += 1024) {
                int l = i ^ j;
                if (l > i) {
                    unsigned long long a = keys[i], bb = keys[l];
                    bool up = ((i & k) == 0);
                    if (up ? (a < bb) : (a > bb)) { keys[i] = bb; keys[l] = a; }
                }
            }
        }
    }
    __syncthreads();
    for (int r = tid; r < 2048; r += 1024)
        g_top[b * 2048 + r] = (r < nk) ? keys[r] : 0ULL;
}

__constant__ float PW[10] = {
    (float)(10.0/1920.0),(float)(16.0/1920.0),(float)(24.0/1920.0),
    (float)(32.0/1920.0),(float)(48.0/1920.0),
    (float)(64.0/1920.0),(float)(96.0/1920.0),
    (float)(128.0/1920.0),(float)(192.0/1920.0),(float)(256.0/1920.0)};
__constant__ float PH[10] = {
    (float)(10.0/1080.0),(float)(16.0/1080.0),(float)(24.0/1080.0),
    (float)(32.0/1080.0),(float)(48.0/1080.0),
    (float)(64.0/1080.0),(float)(96.0/1080.0),
    (float)(128.0/1080.0),(float)(192.0/1080.0),(float)(256.0/1080.0)};

__device__ __forceinline__ void prior_of(int idx, float& pcx, float& pcy,
                                         float& pw, float& ph) {
    int off, fw, step, nm, msoff;
    if (idx < 97200)       { off = 0;      fw = 240; step = 8;  nm = 3; msoff = 0; }
    else if (idx < 113520) { off = 97200;  fw = 120; step = 16; nm = 2; msoff = 3; }
    else if (idx < 117600) { off = 113520; fw = 60;  step = 32; nm = 2; msoff = 5; }
    else                   { off = 117600; fw = 30;  step = 64; nm = 3; msoff = 7; }
    int r = idx - off;
    int cell = r / nm;
    int mi = r - cell * nm;
    int row = cell / fw;
    int col = cell - row * fw;
    double tx = ((double)col + 0.5) * (double)step;
    double ty = ((double)row + 0.5) * (double)step;
    pcx = (float)(tx * (1.0 / 1920.0));
    pcy = (float)(ty * (1.0 / 1080.0));
    pw = PW[msoff + mi];
    ph = PH[msoff + mi];
}

// ---------------------------------------------------------------------------
// K5: full-chip decode of top-2000 rows: out cols 0..13 + box SoA for NMS
// ---------------------------------------------------------------------------
__global__ void k_decode(const float* __restrict__ loc,
                         float* __restrict__ out) {
    int row = blockIdx.x * blockDim.x + threadIdx.x;
    if (row >= NBATCH * TOPK) return;
    int b = row / TOPK;
    int r = row - b * TOPK;
    unsigned long long kk = g_top[b * 2048 + r];
    int idx = 0x7FFFFFFF - (int)(unsigned)(kk & 0xFFFFFFFFu);
    if (idx < 0 || idx >= NPRI) idx = 0;

    float pcx, pcy, pw, ph;
    prior_of(idx, pcx, pcy, pw, ph);
    const float* lp = loc + ((size_t)b * NPRI + (size_t)idx) * 14;
    float l[14];
#pragma unroll
    for (int c = 0; c < 14; c++) l[c] = lp[c];

    float cx = __fadd_rn(pcx, __fmul_rn(__fmul_rn(l[0], 0.1f), pw));
    float cy = __fadd_rn(pcy, __fmul_rn(__fmul_rn(l[1], 0.1f), ph));
    float w  = __fmul_rn(pw, (float)exp_pd((double)__fmul_rn(l[2], 0.1f)));
    float h  = __fmul_rn(ph, (float)exp_pd((double)__fmul_rn(l[3], 0.2f)));
    float x1 = __fsub_rn(cx, __fmul_rn(w, 0.5f));
    float y1 = __fsub_rn(cy, __fmul_rn(h, 0.5f));
    float x2 = __fadd_rn(x1, w);
    float y2 = __fadd_rn(y1, h);

    float* op = out + (size_t)row * 15;
    float X1 = __fmul_rn(x1, 1920.0f), Y1 = __fmul_rn(y1, 1080.0f);
    float X2 = __fmul_rn(x2, 1920.0f), Y2 = __fmul_rn(y2, 1080.0f);
    op[0] = X1; op[1] = Y1; op[2] = X2; op[3] = Y2;
#pragma unroll
    for (int k = 0; k < 5; k++) {
        float lx = __fadd_rn(pcx, __fmul_rn(__fmul_rn(l[4 + 2 * k], 0.1f), pw));
        float ly = __fadd_rn(pcy, __fmul_rn(__fmul_rn(l[5 + 2 * k], 0.1f), ph));
        op[4 + 2 * k] = __fmul_rn(lx, 1920.0f);
        op[5 + 2 * k] = __fmul_rn(ly, 1080.0f);
    }
    g_boxes[b * 8192 + 0 * 2048 + r] = X1;
    g_boxes[b * 8192 + 1 * 2048 + r] = Y1;
    g_boxes[b * 8192 + 2 * 2048 + r] = X2;
    g_boxes[b * 8192 + 3 * 2048 + r] = Y2;
}

// ---------------------------------------------------------------------------
// K6a: suppression bitmask build (full chip). 64x64 rank tiles, upper tri.
// mask[b][i][jt] bit jj set iff IoU(i, jt*64+jj) > 0.3 and j > i.
// Words with jt < it are never written and stay 0 (static zero-init).
// ---------------------------------------------------------------------------
__global__ void k_mask() {
    int jt = blockIdx.x, it = blockIdx.y, b = blockIdx.z;
    if (jt < it) return;
    __shared__ float cx1[64], cy1[64], cx2[64], cy2[64], ca[64];
    int t = threadIdx.x;
    int j0 = jt * 64;
    {
        float x1 = g_boxes[b * 8192 + 0 * 2048 + j0 + t];
        float y1 = g_boxes[b * 8192 + 1 * 2048 + j0 + t];
        float x2 = g_boxes[b * 8192 + 2 * 2048 + j0 + t];
        float y2 = g_boxes[b * 8192 + 3 * 2048 + j0 + t];
        cx1[t] = x1; cy1[t] = y1; cx2[t] = x2; cy2[t] = y2;
        ca[t] = __fmul_rn(fmaxf(__fsub_rn(x2, x1), 0.0f),
                          fmaxf(__fsub_rn(y2, y1), 0.0f));
    }
    __syncthreads();
    int i = it * 64 + t;
    float xi1 = g_boxes[b * 8192 + 0 * 2048 + i];
    float yi1 = g_boxes[b * 8192 + 1 * 2048 + i];
    float xi2 = g_boxes[b * 8192 + 2 * 2048 + i];
    float yi2 = g_boxes[b * 8192 + 3 * 2048 + i];
    float ai = __fmul_rn(fmaxf(__fsub_rn(xi2, xi1), 0.0f),
                         fmaxf(__fsub_rn(yi2, yi1), 0.0f));
    unsigned long long word = 0ULL;
    int jj0 = (jt == it) ? (t + 1) : 0;
    for (int jj = jj0; jj < 64; jj++) {
        float lx = fmaxf(xi1, cx1[jj]), ly = fmaxf(yi1, cy1[jj]);
        float rx = fminf(xi2, cx2[jj]), ry = fminf(yi2, cy2[jj]);
        float iw = fmaxf(__fsub_rn(rx, lx), 0.0f);
        float ih = fmaxf(__fsub_rn(ry, ly), 0.0f);
        float inter = __fmul_rn(iw, ih);
        if (inter > 0.0f) {  // division only when boxes overlap (~4% of pairs)
            float denom = __fadd_rn(
                __fsub_rn(__fadd_rn(ai, ca[jj]), inter), 1e-9f);
            if (__fdiv_rn(inter, denom) > 0.3f) word |= (1ULL << jj);
        }
    }
    g_mask[((size_t)b * 2048 + i) * 32 + jt] = word;
}

// ---------------------------------------------------------------------------
// K6b: per-batch serial scan over the bitmask (warp 0, no per-iter barriers)
//      + KEEP_TOP_K cumsum + write out col 14.
// ---------------------------------------------------------------------------
__global__ void k_serial(float* __restrict__ out) {
    __shared__ unsigned long long initm[32];
    __shared__ unsigned long long keepm[32];
    __shared__ float ss[2048];
    __shared__ int wtot[33];
    int b = blockIdx.x;
    int tid = threadIdx.x;
    int warp = tid >> 5, lane = tid & 31;

    for (int r = tid; r < 2048; r += 1024) {
        unsigned long long kk = g_top[b * 2048 + r];
        float sc = __uint_as_float((unsigned)(kk >> 32));
        ss[r] = (r < TOPK) ? sc : 0.0f;
    }
    __syncthreads();

    // initial-active bits: warp w covers ranks [w*64, w*64+64)
    unsigned lo = __ballot_sync(0xffffffffu, ss[warp * 64 + lane] > 0.0f);
    unsigned hi = __ballot_sync(0xffffffffu, ss[warp * 64 + 32 + lane] > 0.0f);
    if (lane == 0) initm[warp] = ((unsigned long long)hi << 32) | lo;
    __syncthreads();

    if (warp == 0) {
        unsigned long long removed = ~initm[lane];  // bit set = inactive
        const unsigned long long* mrow = g_mask + (size_t)b * 2048 * 32;
        unsigned long long pf[8];
#pragma unroll
        for (int k = 0; k < 8; k++) pf[k] = mrow[(size_t)k * 32 + lane];
        unsigned long long rm_w = __shfl_sync(0xffffffffu, removed, 0);
        for (int i0 = 0; i0 < 2048; i0 += 8) {
#pragma unroll
            for (int k = 0; k < 8; k++) {
                int i = i0 + k;
                int w = i >> 6;
                int bit = i & 63;
                if (bit == 0) rm_w = __shfl_sync(0xffffffffu, removed, w);
                unsigned long long cur = pf[k];
                unsigned long long bc = __shfl_sync(0xffffffffu, cur, w);
                unsigned long long msk =
                    ((rm_w >> bit) & 1ULL) ? 0ULL : ~0ULL;  // active?
                removed |= cur & msk;
                rm_w |= bc & msk;
                int nx = i + 8;
                pf[k] = (nx < 2048) ? mrow[(size_t)nx * 32 + lane] : 0ULL;
            }
        }
        keepm[lane] = ~removed;  // keep == still active when processed
    }
    __syncthreads();

    // cumsum of keep flags; KEEP_TOP_K cap; write col 14
    int e0 = 2 * tid, e1 = 2 * tid + 1;
    int a0 = (int)((keepm[e0 >> 6] >> (e0 & 63)) & 1ULL);
    int a1 = (int)((keepm[e1 >> 6] >> (e1 & 63)) & 1ULL);
    int ps = a0 + a1;
    int v = ps;
#pragma unroll
    for (int o = 1; o < 32; o <<= 1) {
        int u = __shfl_up_sync(0xffffffffu, v, o);
        if (lane >= o) v += u;
    }
    if (lane == 31) wtot[warp] = v;
    __syncthreads();
    if (warp == 0) {
        int w = wtot[lane];
#pragma unroll
        for (int o = 1; o < 32; o <<= 1) {
            int u = __shfl_up_sync(0xffffffffu, w, o);
            if (lane >= o) w += u;
        }
        wtot[lane] = w;
    }
    __syncthreads();
    int base = (warp ? wtot[warp - 1] : 0) + v - ps;
    int c0 = base + a0;
    int c1 = c0 + a1;
    if (e0 < TOPK)
        out[((size_t)b * TOPK + e0) * 15 + 14] =
            ss[e0] * ((a0 && c0 <= KEEPK) ? 1.0f : 0.0f);
    if (e1 < TOPK)
        out[((size_t)b * TOPK + e1) * 15 + 14] =
            ss[e1] * ((a1 && c1 <= KEEPK) ? 1.0f : 0.0f);
}

// ---------------------------------------------------------------------------
extern "C" void kernel_launch(void* const* d_in, const int* in_sizes, int n_in,
                              void* d_out, int out_size) {
    const float* loc = nullptr;
    const float* conf = nullptr;
    const float* iou = nullptr;
    for (int i = 0; i < n_in; i++) {
        if (in_sizes[i] == NBATCH * NPRI * 14) loc = (const float*)d_in[i];
        else if (in_sizes[i] == NBATCH * NPRI * 2) conf = (const float*)d_in[i];
        else if (in_sizes[i] == NBATCH * NPRI) iou = (const float*)d_in[i];
    }
    float* out = (float*)d_out;

    void* hist_ptr = nullptr;
    cudaGetSymbolAddress(&hist_ptr, g_hist);
    cudaMemsetAsync(hist_ptr, 0, sizeof(unsigned) * NBATCH * NBINS, 0);

    int total = NBATCH * NPRI;
    int blocks = (total + 255) / 256;
    k_scores<<<blocks, 256>>>((const float2*)conf, iou);
    k_pivot<<<NBATCH, 1024>>>();
    k_compact<<<blocks, 256>>>();
    k_rescore<<<(NBATCH * CAP + 255) / 256, 256>>>((const float2*)conf, iou);

    cudaFuncSetAttribute(k_sort, cudaFuncAttributeMaxDynamicSharedMemorySize,
                         CAP * sizeof(unsigned long long));
    k_sort<<<NBATCH, 1024, CAP * sizeof(unsigned long long)>>>();

    k_decode<<<(NBATCH * TOPK + 127) / 128, 128>>>(loc, out);

    k_mask<<<dim3(32, 32, NBATCH), 64>>>();
    k_serial<<<NBATCH, 1024>>>(out);
}

// round 8
// speedup vs baseline: 5.2095x; 1.4052x over previous
#include <cuda_runtime.h>
#include <cuda_bf16.h>
#include <math.h>
#include <stdint.h>

#define NBATCH 16
#define NPRI   119130
#define TOPK   2000
#define KEEPK  750
#define CAP    8192
#define NBINS  256
#define BIN_OFF 16024   // (__float_as_uint(0.299f)>>16) == 16025 -> bin 1
#define TARGET 2300     // pivot margin over TOPK (absorbs 1e-6 approx error)

// Level layout (IMG 1920x1080, steps {8,16,32,64}):
// L0: off 0      cnt 97200  fw 240 step 8  nms 3  sizes {10,16,24}
// L1: off 97200  cnt 16320  fw 120 step 16 nms 2  sizes {32,48}
// L2: off 113520 cnt 4080   fw 60  step 32 nms 2  sizes {64,96}
// L3: off 117600 cnt 1530   fw 30  step 64 nms 3  sizes {128,192,256}

__device__ float              g_sapprox[NBATCH * NPRI];
__device__ unsigned int       g_hist[NBATCH * NBINS];
__device__ int                g_pivot[NBATCH];
__device__ int                g_selcnt[NBATCH];
__device__ int                g_selidx[NBATCH * CAP];
__device__ unsigned long long g_sel[NBATCH * CAP];
__device__ unsigned long long g_top[NBATCH * 2048];
__device__ float              g_boxes[NBATCH * 4 * 2048];
// suppression bitmask: [batch][row rank 0..2047][32 x 64-bit col words] = 8MB
__device__ unsigned long long g_mask[(size_t)NBATCH * 2048 * 32];
__device__ double             g_exp_tab[64];   // 2^(j/64)

// ---------------------------------------------------------------------------
// init: fill 2^(j/64) table (deterministic every call)
// ---------------------------------------------------------------------------
__global__ void k_init() {
    int j = threadIdx.x;
    if (j < 64) g_exp_tab[j] = exp2((double)j * 0.015625);
}

// ---------------------------------------------------------------------------
// Fast fp64 exp via 64-entry table + degree-5 poly; error ~2^-52.
// Result rounded once to float == correctly-rounded expf w.p. 1-2^-27/call.
// ---------------------------------------------------------------------------
__device__ __forceinline__ double exp_pd(double x) {
    double t = x * 92.332482616893658071;                // 64*log2(e)
    int ni = __double2int_rn(t);
    double nd = (double)ni;
    double r = fma(nd, -1.0830424693267559625e-02, x);   // ln2_hi/64 (exact/64)
    r = fma(nd, -2.9815858269852932813e-12, r);          // ln2_lo/64
    double q = 8.3333333333333333333e-03;                // 1/120
    q = fma(q, r, 4.1666666666666666667e-02);            // 1/24
    q = fma(q, r, 1.6666666666666666667e-01);            // 1/6
    q = fma(q, r, 0.5);
    q = fma(q, r, 1.0);
    q = q * r;                                           // expm1(r), err ~3e-17
    double T = g_exp_tab[ni & 63];
    T = __longlong_as_double(__double_as_longlong(T) +
                             ((long long)(ni >> 6) << 52));
    return fma(T, q, T);
}

__device__ __forceinline__ float softmax1_exact(float c0, float c1) {
    if (c1 >= c0) {
        float e0 = (float)exp_pd((double)__fsub_rn(c0, c1));
        return __fdiv_rn(1.0f, __fadd_rn(e0, 1.0f));
    } else {
        float e1 = (float)exp_pd((double)__fsub_rn(c1, c0));
        return __fdiv_rn(e1, __fadd_rn(1.0f, e1));
    }
}

// ---------------------------------------------------------------------------
// K1: approximate scores (pure fp32) + per-batch 256-bin histogram
// grid (ceil(NPRI/256), NBATCH) so each block is batch-uniform
// ---------------------------------------------------------------------------
__global__ void k_scores(const float2* __restrict__ conf,
                         const float* __restrict__ iou) {
    __shared__ unsigned sh[NBINS];
    int b = blockIdx.y;
    int p = blockIdx.x * 256 + threadIdx.x;
    sh[threadIdx.x] = 0;
    __syncthreads();
    if (p < NPRI) {
        int i = b * NPRI + p;
        float u = iou[i];
        u = fminf(fmaxf(u, 0.0f), 1.0f);
        float s = 0.0f;
        if (u > 0.0f) {
            float2 c = conf[i];
            float pf = 1.0f / (1.0f + __expf(c.x - c.y));  // rel err ~1e-6
            float sf = sqrtf(pf * u);
            if (sf >= 0.299f) s = sf;                       // guard band
        }
        g_sapprox[i] = s;
        if (s > 0.0f) {
            int bin = (int)(__float_as_uint(s) >> 16) - BIN_OFF;
            bin = min(max(bin, 0), NBINS - 1);
            atomicAdd(&sh[bin], 1u);
        }
    }
    __syncthreads();
    unsigned v = sh[threadIdx.x];
    if (v) atomicAdd(&g_hist[b * NBINS + threadIdx.x], v);
}

// ---------------------------------------------------------------------------
// K2: per-batch pivot via parallel suffix-sum over 256 bins; reset counter
// pivot = largest bin t with (sum of bins >= t) >= TARGET, else 0
// ---------------------------------------------------------------------------
__global__ void k_pivot() {
    __shared__ unsigned C[NBINS];
    __shared__ unsigned wt[8];
    int b = blockIdx.x, t = threadIdx.x;
    int lane = t & 31, w = t >> 5;
    unsigned h = g_hist[b * NBINS + t];
    unsigned v = h;
#pragma unroll
    for (int o = 1; o < 32; o <<= 1) {
        unsigned u = __shfl_up_sync(0xffffffffu, v, o);
        if (lane >= o) v += u;
    }
    if (lane == 31) wt[w] = v;
    __syncthreads();
    if (t < 8) {
        unsigned x = wt[t];
#pragma unroll
        for (int o = 1; o < 8; o <<= 1) {
            unsigned u = __shfl_up_sync(0xffu, x, o);
            if (t >= o) x += u;
        }
        wt[t] = x;
    }
    __syncthreads();
    unsigned pre = v + (w ? wt[w - 1] : 0);  // inclusive prefix (ascending)
    unsigned total = wt[7];
    C[t] = total - pre + h;                  // suffix sum from bin t
    __syncthreads();
    if (t == 0) g_selcnt[b] = 0;
    bool qual = (C[t] >= TARGET) && (t == 255 || C[t + 1] < TARGET);
    if (qual) g_pivot[b] = t;
    if (t == 0 && total < TARGET) g_pivot[b] = 0;  // take all
}

// ---------------------------------------------------------------------------
// K3a: compact candidate INDICES (approx bin >= pivot)
// ---------------------------------------------------------------------------
__global__ void k_compact() {
    int b = blockIdx.y;
    int p = blockIdx.x * 256 + threadIdx.x;
    if (p >= NPRI) return;
    int i = b * NPRI + p;
    float s = g_sapprox[i];
    if (s <= 0.0f) return;
    int bin = (int)(__float_as_uint(s) >> 16) - BIN_OFF;
    bin = min(max(bin, 0), NBINS - 1);
    if (bin < g_pivot[b]) return;
    int pos = atomicAdd(&g_selcnt[b], 1);
    if (pos < CAP) g_selidx[b * CAP + pos] = p;
}

// ---------------------------------------------------------------------------
// K3b: dense exact rescore of compacted candidates (CR score).
//      Key = (score_bits << 32) | (0x7FFFFFFF - idx)
// ---------------------------------------------------------------------------
__global__ void k_rescore(const float2* __restrict__ conf,
                          const float* __restrict__ iou) {
    int gid = blockIdx.x * blockDim.x + threadIdx.x;
    if (gid >= NBATCH * CAP) return;
    int b = gid / CAP;
    int pos = gid - b * CAP;
    unsigned long long key = 0ULL;
    int m = g_selcnt[b];
    if (m > CAP) m = CAP;
    if (pos < m) {
        int idx = g_selidx[b * CAP + pos];
        size_t e = (size_t)b * NPRI + (size_t)idx;
        float2 c = conf[e];
        float u = iou[e];
        u = fminf(fmaxf(u, 0.0f), 1.0f);
        float p = softmax1_exact(c.x, c.y);
        float s = __fsqrt_rn(__fmul_rn(p, u));
        if (s >= 0.3f)
            key = ((unsigned long long)__float_as_uint(s) << 32) |
                  (unsigned)(0x7FFFFFFF - idx);
    }
    g_sel[gid] = key;
}

// ---------------------------------------------------------------------------
// K4: per-batch bitonic sort (desc), pair-indexed (no divergence waste)
// ---------------------------------------------------------------------------
__global__ void k_sort() {
    extern __shared__ unsigned long long keys[];
    int b = blockIdx.x;
    int tid = threadIdx.x;
    int m = g_selcnt[b];
    if (m > CAP) m = CAP;
    int nk = (m <= 2048) ? 2048 : ((m <= 4096) ? 4096 : 8192);
    for (int i = tid; i < nk; i += 1024)
        keys[i] = g_sel[b * CAP + i];   // zero-padded by k_rescore
    int npairs = nk >> 1;
    for (int k = 2; k <= nk; k <<= 1) {
        for (int j = k >> 1; j > 0; j >>= 1) {
            __syncthreads();
            for (int p = tid; p < npairs; p += 1024) {
                int i = ((p & ~(j - 1)) << 1) | (p & (j - 1));
                int l = i + j;
                unsigned long long a = keys[i], bb = keys[l];
                bool up = ((i & k) == 0);
                if (up ? (a < bb) : (a > bb)) { keys[i] = bb; keys[l] = a; }
            }
        }
    }
    __syncthreads();
    for (int r = tid; r < 2048; r += 1024)
        g_top[b * 2048 + r] = (r < nk) ? keys[r] : 0ULL;
}

__constant__ float PW[10] = {
    (float)(10.0/1920.0),(float)(16.0/1920.0),(float)(24.0/1920.0),
    (float)(32.0/1920.0),(float)(48.0/1920.0),
    (float)(64.0/1920.0),(float)(96.0/1920.0),
    (float)(128.0/1920.0),(float)(192.0/1920.0),(float)(256.0/1920.0)};
__constant__ float PH[10] = {
    (float)(10.0/1080.0),(float)(16.0/1080.0),(float)(24.0/1080.0),
    (float)(32.0/1080.0),(float)(48.0/1080.0),
    (float)(64.0/1080.0),(float)(96.0/1080.0),
    (float)(128.0/1080.0),(float)(192.0/1080.0),(float)(256.0/1080.0)};

__device__ __forceinline__ void prior_of(int idx, float& pcx, float& pcy,
                                         float& pw, float& ph) {
    int off, fw, step, nm, msoff;
    if (idx < 97200)       { off = 0;      fw = 240; step = 8;  nm = 3; msoff = 0; }
    else if (idx < 113520) { off = 97200;  fw = 120; step = 16; nm = 2; msoff = 3; }
    else if (idx < 117600) { off = 113520; fw = 60;  step = 32; nm = 2; msoff = 5; }
    else                   { off = 117600; fw = 30;  step = 64; nm = 3; msoff = 7; }
    int r = idx - off;
    int cell = r / nm;
    int mi = r - cell * nm;
    int row = cell / fw;
    int col = cell - row * fw;
    double tx = ((double)col + 0.5) * (double)step;
    double ty = ((double)row + 0.5) * (double)step;
    pcx = (float)(tx * (1.0 / 1920.0));
    pcy = (float)(ty * (1.0 / 1080.0));
    pw = PW[msoff + mi];
    ph = PH[msoff + mi];
}

// ---------------------------------------------------------------------------
// K5: full-chip decode of top-2000 rows: out cols 0..13 + box SoA for NMS
// ---------------------------------------------------------------------------
__global__ void k_decode(const float* __restrict__ loc,
                         float* __restrict__ out) {
    int row = blockIdx.x * blockDim.x + threadIdx.x;
    if (row >= NBATCH * TOPK) return;
    int b = row / TOPK;
    int r = row - b * TOPK;
    unsigned long long kk = g_top[b * 2048 + r];
    int idx = 0x7FFFFFFF - (int)(unsigned)(kk & 0xFFFFFFFFu);
    if (idx < 0 || idx >= NPRI) idx = 0;

    float pcx, pcy, pw, ph;
    prior_of(idx, pcx, pcy, pw, ph);
    const float* lp = loc + ((size_t)b * NPRI + (size_t)idx) * 14;
    float l[14];
#pragma unroll
    for (int c = 0; c < 14; c++) l[c] = lp[c];

    float cx = __fadd_rn(pcx, __fmul_rn(__fmul_rn(l[0], 0.1f), pw));
    float cy = __fadd_rn(pcy, __fmul_rn(__fmul_rn(l[1], 0.1f), ph));
    float w  = __fmul_rn(pw, (float)exp_pd((double)__fmul_rn(l[2], 0.1f)));
    float h  = __fmul_rn(ph, (float)exp_pd((double)__fmul_rn(l[3], 0.2f)));
    float x1 = __fsub_rn(cx, __fmul_rn(w, 0.5f));
    float y1 = __fsub_rn(cy, __fmul_rn(h, 0.5f));
    float x2 = __fadd_rn(x1, w);
    float y2 = __fadd_rn(y1, h);

    float* op = out + (size_t)row * 15;
    float X1 = __fmul_rn(x1, 1920.0f), Y1 = __fmul_rn(y1, 1080.0f);
    float X2 = __fmul_rn(x2, 1920.0f), Y2 = __fmul_rn(y2, 1080.0f);
    op[0] = X1; op[1] = Y1; op[2] = X2; op[3] = Y2;
#pragma unroll
    for (int k = 0; k < 5; k++) {
        float lx = __fadd_rn(pcx, __fmul_rn(__fmul_rn(l[4 + 2 * k], 0.1f), pw));
        float ly = __fadd_rn(pcy, __fmul_rn(__fmul_rn(l[5 + 2 * k], 0.1f), ph));
        op[4 + 2 * k] = __fmul_rn(lx, 1920.0f);
        op[5 + 2 * k] = __fmul_rn(ly, 1080.0f);
    }
    g_boxes[b * 8192 + 0 * 2048 + r] = X1;
    g_boxes[b * 8192 + 1 * 2048 + r] = Y1;
    g_boxes[b * 8192 + 2 * 2048 + r] = X2;
    g_boxes[b * 8192 + 3 * 2048 + r] = Y2;
}

// ---------------------------------------------------------------------------
// K6a: suppression bitmask build (full chip). 64x64 rank tiles, upper tri.
// ---------------------------------------------------------------------------
__global__ void k_mask() {
    int jt = blockIdx.x, it = blockIdx.y, b = blockIdx.z;
    if (jt < it) return;
    __shared__ float cx1[64], cy1[64], cx2[64], cy2[64], ca[64];
    int t = threadIdx.x;
    int j0 = jt * 64;
    {
        float x1 = g_boxes[b * 8192 + 0 * 2048 + j0 + t];
        float y1 = g_boxes[b * 8192 + 1 * 2048 + j0 + t];
        float x2 = g_boxes[b * 8192 + 2 * 2048 + j0 + t];
        float y2 = g_boxes[b * 8192 + 3 * 2048 + j0 + t];
        cx1[t] = x1; cy1[t] = y1; cx2[t] = x2; cy2[t] = y2;
        ca[t] = __fmul_rn(fmaxf(__fsub_rn(x2, x1), 0.0f),
                          fmaxf(__fsub_rn(y2, y1), 0.0f));
    }
    __syncthreads();
    int i = it * 64 + t;
    float xi1 = g_boxes[b * 8192 + 0 * 2048 + i];
    float yi1 = g_boxes[b * 8192 + 1 * 2048 + i];
    float xi2 = g_boxes[b * 8192 + 2 * 2048 + i];
    float yi2 = g_boxes[b * 8192 + 3 * 2048 + i];
    float ai = __fmul_rn(fmaxf(__fsub_rn(xi2, xi1), 0.0f),
                         fmaxf(__fsub_rn(yi2, yi1), 0.0f));
    unsigned long long word = 0ULL;
    int jj0 = (jt == it) ? (t + 1) : 0;
    for (int jj = jj0; jj < 64; jj++) {
        float lx = fmaxf(xi1, cx1[jj]), ly = fmaxf(yi1, cy1[jj]);
        float rx = fminf(xi2, cx2[jj]), ry = fminf(yi2, cy2[jj]);
        float iw = fmaxf(__fsub_rn(rx, lx), 0.0f);
        float ih = fmaxf(__fsub_rn(ry, ly), 0.0f);
        float inter = __fmul_rn(iw, ih);
        if (inter > 0.0f) {  // division only when boxes overlap
            float denom = __fadd_rn(
                __fsub_rn(__fadd_rn(ai, ca[jj]), inter), 1e-9f);
            if (__fdiv_rn(inter, denom) > 0.3f) word |= (1ULL << jj);
        }
    }
    g_mask[((size_t)b * 2048 + i) * 32 + jt] = word;
}

// ---------------------------------------------------------------------------
// K6b: per-batch serial bitmask scan (warp 0; broadcasts prefetched off the
//      chain) + KEEP_TOP_K cumsum + write out col 14.
// ---------------------------------------------------------------------------
__global__ void k_serial(float* __restrict__ out) {
    __shared__ unsigned long long initm[32];
    __shared__ unsigned long long keepm[32];
    __shared__ float ss[2048];
    __shared__ int wtot[33];
    int b = blockIdx.x;
    int tid = threadIdx.x;
    int warp = tid >> 5, lane = tid & 31;

    for (int r = tid; r < 2048; r += 1024) {
        unsigned long long kk = g_top[b * 2048 + r];
        float sc = __uint_as_float((unsigned)(kk >> 32));
        ss[r] = (r < TOPK) ? sc : 0.0f;
    }
    __syncthreads();

    unsigned lo = __ballot_sync(0xffffffffu, ss[warp * 64 + lane] > 0.0f);
    unsigned hi = __ballot_sync(0xffffffffu, ss[warp * 64 + 32 + lane] > 0.0f);
    if (lane == 0) initm[warp] = ((unsigned long long)hi << 32) | lo;
    __syncthreads();

    if (warp == 0) {
        unsigned long long removed = ~initm[lane];  // bit set = inactive
        const unsigned long long* mrow = g_mask + (size_t)b * 2048 * 32;
        unsigned long long pf[8], bc[8];
#pragma unroll
        for (int k = 0; k < 8; k++) pf[k] = mrow[(size_t)k * 32 + lane];
#pragma unroll
        for (int k = 0; k < 8; k++) bc[k] = __shfl_sync(0xffffffffu, pf[k], 0);
        unsigned long long rm_w = __shfl_sync(0xffffffffu, removed, 0);
        for (int i0 = 0; i0 < 2048; i0 += 8) {
            unsigned long long npf[8];
            int nb = i0 + 8;
            if (nb < 2048) {
#pragma unroll
                for (int k = 0; k < 8; k++)
                    npf[k] = mrow[(size_t)(nb + k) * 32 + lane];
            } else {
#pragma unroll
                for (int k = 0; k < 8; k++) npf[k] = 0ULL;
            }
#pragma unroll
            for (int k = 0; k < 8; k++) {
                int i = i0 + k;
                int w = i >> 6;
                int bit = i & 63;
                if (bit == 0) rm_w = __shfl_sync(0xffffffffu, removed, w);
                unsigned long long msk =
                    ((rm_w >> bit) & 1ULL) ? 0ULL : ~0ULL;  // active?
                removed |= pf[k] & msk;
                rm_w |= bc[k] & msk;
            }
            // prefetch broadcasts for next group (off the serial chain)
#pragma unroll
            for (int k = 0; k < 8; k++)
                bc[k] = __shfl_sync(0xffffffffu, npf[k], (nb + k) >> 6);
#pragma unroll
            for (int k = 0; k < 8; k++) pf[k] = npf[k];
        }
        keepm[lane] = ~removed;
    }
    __syncthreads();

    int e0 = 2 * tid, e1 = 2 * tid + 1;
    int a0 = (int)((keepm[e0 >> 6] >> (e0 & 63)) & 1ULL);
    int a1 = (int)((keepm[e1 >> 6] >> (e1 & 63)) & 1ULL);
    int ps = a0 + a1;
    int v = ps;
#pragma unroll
    for (int o = 1; o < 32; o <<= 1) {
        int u = __shfl_up_sync(0xffffffffu, v, o);
        if (lane >= o) v += u;
    }
    if (lane == 31) wtot[warp] = v;
    __syncthreads();
    if (warp == 0) {
        int w = wtot[lane];
#pragma unroll
        for (int o = 1; o < 32; o <<= 1) {
            int u = __shfl_up_sync(0xffffffffu, w, o);
            if (lane >= o) w += u;
        }
        wtot[lane] = w;
    }
    __syncthreads();
    int base = (warp ? wtot[warp - 1] : 0) + v - ps;
    int c0 = base + a0;
    int c1 = c0 + a1;
    if (e0 < TOPK)
        out[((size_t)b * TOPK + e0) * 15 + 14] =
            ss[e0] * ((a0 && c0 <= KEEPK) ? 1.0f : 0.0f);
    if (e1 < TOPK)
        out[((size_t)b * TOPK + e1) * 15 + 14] =
            ss[e1] * ((a1 && c1 <= KEEPK) ? 1.0f : 0.0f);
}

// ---------------------------------------------------------------------------
extern "C" void kernel_launch(void* const* d_in, const int* in_sizes, int n_in,
                              void* d_out, int out_size) {
    const float* loc = nullptr;
    const float* conf = nullptr;
    const float* iou = nullptr;
    for (int i = 0; i < n_in; i++) {
        if (in_sizes[i] == NBATCH * NPRI * 14) loc = (const float*)d_in[i];
        else if (in_sizes[i] == NBATCH * NPRI * 2) conf = (const float*)d_in[i];
        else if (in_sizes[i] == NBATCH * NPRI) iou = (const float*)d_in[i];
    }
    float* out = (float*)d_out;

    void* hist_ptr = nullptr;
    cudaGetSymbolAddress(&hist_ptr, g_hist);
    cudaMemsetAsync(hist_ptr, 0, sizeof(unsigned) * NBATCH * NBINS, 0);
    k_init<<<1, 64>>>();

    dim3 gscore((NPRI + 255) / 256, NBATCH);
    k_scores<<<gscore, 256>>>((const float2*)conf, iou);
    k_pivot<<<NBATCH, 256>>>();
    k_compact<<<gscore, 256>>>();
    k_rescore<<<(NBATCH * CAP + 255) / 256, 256>>>((const float2*)conf, iou);

    cudaFuncSetAttribute(k_sort, cudaFuncAttributeMaxDynamicSharedMemorySize,
                         CAP * sizeof(unsigned long long));
    k_sort<<<NBATCH, 1024, CAP * sizeof(unsigned long long)>>>();

    k_decode<<<(NBATCH * TOPK + 127) / 128, 128>>>(loc, out);

    k_mask<<<dim3(32, 32, NBATCH), 64>>>();
    k_serial<<<NBATCH, 1024>>>(out);
}

// round 9
// speedup vs baseline: 8.4171x; 1.6157x over previous
#include <cuda_runtime.h>
#include <cuda_bf16.h>
#include <math.h>
#include <stdint.h>

#define NBATCH 16
#define NPRI   119130
#define TOPK   2000
#define KEEPK  750
#define CAP    8192
#define NBINS  256
#define BIN_OFF 16024   // (__float_as_uint(0.299f)>>16) == 16025 -> bin 1
#define TARGET 2300     // pivot margin over TOPK (absorbs 1e-6 approx error)

// Level layout (IMG 1920x1080, steps {8,16,32,64}):
// L0: off 0      cnt 97200  fw 240 step 8  nms 3  sizes {10,16,24}
// L1: off 97200  cnt 16320  fw 120 step 16 nms 2  sizes {32,48}
// L2: off 113520 cnt 4080   fw 60  step 32 nms 2  sizes {64,96}
// L3: off 117600 cnt 1530   fw 30  step 64 nms 3  sizes {128,192,256}

__device__ unsigned char      g_bins[NBATCH * NPRI];   // 0 = not candidate
__device__ unsigned int       g_hist[NBATCH * NBINS];
__device__ int                g_selcnt[NBATCH];
__device__ unsigned long long g_sel[NBATCH * CAP];
__device__ unsigned long long g_top[NBATCH * 2048];
__device__ float              g_boxes[NBATCH * 4 * 2048];
// suppression bitmask: [batch][row rank 0..2047][32 x 64-bit col words] = 8MB
__device__ unsigned long long g_mask[(size_t)NBATCH * 2048 * 32];
__device__ double             g_exp_tab[64];   // 2^(j/64)

// ---------------------------------------------------------------------------
// Fast fp64 exp via 64-entry table + degree-5 poly; error ~2^-52.
// Result rounded once to float == correctly-rounded expf w.p. 1-2^-27/call.
// ---------------------------------------------------------------------------
__device__ __forceinline__ double exp_pd(double x) {
    double t = x * 92.332482616893658071;                // 64*log2(e)
    int ni = __double2int_rn(t);
    double nd = (double)ni;
    double r = fma(nd, -1.0830424693267559625e-02, x);   // ln2_hi/64
    r = fma(nd, -2.9815858269852932813e-12, r);          // ln2_lo/64
    double q = 8.3333333333333333333e-03;                // 1/120
    q = fma(q, r, 4.1666666666666666667e-02);            // 1/24
    q = fma(q, r, 1.6666666666666666667e-01);            // 1/6
    q = fma(q, r, 0.5);
    q = fma(q, r, 1.0);
    q = q * r;                                           // expm1(r)
    double T = g_exp_tab[ni & 63];
    T = __longlong_as_double(__double_as_longlong(T) +
                             ((long long)(ni >> 6) << 52));
    return fma(T, q, T);
}

__device__ __forceinline__ float softmax1_exact(float c0, float c1) {
    if (c1 >= c0) {
        float e0 = (float)exp_pd((double)__fsub_rn(c0, c1));
        return __fdiv_rn(1.0f, __fadd_rn(e0, 1.0f));
    } else {
        float e1 = (float)exp_pd((double)__fsub_rn(c1, c0));
        return __fdiv_rn(e1, __fadd_rn(1.0f, e1));
    }
}

__device__ __forceinline__ unsigned char bin_of(float c0, float c1, float u) {
    float s = 0.0f;
    if (u > 0.0f) {
        float pf = 1.0f / (1.0f + __expf(c0 - c1));  // rel err ~1e-6
        float sf = sqrtf(pf * u);
        if (sf >= 0.299f) s = sf;                     // guard band
    }
    if (s <= 0.0f) return 0;
    int bin = (int)(__float_as_uint(s) >> 16) - BIN_OFF;
    return (unsigned char)min(max(bin, 1), 255);
}

// ---------------------------------------------------------------------------
// K1: approx scores -> u8 bins (2 priors/thread, vector loads) + 256-bin
//     histogram; also fills exp table and zeroes g_selcnt.
// grid: (ceil(NPRI/512), NBATCH) x 256 threads
// ---------------------------------------------------------------------------
__global__ void k_scores(const float* __restrict__ conf,
                         const float* __restrict__ iou) {
    __shared__ unsigned sh[NBINS];
    int b = blockIdx.y;
    int t = threadIdx.x;
    if (blockIdx.x == 0) {
        if (blockIdx.y == 0 && t < 64)
            g_exp_tab[t] = exp2((double)t * 0.015625);
        if (t == 0) g_selcnt[b] = 0;
    }
    sh[t] = 0;
    __syncthreads();
    int h = blockIdx.x * 256 + t;           // half-index (2 priors each)
    if (h < NPRI / 2) {
        const float4* cb = (const float4*)(conf + (size_t)b * NPRI * 2);
        const float2* ib = (const float2*)(iou + (size_t)b * NPRI);
        float4 c = cb[h];
        float2 uv = ib[h];
        float u0 = fminf(fmaxf(uv.x, 0.0f), 1.0f);
        float u1 = fminf(fmaxf(uv.y, 0.0f), 1.0f);
        unsigned char b0 = bin_of(c.x, c.y, u0);
        unsigned char b1 = bin_of(c.z, c.w, u1);
        ((unsigned short*)g_bins)[(size_t)b * (NPRI / 2) + h] =
            (unsigned short)(b0 | ((unsigned)b1 << 8));
        if (b0) atomicAdd(&sh[b0], 1u);
        if (b1) atomicAdd(&sh[b1], 1u);
    }
    __syncthreads();
    unsigned v = sh[t];
    if (v) atomicAdd(&g_hist[b * NBINS + t], v);
}

// ---------------------------------------------------------------------------
// K2: fused pivot (recomputed per block, deterministic) + compaction
//     (block-local) + dense exact rescore -> final sort keys in g_sel.
// ---------------------------------------------------------------------------
__global__ void k_compact(const float* __restrict__ conf,
                          const float* __restrict__ iou) {
    __shared__ unsigned s_wt[8];
    __shared__ int s_pivot;
    __shared__ int s_cnt;
    __shared__ int s_base;
    __shared__ int s_idx[512];
    int b = blockIdx.y;
    int t = threadIdx.x;
    int lane = t & 31, w = t >> 5;

    // --- pivot from histogram (identical algorithm to old k_pivot) ---
    unsigned hh = g_hist[b * NBINS + t];
    unsigned v = hh;
#pragma unroll
    for (int o = 1; o < 32; o <<= 1) {
        unsigned u = __shfl_up_sync(0xffffffffu, v, o);
        if (lane >= o) v += u;
    }
    if (lane == 31) s_wt[w] = v;
    if (t == 0) s_cnt = 0;
    __syncthreads();
    if (t < 8) {
        unsigned x = s_wt[t];
#pragma unroll
        for (int o = 1; o < 8; o <<= 1) {
            unsigned u = __shfl_up_sync(0xffu, x, o);
            if (t >= o) x += u;
        }
        s_wt[t] = x;
    }
    __syncthreads();
    unsigned pre = v + (w ? s_wt[w - 1] : 0);   // inclusive prefix
    unsigned total = s_wt[7];
    unsigned Ct = total - pre + hh;             // suffix sum from bin t
    bool qual = (Ct >= TARGET) && (t == 255 || (Ct - hh) < TARGET);
    if (qual) s_pivot = t;
    if (t == 0 && total < TARGET) s_pivot = 0;
    __syncthreads();
    int pivot = s_pivot;

    // --- compact candidates (2 priors/thread) into smem ---
    int h = blockIdx.x * 256 + t;
    if (h < NPRI / 2) {
        unsigned short bb =
            ((const unsigned short*)g_bins)[(size_t)b * (NPRI / 2) + h];
        int b0 = bb & 0xFF, b1 = bb >> 8;
        if (b0 && b0 >= pivot) s_idx[atomicAdd(&s_cnt, 1)] = 2 * h;
        if (b1 && b1 >= pivot) s_idx[atomicAdd(&s_cnt, 1)] = 2 * h + 1;
    }
    __syncthreads();
    int cnt = s_cnt;
    if (t == 0 && cnt > 0) s_base = atomicAdd(&g_selcnt[b], cnt);
    __syncthreads();

    // --- dense exact rescore of this block's candidates ---
    for (int k = t; k < cnt; k += 256) {
        int idx = s_idx[k];
        size_t e = (size_t)b * NPRI + (size_t)idx;
        float2 c = ((const float2*)conf)[e];
        float u = iou[e];
        u = fminf(fmaxf(u, 0.0f), 1.0f);
        float p = softmax1_exact(c.x, c.y);
        float s = __fsqrt_rn(__fmul_rn(p, u));
        unsigned long long key = 0ULL;
        if (s >= 0.3f)
            key = ((unsigned long long)__float_as_uint(s) << 32) |
                  (unsigned)(0x7FFFFFFF - idx);
        int pos = s_base + k;
        if (pos < CAP) g_sel[b * CAP + pos] = key;
    }
}

// ---------------------------------------------------------------------------
// K4: per-batch bitonic sort (desc), pair-indexed; emit top-2048 keys
// ---------------------------------------------------------------------------
__global__ void k_sort() {
    extern __shared__ unsigned long long keys[];
    int b = blockIdx.x;
    int tid = threadIdx.x;
    int m = g_selcnt[b];
    if (m > CAP) m = CAP;
    int nk = (m <= 2048) ? 2048 : ((m <= 4096) ? 4096 : 8192);
    for (int i = tid; i < nk; i += 1024)
        keys[i] = g_sel[b * CAP + i];   // zero-padded (g_sel pre-zeroed)
    int npairs = nk >> 1;
    for (int k = 2; k <= nk; k <<= 1) {
        for (int j = k >> 1; j > 0; j >>= 1) {
            __syncthreads();
            for (int p = tid; p < npairs; p += 1024) {
                int i = ((p & ~(j - 1)) << 1) | (p & (j - 1));
                int l = i + j;
                unsigned long long a = keys[i], bb = keys[l];
                bool up = ((i & k) == 0);
                if (up ? (a < bb) : (a > bb)) { keys[i] = bb; keys[l] = a; }
            }
        }
    }
    __syncthreads();
    for (int r = tid; r < 2048; r += 1024)
        g_top[b * 2048 + r] = (r < nk) ? keys[r] : 0ULL;
}

__constant__ float PW[10] = {
    (float)(10.0/1920.0),(float)(16.0/1920.0),(float)(24.0/1920.0),
    (float)(32.0/1920.0),(float)(48.0/1920.0),
    (float)(64.0/1920.0),(float)(96.0/1920.0),
    (float)(128.0/1920.0),(float)(192.0/1920.0),(float)(256.0/1920.0)};
__constant__ float PH[10] = {
    (float)(10.0/1080.0),(float)(16.0/1080.0),(float)(24.0/1080.0),
    (float)(32.0/1080.0),(float)(48.0/1080.0),
    (float)(64.0/1080.0),(float)(96.0/1080.0),
    (float)(128.0/1080.0),(float)(192.0/1080.0),(float)(256.0/1080.0)};

__device__ __forceinline__ void prior_of(int idx, float& pcx, float& pcy,
                                         float& pw, float& ph) {
    int off, fw, step, nm, msoff;
    if (idx < 97200)       { off = 0;      fw = 240; step = 8;  nm = 3; msoff = 0; }
    else if (idx < 113520) { off = 97200;  fw = 120; step = 16; nm = 2; msoff = 3; }
    else if (idx < 117600) { off = 113520; fw = 60;  step = 32; nm = 2; msoff = 5; }
    else                   { off = 117600; fw = 30;  step = 64; nm = 3; msoff = 7; }
    int r = idx - off;
    int cell = r / nm;
    int mi = r - cell * nm;
    int row = cell / fw;
    int col = cell - row * fw;
    double tx = ((double)col + 0.5) * (double)step;
    double ty = ((double)row + 0.5) * (double)step;
    pcx = (float)(tx * (1.0 / 1920.0));
    pcy = (float)(ty * (1.0 / 1080.0));
    pw = PW[msoff + mi];
    ph = PH[msoff + mi];
}

// ---------------------------------------------------------------------------
// K5: full-chip decode of top-2000 rows: out cols 0..13 + box SoA for NMS
// ---------------------------------------------------------------------------
__global__ void k_decode(const float* __restrict__ loc,
                         float* __restrict__ out) {
    int row = blockIdx.x * blockDim.x + threadIdx.x;
    if (row >= NBATCH * TOPK) return;
    int b = row / TOPK;
    int r = row - b * TOPK;
    unsigned long long kk = g_top[b * 2048 + r];
    int idx = 0x7FFFFFFF - (int)(unsigned)(kk & 0xFFFFFFFFu);
    if (idx < 0 || idx >= NPRI) idx = 0;

    float pcx, pcy, pw, ph;
    prior_of(idx, pcx, pcy, pw, ph);
    const float* lp = loc + ((size_t)b * NPRI + (size_t)idx) * 14;
    float l[14];
#pragma unroll
    for (int c = 0; c < 14; c++) l[c] = lp[c];

    float cx = __fadd_rn(pcx, __fmul_rn(__fmul_rn(l[0], 0.1f), pw));
    float cy = __fadd_rn(pcy, __fmul_rn(__fmul_rn(l[1], 0.1f), ph));
    float w  = __fmul_rn(pw, (float)exp_pd((double)__fmul_rn(l[2], 0.1f)));
    float h  = __fmul_rn(ph, (float)exp_pd((double)__fmul_rn(l[3], 0.2f)));
    float x1 = __fsub_rn(cx, __fmul_rn(w, 0.5f));
    float y1 = __fsub_rn(cy, __fmul_rn(h, 0.5f));
    float x2 = __fadd_rn(x1, w);
    float y2 = __fadd_rn(y1, h);

    float* op = out + (size_t)row * 15;
    float X1 = __fmul_rn(x1, 1920.0f), Y1 = __fmul_rn(y1, 1080.0f);
    float X2 = __fmul_rn(x2, 1920.0f), Y2 = __fmul_rn(y2, 1080.0f);
    op[0] = X1; op[1] = Y1; op[2] = X2; op[3] = Y2;
#pragma unroll
    for (int k = 0; k < 5; k++) {
        float lx = __fadd_rn(pcx, __fmul_rn(__fmul_rn(l[4 + 2 * k], 0.1f), pw));
        float ly = __fadd_rn(pcy, __fmul_rn(__fmul_rn(l[5 + 2 * k], 0.1f), ph));
        op[4 + 2 * k] = __fmul_rn(lx, 1920.0f);
        op[5 + 2 * k] = __fmul_rn(ly, 1080.0f);
    }
    g_boxes[b * 8192 + 0 * 2048 + r] = X1;
    g_boxes[b * 8192 + 1 * 2048 + r] = Y1;
    g_boxes[b * 8192 + 2 * 2048 + r] = X2;
    g_boxes[b * 8192 + 3 * 2048 + r] = Y2;
}

// ---------------------------------------------------------------------------
// K6a: suppression bitmask build (full chip). 64x64 rank tiles, upper tri.
// ---------------------------------------------------------------------------
__global__ void k_mask() {
    int jt = blockIdx.x, it = blockIdx.y, b = blockIdx.z;
    if (jt < it) return;
    __shared__ float cx1[64], cy1[64], cx2[64], cy2[64], ca[64];
    int t = threadIdx.x;
    int j0 = jt * 64;
    {
        float x1 = g_boxes[b * 8192 + 0 * 2048 + j0 + t];
        float y1 = g_boxes[b * 8192 + 1 * 2048 + j0 + t];
        float x2 = g_boxes[b * 8192 + 2 * 2048 + j0 + t];
        float y2 = g_boxes[b * 8192 + 3 * 2048 + j0 + t];
        cx1[t] = x1; cy1[t] = y1; cx2[t] = x2; cy2[t] = y2;
        ca[t] = __fmul_rn(fmaxf(__fsub_rn(x2, x1), 0.0f),
                          fmaxf(__fsub_rn(y2, y1), 0.0f));
    }
    __syncthreads();
    int i = it * 64 + t;
    float xi1 = g_boxes[b * 8192 + 0 * 2048 + i];
    float yi1 = g_boxes[b * 8192 + 1 * 2048 + i];
    float xi2 = g_boxes[b * 8192 + 2 * 2048 + i];
    float yi2 = g_boxes[b * 8192 + 3 * 2048 + i];
    float ai = __fmul_rn(fmaxf(__fsub_rn(xi2, xi1), 0.0f),
                         fmaxf(__fsub_rn(yi2, yi1), 0.0f));
    unsigned long long word = 0ULL;
    int jj0 = (jt == it) ? (t + 1) : 0;
    for (int jj = jj0; jj < 64; jj++) {
        float lx = fmaxf(xi1, cx1[jj]), ly = fmaxf(yi1, cy1[jj]);
        float rx = fminf(xi2, cx2[jj]), ry = fminf(yi2, cy2[jj]);
        float iw = fmaxf(__fsub_rn(rx, lx), 0.0f);
        float ih = fmaxf(__fsub_rn(ry, ly), 0.0f);
        float inter = __fmul_rn(iw, ih);
        if (inter > 0.0f) {  // division only when boxes overlap
            float denom = __fadd_rn(
                __fsub_rn(__fadd_rn(ai, ca[jj]), inter), 1e-9f);
            if (__fdiv_rn(inter, denom) > 0.3f) word |= (1ULL << jj);
        }
    }
    g_mask[((size_t)b * 2048 + i) * 32 + jt] = word;
}

// ---------------------------------------------------------------------------
// K6b: per-batch serial bitmask scan (warp 0; broadcasts prefetched off the
//      chain) + KEEP_TOP_K cumsum + write out col 14.
// ---------------------------------------------------------------------------
__global__ void k_serial(float* __restrict__ out) {
    __shared__ unsigned long long initm[32];
    __shared__ unsigned long long keepm[32];
    __shared__ float ss[2048];
    __shared__ int wtot[33];
    int b = blockIdx.x;
    int tid = threadIdx.x;
    int warp = tid >> 5, lane = tid & 31;

    for (int r = tid; r < 2048; r += 1024) {
        unsigned long long kk = g_top[b * 2048 + r];
        float sc = __uint_as_float((unsigned)(kk >> 32));
        ss[r] = (r < TOPK) ? sc : 0.0f;
    }
    __syncthreads();

    unsigned lo = __ballot_sync(0xffffffffu, ss[warp * 64 + lane] > 0.0f);
    unsigned hi = __ballot_sync(0xffffffffu, ss[warp * 64 + 32 + lane] > 0.0f);
    if (lane == 0) initm[warp] = ((unsigned long long)hi << 32) | lo;
    __syncthreads();

    if (warp == 0) {
        unsigned long long removed = ~initm[lane];  // bit set = inactive
        const unsigned long long* mrow = g_mask + (size_t)b * 2048 * 32;
        unsigned long long pf[8], bc[8];
#pragma unroll
        for (int k = 0; k < 8; k++) pf[k] = mrow[(size_t)k * 32 + lane];
#pragma unroll
        for (int k = 0; k < 8; k++) bc[k] = __shfl_sync(0xffffffffu, pf[k], 0);
        unsigned long long rm_w = __shfl_sync(0xffffffffu, removed, 0);
        for (int i0 = 0; i0 < 2048; i0 += 8) {
            unsigned long long npf[8];
            int nb = i0 + 8;
            if (nb < 2048) {
#pragma unroll
                for (int k = 0; k < 8; k++)
                    npf[k] = mrow[(size_t)(nb + k) * 32 + lane];
            } else {
#pragma unroll
                for (int k = 0; k < 8; k++) npf[k] = 0ULL;
            }
#pragma unroll
            for (int k = 0; k < 8; k++) {
                int i = i0 + k;
                int w = i >> 6;
                int bit = i & 63;
                if (bit == 0) rm_w = __shfl_sync(0xffffffffu, removed, w);
                unsigned long long msk =
                    ((rm_w >> bit) & 1ULL) ? 0ULL : ~0ULL;  // active?
                removed |= pf[k] & msk;
                rm_w |= bc[k] & msk;
            }
#pragma unroll
            for (int k = 0; k < 8; k++)
                bc[k] = __shfl_sync(0xffffffffu, npf[k], (nb + k) >> 6);
#pragma unroll
            for (int k = 0; k < 8; k++) pf[k] = npf[k];
        }
        keepm[lane] = ~removed;
    }
    __syncthreads();

    int e0 = 2 * tid, e1 = 2 * tid + 1;
    int a0 = (int)((keepm[e0 >> 6] >> (e0 & 63)) & 1ULL);
    int a1 = (int)((keepm[e1 >> 6] >> (e1 & 63)) & 1ULL);
    int ps = a0 + a1;
    int v = ps;
#pragma unroll
    for (int o = 1; o < 32; o <<= 1) {
        int u = __shfl_up_sync(0xffffffffu, v, o);
        if (lane >= o) v += u;
    }
    if (lane == 31) wtot[warp] = v;
    __syncthreads();
    if (warp == 0) {
        int w = wtot[lane];
#pragma unroll
        for (int o = 1; o < 32; o <<= 1) {
            int u = __shfl_up_sync(0xffffffffu, w, o);
            if (lane >= o) w += u;
        }
        wtot[lane] = w;
    }
    __syncthreads();
    int base = (warp ? wtot[warp - 1] : 0) + v - ps;
    int c0 = base + a0;
    int c1 = c0 + a1;
    if (e0 < TOPK)
        out[((size_t)b * TOPK + e0) * 15 + 14] =
            ss[e0] * ((a0 && c0 <= KEEPK) ? 1.0f : 0.0f);
    if (e1 < TOPK)
        out[((size_t)b * TOPK + e1) * 15 + 14] =
            ss[e1] * ((a1 && c1 <= KEEPK) ? 1.0f : 0.0f);
}

// ---------------------------------------------------------------------------
extern "C" void kernel_launch(void* const* d_in, const int* in_sizes, int n_in,
                              void* d_out, int out_size) {
    const float* loc = nullptr;
    const float* conf = nullptr;
    const float* iou = nullptr;
    for (int i = 0; i < n_in; i++) {
        if (in_sizes[i] == NBATCH * NPRI * 14) loc = (const float*)d_in[i];
        else if (in_sizes[i] == NBATCH * NPRI * 2) conf = (const float*)d_in[i];
        else if (in_sizes[i] == NBATCH * NPRI) iou = (const float*)d_in[i];
    }
    float* out = (float*)d_out;

    void* hist_ptr = nullptr;
    cudaGetSymbolAddress(&hist_ptr, g_hist);
    cudaMemsetAsync(hist_ptr, 0, sizeof(unsigned) * NBATCH * NBINS, 0);
    void* sel_ptr = nullptr;
    cudaGetSymbolAddress(&sel_ptr, g_sel);
    cudaMemsetAsync(sel_ptr, 0,
                    sizeof(unsigned long long) * NBATCH * CAP, 0);

    dim3 ghalf((NPRI / 2 + 255) / 256, NBATCH);
    k_scores<<<ghalf, 256>>>(conf, iou);
    k_compact<<<ghalf, 256>>>(conf, iou);

    cudaFuncSetAttribute(k_sort, cudaFuncAttributeMaxDynamicSharedMemorySize,
                         CAP * sizeof(unsigned long long));
    k_sort<<<NBATCH, 1024, CAP * sizeof(unsigned long long)>>>();

    k_decode<<<(NBATCH * TOPK + 127) / 128, 128>>>(loc, out);

    k_mask<<<dim3(32, 32, NBATCH), 64>>>();
    k_serial<<<NBATCH, 1024>>>(out);
}

// round 10
// speedup vs baseline: 8.4894x; 1.0086x over previous
#include <cuda_runtime.h>
#include <cuda_bf16.h>
#include <math.h>
#include <stdint.h>

#define NBATCH 16
#define NPRI   119130
#define TOPK   2000
#define KEEPK  750
#define CAP    8192
#define NBINS  256
#define BIN_OFF 16024   // (__float_as_uint(0.299f)>>16) == 16025 -> bin 1
#define TARGET 2300     // pivot margin over TOPK (absorbs 1e-6 approx error)

// Level layout (IMG 1920x1080, steps {8,16,32,64}):
// L0: off 0      cnt 97200  fw 240 step 8  nms 3  sizes {10,16,24}
// L1: off 97200  cnt 16320  fw 120 step 16 nms 2  sizes {32,48}
// L2: off 113520 cnt 4080   fw 60  step 32 nms 2  sizes {64,96}
// L3: off 117600 cnt 1530   fw 30  step 64 nms 3  sizes {128,192,256}

__device__ unsigned char      g_bins[NBATCH * NPRI];   // 0 = not candidate
__device__ unsigned int       g_hist[NBATCH * NBINS];
__device__ int                g_selcnt[NBATCH];
__device__ unsigned long long g_sel[NBATCH * CAP];
__device__ unsigned long long g_top[NBATCH * 2048];
__device__ float              g_boxes[NBATCH * 4 * 2048];
// suppression bitmask: [batch][row rank 0..2047][32 x 64-bit col words] = 8MB
__device__ unsigned long long g_mask[(size_t)NBATCH * 2048 * 32];
__device__ double             g_exp_tab[64];   // 2^(j/64)

// ---------------------------------------------------------------------------
// Fast fp64 exp via 64-entry table + degree-5 poly; error ~2^-52.
// Result rounded once to float == correctly-rounded expf w.p. 1-2^-27/call.
// ---------------------------------------------------------------------------
__device__ __forceinline__ double exp_pd(double x) {
    double t = x * 92.332482616893658071;                // 64*log2(e)
    int ni = __double2int_rn(t);
    double nd = (double)ni;
    double r = fma(nd, -1.0830424693267559625e-02, x);   // ln2_hi/64
    r = fma(nd, -2.9815858269852932813e-12, r);          // ln2_lo/64
    double q = 8.3333333333333333333e-03;                // 1/120
    q = fma(q, r, 4.1666666666666666667e-02);            // 1/24
    q = fma(q, r, 1.6666666666666666667e-01);            // 1/6
    q = fma(q, r, 0.5);
    q = fma(q, r, 1.0);
    q = q * r;                                           // expm1(r)
    double T = g_exp_tab[ni & 63];
    T = __longlong_as_double(__double_as_longlong(T) +
                             ((long long)(ni >> 6) << 52));
    return fma(T, q, T);
}

__device__ __forceinline__ float softmax1_exact(float c0, float c1) {
    if (c1 >= c0) {
        float e0 = (float)exp_pd((double)__fsub_rn(c0, c1));
        return __fdiv_rn(1.0f, __fadd_rn(e0, 1.0f));
    } else {
        float e1 = (float)exp_pd((double)__fsub_rn(c1, c0));
        return __fdiv_rn(e1, __fadd_rn(1.0f, e1));
    }
}

__device__ __forceinline__ unsigned char bin_of(float c0, float c1, float u) {
    float s = 0.0f;
    if (u > 0.0f) {
        float pf = 1.0f / (1.0f + __expf(c0 - c1));  // rel err ~1e-6
        float sf = sqrtf(pf * u);
        if (sf >= 0.299f) s = sf;                     // guard band
    }
    if (s <= 0.0f) return 0;
    int bin = (int)(__float_as_uint(s) >> 16) - BIN_OFF;
    return (unsigned char)min(max(bin, 1), 255);
}

// ---------------------------------------------------------------------------
// K1: approx scores -> u8 bins (2 priors/thread, vector loads) + 256-bin
//     histogram; also fills exp table and zeroes g_selcnt.
// grid: (ceil(NPRI/512), NBATCH) x 256 threads
// ---------------------------------------------------------------------------
__global__ void k_scores(const float* __restrict__ conf,
                         const float* __restrict__ iou) {
    __shared__ unsigned sh[NBINS];
    int b = blockIdx.y;
    int t = threadIdx.x;
    if (blockIdx.x == 0) {
        if (blockIdx.y == 0 && t < 64)
            g_exp_tab[t] = exp2((double)t * 0.015625);
        if (t == 0) g_selcnt[b] = 0;
    }
    sh[t] = 0;
    __syncthreads();
    int h = blockIdx.x * 256 + t;           // half-index (2 priors each)
    if (h < NPRI / 2) {
        const float4* cb = (const float4*)(conf + (size_t)b * NPRI * 2);
        const float2* ib = (const float2*)(iou + (size_t)b * NPRI);
        float4 c = cb[h];
        float2 uv = ib[h];
        float u0 = fminf(fmaxf(uv.x, 0.0f), 1.0f);
        float u1 = fminf(fmaxf(uv.y, 0.0f), 1.0f);
        unsigned char b0 = bin_of(c.x, c.y, u0);
        unsigned char b1 = bin_of(c.z, c.w, u1);
        ((unsigned short*)g_bins)[(size_t)b * (NPRI / 2) + h] =
            (unsigned short)(b0 | ((unsigned)b1 << 8));
        if (b0) atomicAdd(&sh[b0], 1u);
        if (b1) atomicAdd(&sh[b1], 1u);
    }
    __syncthreads();
    unsigned v = sh[t];
    if (v) atomicAdd(&g_hist[b * NBINS + t], v);
}

// ---------------------------------------------------------------------------
// K2: fused pivot (recomputed per block, deterministic) + compaction
//     (block-local) + dense exact rescore -> final sort keys in g_sel.
// ---------------------------------------------------------------------------
__global__ void k_compact(const float* __restrict__ conf,
                          const float* __restrict__ iou) {
    __shared__ unsigned s_wt[8];
    __shared__ int s_pivot;
    __shared__ int s_cnt;
    __shared__ int s_base;
    __shared__ int s_idx[512];
    int b = blockIdx.y;
    int t = threadIdx.x;
    int lane = t & 31, w = t >> 5;

    // --- pivot from histogram (identical algorithm to old k_pivot) ---
    unsigned hh = g_hist[b * NBINS + t];
    unsigned v = hh;
#pragma unroll
    for (int o = 1; o < 32; o <<= 1) {
        unsigned u = __shfl_up_sync(0xffffffffu, v, o);
        if (lane >= o) v += u;
    }
    if (lane == 31) s_wt[w] = v;
    if (t == 0) s_cnt = 0;
    __syncthreads();
    if (t < 8) {
        unsigned x = s_wt[t];
#pragma unroll
        for (int o = 1; o < 8; o <<= 1) {
            unsigned u = __shfl_up_sync(0xffu, x, o);
            if (t >= o) x += u;
        }
        s_wt[t] = x;
    }
    __syncthreads();
    unsigned pre = v + (w ? s_wt[w - 1] : 0);   // inclusive prefix
    unsigned total = s_wt[7];
    unsigned Ct = total - pre + hh;             // suffix sum from bin t
    bool qual = (Ct >= TARGET) && (t == 255 || (Ct - hh) < TARGET);
    if (qual) s_pivot = t;
    if (t == 0 && total < TARGET) s_pivot = 0;
    __syncthreads();
    int pivot = s_pivot;

    // --- compact candidates (2 priors/thread) into smem ---
    int h = blockIdx.x * 256 + t;
    if (h < NPRI / 2) {
        unsigned short bb =
            ((const unsigned short*)g_bins)[(size_t)b * (NPRI / 2) + h];
        int b0 = bb & 0xFF, b1 = bb >> 8;
        if (b0 && b0 >= pivot) s_idx[atomicAdd(&s_cnt, 1)] = 2 * h;
        if (b1 && b1 >= pivot) s_idx[atomicAdd(&s_cnt, 1)] = 2 * h + 1;
    }
    __syncthreads();
    int cnt = s_cnt;
    if (t == 0 && cnt > 0) s_base = atomicAdd(&g_selcnt[b], cnt);
    __syncthreads();

    // --- dense exact rescore of this block's candidates ---
    for (int k = t; k < cnt; k += 256) {
        int idx = s_idx[k];
        size_t e = (size_t)b * NPRI + (size_t)idx;
        float2 c = ((const float2*)conf)[e];
        float u = iou[e];
        u = fminf(fmaxf(u, 0.0f), 1.0f);
        float p = softmax1_exact(c.x, c.y);
        float s = __fsqrt_rn(__fmul_rn(p, u));
        unsigned long long key = 0ULL;
        if (s >= 0.3f)
            key = ((unsigned long long)__float_as_uint(s) << 32) |
                  (unsigned)(0x7FFFFFFF - idx);
        int pos = s_base + k;
        if (pos < CAP) g_sel[b * CAP + pos] = key;
    }
}

// ---------------------------------------------------------------------------
// K4: per-batch bitonic sort (desc), pair-indexed; emit top-2048 keys
// ---------------------------------------------------------------------------
__global__ void k_sort() {
    extern __shared__ unsigned long long keys[];
    int b = blockIdx.x;
    int tid = threadIdx.x;
    int m = g_selcnt[b];
    if (m > CAP) m = CAP;
    int nk = (m <= 2048) ? 2048 : ((m <= 4096) ? 4096 : 8192);
    for (int i = tid; i < nk; i += 1024)
        keys[i] = g_sel[b * CAP + i];   // zero-padded (g_sel pre-zeroed)
    int npairs = nk >> 1;
    for (int k = 2; k <= nk; k <<= 1) {
        for (int j = k >> 1; j > 0; j >>= 1) {
            __syncthreads();
            for (int p = tid; p < npairs; p += 1024) {
                int i = ((p & ~(j - 1)) << 1) | (p & (j - 1));
                int l = i + j;
                unsigned long long a = keys[i], bb = keys[l];
                bool up = ((i & k) == 0);
                if (up ? (a < bb) : (a > bb)) { keys[i] = bb; keys[l] = a; }
            }
        }
    }
    __syncthreads();
    for (int r = tid; r < 2048; r += 1024)
        g_top[b * 2048 + r] = (r < nk) ? keys[r] : 0ULL;
}

__constant__ float PW[10] = {
    (float)(10.0/1920.0),(float)(16.0/1920.0),(float)(24.0/1920.0),
    (float)(32.0/1920.0),(float)(48.0/1920.0),
    (float)(64.0/1920.0),(float)(96.0/1920.0),
    (float)(128.0/1920.0),(float)(192.0/1920.0),(float)(256.0/1920.0)};
__constant__ float PH[10] = {
    (float)(10.0/1080.0),(float)(16.0/1080.0),(float)(24.0/1080.0),
    (float)(32.0/1080.0),(float)(48.0/1080.0),
    (float)(64.0/1080.0),(float)(96.0/1080.0),
    (float)(128.0/1080.0),(float)(192.0/1080.0),(float)(256.0/1080.0)};

__device__ __forceinline__ void prior_of(int idx, float& pcx, float& pcy,
                                         float& pw, float& ph) {
    int off, fw, step, nm, msoff;
    if (idx < 97200)       { off = 0;      fw = 240; step = 8;  nm = 3; msoff = 0; }
    else if (idx < 113520) { off = 97200;  fw = 120; step = 16; nm = 2; msoff = 3; }
    else if (idx < 117600) { off = 113520; fw = 60;  step = 32; nm = 2; msoff = 5; }
    else                   { off = 117600; fw = 30;  step = 64; nm = 3; msoff = 7; }
    int r = idx - off;
    int cell = r / nm;
    int mi = r - cell * nm;
    int row = cell / fw;
    int col = cell - row * fw;
    double tx = ((double)col + 0.5) * (double)step;
    double ty = ((double)row + 0.5) * (double)step;
    pcx = (float)(tx * (1.0 / 1920.0));
    pcy = (float)(ty * (1.0 / 1080.0));
    pw = PW[msoff + mi];
    ph = PH[msoff + mi];
}

// ---------------------------------------------------------------------------
// K5: full-chip decode of top-2000 rows: out cols 0..13 + box SoA for NMS
// ---------------------------------------------------------------------------
__global__ void k_decode(const float* __restrict__ loc,
                         float* __restrict__ out) {
    int row = blockIdx.x * blockDim.x + threadIdx.x;
    if (row >= NBATCH * TOPK) return;
    int b = row / TOPK;
    int r = row - b * TOPK;
    unsigned long long kk = g_top[b * 2048 + r];
    int idx = 0x7FFFFFFF - (int)(unsigned)(kk & 0xFFFFFFFFu);
    if (idx < 0 || idx >= NPRI) idx = 0;

    float pcx, pcy, pw, ph;
    prior_of(idx, pcx, pcy, pw, ph);
    const float* lp = loc + ((size_t)b * NPRI + (size_t)idx) * 14;
    float l[14];
#pragma unroll
    for (int c = 0; c < 14; c++) l[c] = lp[c];

    float cx = __fadd_rn(pcx, __fmul_rn(__fmul_rn(l[0], 0.1f), pw));
    float cy = __fadd_rn(pcy, __fmul_rn(__fmul_rn(l[1], 0.1f), ph));
    float w  = __fmul_rn(pw, (float)exp_pd((double)__fmul_rn(l[2], 0.1f)));
    float h  = __fmul_rn(ph, (float)exp_pd((double)__fmul_rn(l[3], 0.2f)));
    float x1 = __fsub_rn(cx, __fmul_rn(w, 0.5f));
    float y1 = __fsub_rn(cy, __fmul_rn(h, 0.5f));
    float x2 = __fadd_rn(x1, w);
    float y2 = __fadd_rn(y1, h);

    float* op = out + (size_t)row * 15;
    float X1 = __fmul_rn(x1, 1920.0f), Y1 = __fmul_rn(y1, 1080.0f);
    float X2 = __fmul_rn(x2, 1920.0f), Y2 = __fmul_rn(y2, 1080.0f);
    op[0] = X1; op[1] = Y1; op[2] = X2; op[3] = Y2;
#pragma unroll
    for (int k = 0; k < 5; k++) {
        float lx = __fadd_rn(pcx, __fmul_rn(__fmul_rn(l[4 + 2 * k], 0.1f), pw));
        float ly = __fadd_rn(pcy, __fmul_rn(__fmul_rn(l[5 + 2 * k], 0.1f), ph));
        op[4 + 2 * k] = __fmul_rn(lx, 1920.0f);
        op[5 + 2 * k] = __fmul_rn(ly, 1080.0f);
    }
    g_boxes[b * 8192 + 0 * 2048 + r] = X1;
    g_boxes[b * 8192 + 1 * 2048 + r] = Y1;
    g_boxes[b * 8192 + 2 * 2048 + r] = X2;
    g_boxes[b * 8192 + 3 * 2048 + r] = Y2;
}

// ---------------------------------------------------------------------------
// K6a: suppression bitmask build (full chip). 64x64 rank tiles, upper tri.
// ---------------------------------------------------------------------------
__global__ void k_mask() {
    int jt = blockIdx.x, it = blockIdx.y, b = blockIdx.z;
    if (jt < it) return;
    __shared__ float cx1[64], cy1[64], cx2[64], cy2[64], ca[64];
    int t = threadIdx.x;
    int j0 = jt * 64;
    {
        float x1 = g_boxes[b * 8192 + 0 * 2048 + j0 + t];
        float y1 = g_boxes[b * 8192 + 1 * 2048 + j0 + t];
        float x2 = g_boxes[b * 8192 + 2 * 2048 + j0 + t];
        float y2 = g_boxes[b * 8192 + 3 * 2048 + j0 + t];
        cx1[t] = x1; cy1[t] = y1; cx2[t] = x2; cy2[t] = y2;
        ca[t] = __fmul_rn(fmaxf(__fsub_rn(x2, x1), 0.0f),
                          fmaxf(__fsub_rn(y2, y1), 0.0f));
    }
    __syncthreads();
    int i = it * 64 + t;
    float xi1 = g_boxes[b * 8192 + 0 * 2048 + i];
    float yi1 = g_boxes[b * 8192 + 1 * 2048 + i];
    float xi2 = g_boxes[b * 8192 + 2 * 2048 + i];
    float yi2 = g_boxes[b * 8192 + 3 * 2048 + i];
    float ai = __fmul_rn(fmaxf(__fsub_rn(xi2, xi1), 0.0f),
                         fmaxf(__fsub_rn(yi2, yi1), 0.0f));
    unsigned long long word = 0ULL;
    int jj0 = (jt == it) ? (t + 1) : 0;
    for (int jj = jj0; jj < 64; jj++) {
        float lx = fmaxf(xi1, cx1[jj]), ly = fmaxf(yi1, cy1[jj]);
        float rx = fminf(xi2, cx2[jj]), ry = fminf(yi2, cy2[jj]);
        float iw = fmaxf(__fsub_rn(rx, lx), 0.0f);
        float ih = fmaxf(__fsub_rn(ry, ly), 0.0f);
        float inter = __fmul_rn(iw, ih);
        if (inter > 0.0f) {  // division only when boxes overlap
            float denom = __fadd_rn(
                __fsub_rn(__fadd_rn(ai, ca[jj]), inter), 1e-9f);
            if (__fdiv_rn(inter, denom) > 0.3f) word |= (1ULL << jj);
        }
    }
    g_mask[((size_t)b * 2048 + i) * 32 + jt] = word;
}

// ---------------------------------------------------------------------------
// K6b: per-batch serial bitmask scan (warp 0; broadcasts prefetched off the
//      chain) + KEEP_TOP_K cumsum + write out col 14.
// ---------------------------------------------------------------------------
__global__ void k_serial(float* __restrict__ out) {
    __shared__ unsigned long long initm[32];
    __shared__ unsigned long long keepm[32];
    __shared__ float ss[2048];
    __shared__ int wtot[33];
    int b = blockIdx.x;
    int tid = threadIdx.x;
    int warp = tid >> 5, lane = tid & 31;

    for (int r = tid; r < 2048; r += 1024) {
        unsigned long long kk = g_top[b * 2048 + r];
        float sc = __uint_as_float((unsigned)(kk >> 32));
        ss[r] = (r < TOPK) ? sc : 0.0f;
    }
    __syncthreads();

    unsigned lo = __ballot_sync(0xffffffffu, ss[warp * 64 + lane] > 0.0f);
    unsigned hi = __ballot_sync(0xffffffffu, ss[warp * 64 + 32 + lane] > 0.0f);
    if (lane == 0) initm[warp] = ((unsigned long long)hi << 32) | lo;
    __syncthreads();

    if (warp == 0) {
        unsigned long long removed = ~initm[lane];  // bit set = inactive
        const unsigned long long* mrow = g_mask + (size_t)b * 2048 * 32;
        unsigned long long pf[8], bc[8];
#pragma unroll
        for (int k = 0; k < 8; k++) pf[k] = mrow[(size_t)k * 32 + lane];
#pragma unroll
        for (int k = 0; k < 8; k++) bc[k] = __shfl_sync(0xffffffffu, pf[k], 0);
        unsigned long long rm_w = __shfl_sync(0xffffffffu, removed, 0);
        for (int i0 = 0; i0 < 2048; i0 += 8) {
            unsigned long long npf[8];
            int nb = i0 + 8;
            if (nb < 2048) {
#pragma unroll
                for (int k = 0; k < 8; k++)
                    npf[k] = mrow[(size_t)(nb + k) * 32 + lane];
            } else {
#pragma unroll
                for (int k = 0; k < 8; k++) npf[k] = 0ULL;
            }
#pragma unroll
            for (int k = 0; k < 8; k++) {
                int i = i0 + k;
                int w = i >> 6;
                int bit = i & 63;
                if (bit == 0) rm_w = __shfl_sync(0xffffffffu, removed, w);
                unsigned long long msk =
                    ((rm_w >> bit) & 1ULL) ? 0ULL : ~0ULL;  // active?
                removed |= pf[k] & msk;
                rm_w |= bc[k] & msk;
            }
#pragma unroll
            for (int k = 0; k < 8; k++)
                bc[k] = __shfl_sync(0xffffffffu, npf[k], (nb + k) >> 6);
#pragma unroll
            for (int k = 0; k < 8; k++) pf[k] = npf[k];
        }
        keepm[lane] = ~removed;
    }
    __syncthreads();

    int e0 = 2 * tid, e1 = 2 * tid + 1;
    int a0 = (int)((keepm[e0 >> 6] >> (e0 & 63)) & 1ULL);
    int a1 = (int)((keepm[e1 >> 6] >> (e1 & 63)) & 1ULL);
    int ps = a0 + a1;
    int v = ps;
#pragma unroll
    for (int o = 1; o < 32; o <<= 1) {
        int u = __shfl_up_sync(0xffffffffu, v, o);
        if (lane >= o) v += u;
    }
    if (lane == 31) wtot[warp] = v;
    __syncthreads();
    if (warp == 0) {
        int w = wtot[lane];
#pragma unroll
        for (int o = 1; o < 32; o <<= 1) {
            int u = __shfl_up_sync(0xffffffffu, w, o);
            if (lane >= o) w += u;
        }
        wtot[lane] = w;
    }
    __syncthreads();
    int base = (warp ? wtot[warp - 1] : 0) + v - ps;
    int c0 = base + a0;
    int c1 = c0 + a1;
    if (e0 < TOPK)
        out[((size_t)b * TOPK + e0) * 15 + 14] =
            ss[e0] * ((a0 && c0 <= KEEPK) ? 1.0f : 0.0f);
    if (e1 < TOPK)
        out[((size_t)b * TOPK + e1) * 15 + 14] =
            ss[e1] * ((a1 && c1 <= KEEPK) ? 1.0f : 0.0f);
}

// ---------------------------------------------------------------------------
extern "C" void kernel_launch(void* const* d_in, const int* in_sizes, int n_in,
                              void* d_out, int out_size) {
    const float* loc = nullptr;
    const float* conf = nullptr;
    const float* iou = nullptr;
    for (int i = 0; i < n_in; i++) {
        if (in_sizes[i] == NBATCH * NPRI * 14) loc = (const float*)d_in[i];
        else if (in_sizes[i] == NBATCH * NPRI * 2) conf = (const float*)d_in[i];
        else if (in_sizes[i] == NBATCH * NPRI) iou = (const float*)d_in[i];
    }
    float* out = (float*)d_out;

    void* hist_ptr = nullptr;
    cudaGetSymbolAddress(&hist_ptr, g_hist);
    cudaMemsetAsync(hist_ptr, 0, sizeof(unsigned) * NBATCH * NBINS, 0);
    void* sel_ptr = nullptr;
    cudaGetSymbolAddress(&sel_ptr, g_sel);
    cudaMemsetAsync(sel_ptr, 0,
                    sizeof(unsigned long long) * NBATCH * CAP, 0);

    dim3 ghalf((NPRI / 2 + 255) / 256, NBATCH);
    k_scores<<<ghalf, 256>>>(conf, iou);
    k_compact<<<ghalf, 256>>>(conf, iou);

    cudaFuncSetAttribute(k_sort, cudaFuncAttributeMaxDynamicSharedMemorySize,
                         CAP * sizeof(unsigned long long));
    k_sort<<<NBATCH, 1024, CAP * sizeof(unsigned long long)>>>();

    k_decode<<<(NBATCH * TOPK + 127) / 128, 128>>>(loc, out);

    k_mask<<<dim3(32, 32, NBATCH), 64>>>();
    k_serial<<<NBATCH, 1024>>>(out);
}

// round 12
// speedup vs baseline: 11.9316x; 1.4055x over previous
#include <cuda_runtime.h>
#include <cuda_bf16.h>
#include <math.h>
#include <stdint.h>

#define NBATCH 16
#define NPRI   119130
#define TOPK   2000
#define KEEPK  750
#define CAP    8192
#define NBINS  256
#define BIN_OFF 16024   // (__float_as_uint(0.299f)>>16) == 16025 -> bin 1
#define TARGET 2300     // pivot margin over TOPK (absorbs 1e-6 approx error)

// Level layout (IMG 1920x1080, steps {8,16,32,64}):
// L0: off 0      cnt 97200  fw 240 step 8  nms 3  sizes {10,16,24}
// L1: off 97200  cnt 16320  fw 120 step 16 nms 2  sizes {32,48}
// L2: off 113520 cnt 4080   fw 60  step 32 nms 2  sizes {64,96}
// L3: off 117600 cnt 1530   fw 30  step 64 nms 3  sizes {128,192,256}

__device__ unsigned char      g_bins[NBATCH * NPRI];   // 0 = not candidate
__device__ unsigned int       g_hist[NBATCH * NBINS];  // zeroed by k_serial
__device__ int                g_selcnt[NBATCH];        // zeroed by k_serial
__device__ unsigned long long g_sel[NBATCH * CAP];
__device__ unsigned long long g_top[NBATCH * 2048];
__device__ float              g_boxes[NBATCH * 4 * 2048];
// suppression bitmask: lower-tri words never written, stay 0 (static init)
__device__ unsigned long long g_mask[(size_t)NBATCH * 2048 * 32];
__device__ double             g_exp_tab[64];   // 2^(j/64)

// ---------------------------------------------------------------------------
// Fast fp64 exp via 64-entry table + degree-5 poly; error ~2^-52.
// Result rounded once to float == correctly-rounded expf w.p. 1-2^-27/call.
// ---------------------------------------------------------------------------
__device__ __forceinline__ double exp_pd(double x) {
    double t = x * 92.332482616893658071;                // 64*log2(e)
    int ni = __double2int_rn(t);
    double nd = (double)ni;
    double r = fma(nd, -1.0830424693267559625e-02, x);   // ln2_hi/64
    r = fma(nd, -2.9815858269852932813e-12, r);          // ln2_lo/64
    double q = 8.3333333333333333333e-03;                // 1/120
    q = fma(q, r, 4.1666666666666666667e-02);            // 1/24
    q = fma(q, r, 1.6666666666666666667e-01);            // 1/6
    q = fma(q, r, 0.5);
    q = fma(q, r, 1.0);
    q = q * r;                                           // expm1(r)
    double T = g_exp_tab[ni & 63];
    T = __longlong_as_double(__double_as_longlong(T) +
                             ((long long)(ni >> 6) << 52));
    return fma(T, q, T);
}

__device__ __forceinline__ float softmax1_exact(float c0, float c1) {
    if (c1 >= c0) {
        float e0 = (float)exp_pd((double)__fsub_rn(c0, c1));
        return __fdiv_rn(1.0f, __fadd_rn(e0, 1.0f));
    } else {
        float e1 = (float)exp_pd((double)__fsub_rn(c1, c0));
        return __fdiv_rn(e1, __fadd_rn(1.0f, e1));
    }
}

__device__ __forceinline__ unsigned char bin_of(float c0, float c1, float u) {
    float s = 0.0f;
    if (u > 0.0f) {
        float pf = 1.0f / (1.0f + __expf(c0 - c1));  // rel err ~1e-6
        float sf = sqrtf(pf * u);
        if (sf >= 0.299f) s = sf;                     // guard band
    }
    if (s <= 0.0f) return 0;
    int bin = (int)(__float_as_uint(s) >> 16) - BIN_OFF;
    return (unsigned char)min(max(bin, 1), 255);
}

// ---------------------------------------------------------------------------
// K1: approx scores -> u8 bins (2 priors/thread, vector loads) + histogram;
//     block (0,0) also fills the exp table.
// ---------------------------------------------------------------------------
__global__ void k_scores(const float* __restrict__ conf,
                         const float* __restrict__ iou) {
    __shared__ unsigned sh[NBINS];
    int b = blockIdx.y;
    int t = threadIdx.x;
    if (blockIdx.x == 0 && blockIdx.y == 0 && t < 64)
        g_exp_tab[t] = exp2((double)t * 0.015625);
    sh[t] = 0;
    __syncthreads();
    int h = blockIdx.x * 256 + t;           // half-index (2 priors each)
    if (h < NPRI / 2) {
        const float4* cb = (const float4*)(conf + (size_t)b * NPRI * 2);
        const float2* ib = (const float2*)(iou + (size_t)b * NPRI);
        float4 c = cb[h];
        float2 uv = ib[h];
        float u0 = fminf(fmaxf(uv.x, 0.0f), 1.0f);
        float u1 = fminf(fmaxf(uv.y, 0.0f), 1.0f);
        unsigned char b0 = bin_of(c.x, c.y, u0);
        unsigned char b1 = bin_of(c.z, c.w, u1);
        ((unsigned short*)g_bins)[(size_t)b * (NPRI / 2) + h] =
            (unsigned short)(b0 | ((unsigned)b1 << 8));
        if (b0) atomicAdd(&sh[b0], 1u);
        if (b1) atomicAdd(&sh[b1], 1u);
    }
    __syncthreads();
    unsigned v = sh[t];
    if (v) atomicAdd(&g_hist[b * NBINS + t], v);
}

// ---------------------------------------------------------------------------
// K2: fused pivot (recomputed per block, deterministic) + compaction
//     (block-local) + dense exact rescore -> final sort keys in g_sel.
// ---------------------------------------------------------------------------
__global__ void k_compact(const float* __restrict__ conf,
                          const float* __restrict__ iou) {
    __shared__ unsigned s_wt[8];
    __shared__ int s_pivot;
    __shared__ int s_cnt;
    __shared__ int s_base;
    __shared__ int s_idx[512];
    int b = blockIdx.y;
    int t = threadIdx.x;
    int lane = t & 31, w = t >> 5;

    unsigned hh = g_hist[b * NBINS + t];
    unsigned v = hh;
#pragma unroll
    for (int o = 1; o < 32; o <<= 1) {
        unsigned u = __shfl_up_sync(0xffffffffu, v, o);
        if (lane >= o) v += u;
    }
    if (lane == 31) s_wt[w] = v;
    if (t == 0) s_cnt = 0;
    __syncthreads();
    if (t < 8) {
        unsigned x = s_wt[t];
#pragma unroll
        for (int o = 1; o < 8; o <<= 1) {
            unsigned u = __shfl_up_sync(0xffu, x, o);
            if (t >= o) x += u;
        }
        s_wt[t] = x;
    }
    __syncthreads();
    unsigned pre = v + (w ? s_wt[w - 1] : 0);   // inclusive prefix
    unsigned total = s_wt[7];
    unsigned Ct = total - pre + hh;             // suffix sum from bin t
    bool qual = (Ct >= TARGET) && (t == 255 || (Ct - hh) < TARGET);
    if (qual) s_pivot = t;
    if (t == 0 && total < TARGET) s_pivot = 0;
    __syncthreads();
    int pivot = s_pivot;

    int h = blockIdx.x * 256 + t;
    if (h < NPRI / 2) {
        unsigned short bb =
            ((const unsigned short*)g_bins)[(size_t)b * (NPRI / 2) + h];
        int b0 = bb & 0xFF, b1 = bb >> 8;
        if (b0 && b0 >= pivot) s_idx[atomicAdd(&s_cnt, 1)] = 2 * h;
        if (b1 && b1 >= pivot) s_idx[atomicAdd(&s_cnt, 1)] = 2 * h + 1;
    }
    __syncthreads();
    int cnt = s_cnt;
    if (t == 0 && cnt > 0) s_base = atomicAdd(&g_selcnt[b], cnt);
    __syncthreads();

    for (int k = t; k < cnt; k += 256) {
        int idx = s_idx[k];
        size_t e = (size_t)b * NPRI + (size_t)idx;
        float2 c = ((const float2*)conf)[e];
        float u = iou[e];
        u = fminf(fmaxf(u, 0.0f), 1.0f);
        float p = softmax1_exact(c.x, c.y);
        float s = __fsqrt_rn(__fmul_rn(p, u));
        unsigned long long key = 0ULL;
        if (s >= 0.3f)
            key = ((unsigned long long)__float_as_uint(s) << 32) |
                  (unsigned)(0x7FFFFFFF - idx);
        int pos = s_base + k;
        if (pos < CAP) g_sel[b * CAP + pos] = key;
    }
}

// ---------------------------------------------------------------------------
// K3: per-(batch,chunk) bitonic sort desc of 2048 keys (1 pair/thread/pass).
//     Conditional zero-pad load (i>=m -> 0) removes the g_sel memset.
// ---------------------------------------------------------------------------
__global__ void k_sortchunk() {
    __shared__ unsigned long long keys[2048];
    int b = blockIdx.y, c = blockIdx.x;
    int tid = threadIdx.x;
    int m = g_selcnt[b];
    if (m > CAP) m = CAP;
    int base = c * 2048;
    for (int i = tid; i < 2048; i += 1024)
        keys[i] = (base + i < m) ? g_sel[b * CAP + base + i] : 0ULL;
    for (int k = 2; k <= 2048; k <<= 1) {
        for (int j = k >> 1; j > 0; j >>= 1) {
            __syncthreads();
            int i = ((tid & ~(j - 1)) << 1) | (tid & (j - 1));
            int l = i + j;
            unsigned long long a = keys[i], bb = keys[l];
            bool up = ((i & k) == 0);
            if (up ? (a < bb) : (a > bb)) { keys[i] = bb; keys[l] = a; }
        }
    }
    __syncthreads();
    for (int i = tid; i < 2048; i += 1024)
        g_sel[b * CAP + base + i] = keys[i];
}

// ---------------------------------------------------------------------------
// Bitonic top-2048 merge of two descending 2048 arrays:
// M[i] = max(A[i], B[2047-i]) holds the top 2048 and is bitonic; 11-pass
// bitonic merge (desc) sorts it.
// ---------------------------------------------------------------------------
__device__ __forceinline__ void merge_top(const unsigned long long* A,
                                          const unsigned long long* B,
                                          unsigned long long* outp, int tid) {
    __shared__ unsigned long long keys[2048];
    for (int i = tid; i < 2048; i += 1024) {
        unsigned long long a = A[i], bb = B[2047 - i];
        keys[i] = (a < bb) ? bb : a;
    }
    for (int j = 1024; j > 0; j >>= 1) {
        __syncthreads();
        int i = ((tid & ~(j - 1)) << 1) | (tid & (j - 1));
        int l = i + j;
        unsigned long long a = keys[i], bb = keys[l];
        if (a < bb) { keys[i] = bb; keys[l] = a; }
    }
    __syncthreads();
    for (int i = tid; i < 2048; i += 1024) outp[i] = keys[i];
}

__global__ void k_merge1() {
    int b = blockIdx.y;
    int pa = blockIdx.x * 2;   // chunk pairs (0,1) and (2,3)
    unsigned long long* A = g_sel + (size_t)b * CAP + pa * 2048;
    merge_top(A, A + 2048, A, threadIdx.x);
}

__global__ void k_merge2() {
    int b = blockIdx.x;
    unsigned long long* A = g_sel + (size_t)b * CAP;
    merge_top(A, A + 2 * 2048, g_top + (size_t)b * 2048, threadIdx.x);
}

__constant__ float PW[10] = {
    (float)(10.0/1920.0),(float)(16.0/1920.0),(float)(24.0/1920.0),
    (float)(32.0/1920.0),(float)(48.0/1920.0),
    (float)(64.0/1920.0),(float)(96.0/1920.0),
    (float)(128.0/1920.0),(float)(192.0/1920.0),(float)(256.0/1920.0)};
__constant__ float PH[10] = {
    (float)(10.0/1080.0),(float)(16.0/1080.0),(float)(24.0/1080.0),
    (float)(32.0/1080.0),(float)(48.0/1080.0),
    (float)(64.0/1080.0),(float)(96.0/1080.0),
    (float)(128.0/1080.0),(float)(192.0/1080.0),(float)(256.0/1080.0)};

__device__ __forceinline__ void prior_of(int idx, float& pcx, float& pcy,
                                         float& pw, float& ph) {
    int off, fw, step, nm, msoff;
    if (idx < 97200)       { off = 0;      fw = 240; step = 8;  nm = 3; msoff = 0; }
    else if (idx < 113520) { off = 97200;  fw = 120; step = 16; nm = 2; msoff = 3; }
    else if (idx < 117600) { off = 113520; fw = 60;  step = 32; nm = 2; msoff = 5; }
    else                   { off = 117600; fw = 30;  step = 64; nm = 3; msoff = 7; }
    int r = idx - off;
    int cell = r / nm;
    int mi = r - cell * nm;
    int row = cell / fw;
    int col = cell - row * fw;
    double tx = ((double)col + 0.5) * (double)step;
    double ty = ((double)row + 0.5) * (double)step;
    pcx = (float)(tx * (1.0 / 1920.0));
    pcy = (float)(ty * (1.0 / 1080.0));
    pw = PW[msoff + mi];
    ph = PH[msoff + mi];
}

// ---------------------------------------------------------------------------
// K5: full-chip decode of top-2000 rows: out cols 0..13 + box SoA for NMS
// ---------------------------------------------------------------------------
__global__ void k_decode(const float* __restrict__ loc,
                         float* __restrict__ out) {
    int row = blockIdx.x * blockDim.x + threadIdx.x;
    if (row >= NBATCH * TOPK) return;
    int b = row / TOPK;
    int r = row - b * TOPK;
    unsigned long long kk = g_top[b * 2048 + r];
    int idx = 0x7FFFFFFF - (int)(unsigned)(kk & 0xFFFFFFFFu);
    if (idx < 0 || idx >= NPRI) idx = 0;

    float pcx, pcy, pw, ph;
    prior_of(idx, pcx, pcy, pw, ph);
    const float* lp = loc + ((size_t)b * NPRI + (size_t)idx) * 14;
    float l[14];
#pragma unroll
    for (int c = 0; c < 14; c++) l[c] = lp[c];

    float cx = __fadd_rn(pcx, __fmul_rn(__fmul_rn(l[0], 0.1f), pw));
    float cy = __fadd_rn(pcy, __fmul_rn(__fmul_rn(l[1], 0.1f), ph));
    float w  = __fmul_rn(pw, (float)exp_pd((double)__fmul_rn(l[2], 0.1f)));
    float h  = __fmul_rn(ph, (float)exp_pd((double)__fmul_rn(l[3], 0.2f)));
    float x1 = __fsub_rn(cx, __fmul_rn(w, 0.5f));
    float y1 = __fsub_rn(cy, __fmul_rn(h, 0.5f));
    float x2 = __fadd_rn(x1, w);
    float y2 = __fadd_rn(y1, h);

    float* op = out + (size_t)row * 15;
    float X1 = __fmul_rn(x1, 1920.0f), Y1 = __fmul_rn(y1, 1080.0f);
    float X2 = __fmul_rn(x2, 1920.0f), Y2 = __fmul_rn(y2, 1080.0f);
    op[0] = X1; op[1] = Y1; op[2] = X2; op[3] = Y2;
#pragma unroll
    for (int k = 0; k < 5; k++) {
        float lx = __fadd_rn(pcx, __fmul_rn(__fmul_rn(l[4 + 2 * k], 0.1f), pw));
        float ly = __fadd_rn(pcy, __fmul_rn(__fmul_rn(l[5 + 2 * k], 0.1f), ph));
        op[4 + 2 * k] = __fmul_rn(lx, 1920.0f);
        op[5 + 2 * k] = __fmul_rn(ly, 1080.0f);
    }
    g_boxes[b * 8192 + 0 * 2048 + r] = X1;
    g_boxes[b * 8192 + 1 * 2048 + r] = Y1;
    g_boxes[b * 8192 + 2 * 2048 + r] = X2;
    g_boxes[b * 8192 + 3 * 2048 + r] = Y2;
}

// ---------------------------------------------------------------------------
// K6a: suppression bitmask build (full chip). 64x64 rank tiles, upper tri.
// ---------------------------------------------------------------------------
__global__ void k_mask() {
    int jt = blockIdx.x, it = blockIdx.y, b = blockIdx.z;
    if (jt < it) return;
    __shared__ float cx1[64], cy1[64], cx2[64], cy2[64], ca[64];
    int t = threadIdx.x;
    int j0 = jt * 64;
    {
        float x1 = g_boxes[b * 8192 + 0 * 2048 + j0 + t];
        float y1 = g_boxes[b * 8192 + 1 * 2048 + j0 + t];
        float x2 = g_boxes[b * 8192 + 2 * 2048 + j0 + t];
        float y2 = g_boxes[b * 8192 + 3 * 2048 + j0 + t];
        cx1[t] = x1; cy1[t] = y1; cx2[t] = x2; cy2[t] = y2;
        ca[t] = __fmul_rn(fmaxf(__fsub_rn(x2, x1), 0.0f),
                          fmaxf(__fsub_rn(y2, y1), 0.0f));
    }
    __syncthreads();
    int i = it * 64 + t;
    float xi1 = g_boxes[b * 8192 + 0 * 2048 + i];
    float yi1 = g_boxes[b * 8192 + 1 * 2048 + i];
    float xi2 = g_boxes[b * 8192 + 2 * 2048 + i];
    float yi2 = g_boxes[b * 8192 + 3 * 2048 + i];
    float ai = __fmul_rn(fmaxf(__fsub_rn(xi2, xi1), 0.0f),
                         fmaxf(__fsub_rn(yi2, yi1), 0.0f));
    unsigned long long word = 0ULL;
    int jj0 = (jt == it) ? (t + 1) : 0;
    for (int jj = jj0; jj < 64; jj++) {
        float lx = fmaxf(xi1, cx1[jj]), ly = fmaxf(yi1, cy1[jj]);
        float rx = fminf(xi2, cx2[jj]), ry = fminf(yi2, cy2[jj]);
        float iw = fmaxf(__fsub_rn(rx, lx), 0.0f);
        float ih = fmaxf(__fsub_rn(ry, ly), 0.0f);
        float inter = __fmul_rn(iw, ih);
        if (inter > 0.0f) {  // division only when boxes overlap
            float denom = __fadd_rn(
                __fsub_rn(__fadd_rn(ai, ca[jj]), inter), 1e-9f);
            if (__fdiv_rn(inter, denom) > 0.3f) word |= (1ULL << jj);
        }
    }
    g_mask[((size_t)b * 2048 + i) * 32 + jt] = word;
}

// ---------------------------------------------------------------------------
// K6b: per-batch serial bitmask scan. All 32 warps double-buffer 128-row
//      (32KB) chunks of g_mask into smem; warp 0 runs the bit chain with the
//      owner word read via LDS broadcast. Then KEEP_TOP_K cumsum -> col 14.
//      Also zeroes g_hist[b] / g_selcnt[b] for the next run.
// ---------------------------------------------------------------------------
__global__ void k_serial(float* __restrict__ out) {
    extern __shared__ unsigned long long sbuf[];   // 2 * 128 * 32 ull = 64KB
    __shared__ unsigned long long initm[32];
    __shared__ unsigned long long keepm[32];
    __shared__ float ss[2048];
    __shared__ int wtot[33];
    int b = blockIdx.x;
    int tid = threadIdx.x;
    int warp = tid >> 5, lane = tid & 31;

    for (int r = tid; r < 2048; r += 1024) {
        unsigned long long kk = g_top[b * 2048 + r];
        float sc = __uint_as_float((unsigned)(kk >> 32));
        ss[r] = (r < TOPK) ? sc : 0.0f;
    }
    // housekeeping for next run (hist/selcnt consumed earlier this run)
    if (tid < NBINS) g_hist[b * NBINS + tid] = 0;
    if (tid == 0) g_selcnt[b] = 0;
    __syncthreads();

    unsigned lo = __ballot_sync(0xffffffffu, ss[warp * 64 + lane] > 0.0f);
    unsigned hi = __ballot_sync(0xffffffffu, ss[warp * 64 + 32 + lane] > 0.0f);
    if (lane == 0) initm[warp] = ((unsigned long long)hi << 32) | lo;

    const unsigned long long* mrow = g_mask + (size_t)b * 2048 * 32;
    // preload chunk 0 (rows 0..127 = words 0..4095)
    for (int k = tid; k < 4096; k += 1024) sbuf[k] = mrow[k];
    __syncthreads();

    unsigned long long removed = ~initm[lane];  // bit set = inactive
    for (int c = 0; c < 16; c++) {
        int pb = (c & 1) * 4096;
        if (warp != 0 && c + 1 < 16) {
            int nb = ((c + 1) & 1) * 4096;
            const unsigned long long* src = mrow + (size_t)(c + 1) * 4096;
            for (int k = tid - 32; k < 4096; k += 992)
                sbuf[nb + k] = src[k];
        }
        if (warp == 0) {
            unsigned long long rm_w = 0;
#pragma unroll 8
            for (int il = 0; il < 128; il++) {
                int i = c * 128 + il;
                int w = i >> 6, bit = i & 63;
                if (bit == 0) rm_w = __shfl_sync(0xffffffffu, removed, w);
                unsigned long long own = sbuf[pb + il * 32 + lane];
                unsigned long long bc  = sbuf[pb + il * 32 + w];
                unsigned long long msk =
                    ((rm_w >> bit) & 1ULL) ? 0ULL : ~0ULL;  // active?
                removed |= own & msk;
                rm_w |= bc & msk;
            }
        }
        __syncthreads();
    }
    if (warp == 0) keepm[lane] = ~removed;
    __syncthreads();

    int e0 = 2 * tid, e1 = 2 * tid + 1;
    int a0 = (int)((keepm[e0 >> 6] >> (e0 & 63)) & 1ULL);
    int a1 = (int)((keepm[e1 >> 6] >> (e1 & 63)) & 1ULL);
    int ps = a0 + a1;
    int v = ps;
#pragma unroll
    for (int o = 1; o < 32; o <<= 1) {
        int u = __shfl_up_sync(0xffffffffu, v, o);
        if (lane >= o) v += u;
    }
    if (lane == 31) wtot[warp] = v;
    __syncthreads();
    if (warp == 0) {
        int w = wtot[lane];
#pragma unroll
        for (int o = 1; o < 32; o <<= 1) {
            int u = __shfl_up_sync(0xffffffffu, w, o);
            if (lane >= o) w += u;
        }
        wtot[lane] = w;
    }
    __syncthreads();
    int base = (warp ? wtot[warp - 1] : 0) + v - ps;
    int c0 = base + a0;
    int c1 = c0 + a1;
    if (e0 < TOPK)
        out[((size_t)b * TOPK + e0) * 15 + 14] =
            ss[e0] * ((a0 && c0 <= KEEPK) ? 1.0f : 0.0f);
    if (e1 < TOPK)
        out[((size_t)b * TOPK + e1) * 15 + 14] =
            ss[e1] * ((a1 && c1 <= KEEPK) ? 1.0f : 0.0f);
}

// ---------------------------------------------------------------------------
extern "C" void kernel_launch(void* const* d_in, const int* in_sizes, int n_in,
                              void* d_out, int out_size) {
    const float* loc = nullptr;
    const float* conf = nullptr;
    const float* iou = nullptr;
    for (int i = 0; i < n_in; i++) {
        if (in_sizes[i] == NBATCH * NPRI * 14) loc = (const float*)d_in[i];
        else if (in_sizes[i] == NBATCH * NPRI * 2) conf = (const float*)d_in[i];
        else if (in_sizes[i] == NBATCH * NPRI) iou = (const float*)d_in[i];
    }
    float* out = (float*)d_out;

    dim3 ghalf((NPRI / 2 + 255) / 256, NBATCH);
    k_scores<<<ghalf, 256>>>(conf, iou);
    k_compact<<<ghalf, 256>>>(conf, iou);

    k_sortchunk<<<dim3(4, NBATCH), 1024>>>();
    k_merge1<<<dim3(2, NBATCH), 1024>>>();
    k_merge2<<<NBATCH, 1024>>>();

    k_decode<<<(NBATCH * TOPK + 127) / 128, 128>>>(loc, out);

    k_mask<<<dim3(32, 32, NBATCH), 64>>>();

    cudaFuncSetAttribute(k_serial, cudaFuncAttributeMaxDynamicSharedMemorySize,
                         65536);
    k_serial<<<NBATCH, 1024, 65536>>>(out);
}

// round 13
// speedup vs baseline: 14.8279x; 1.2427x over previous
#include <cuda_runtime.h>
#include <cuda_bf16.h>
#include <math.h>
#include <stdint.h>

#define NBATCH 16
#define NPRI   119130
#define TOPK   2000
#define KEEPK  750
#define CAP    8192
#define NBINS  256
#define BIN_OFF 16024   // (__float_as_uint(0.299f)>>16) == 16025 -> bin 1
#define TARGET 2300     // pivot margin over TOPK (absorbs 1e-6 approx error)

// Level layout (IMG 1920x1080, steps {8,16,32,64}):
// L0: off 0      cnt 97200  fw 240 step 8  nms 3  sizes {10,16,24}
// L1: off 97200  cnt 16320  fw 120 step 16 nms 2  sizes {32,48}
// L2: off 113520 cnt 4080   fw 60  step 32 nms 2  sizes {64,96}
// L3: off 117600 cnt 1530   fw 30  step 64 nms 3  sizes {128,192,256}

__device__ unsigned char      g_bins[NBATCH * NPRI];   // 0 = not candidate
__device__ unsigned int       g_hist[NBATCH * NBINS];  // zeroed by k_serial
__device__ int                g_selcnt[NBATCH];        // zeroed by k_serial
__device__ unsigned long long g_sel[NBATCH * CAP];
__device__ unsigned long long g_top[NBATCH * 2048];
__device__ float              g_boxes[NBATCH * 4 * 2048];
// suppression bitmask: lower-tri words never written, stay 0 (static init)
__device__ unsigned long long g_mask[(size_t)NBATCH * 2048 * 32];
__device__ double             g_exp_tab[64];   // 2^(j/64)

// ---------------------------------------------------------------------------
// Fast fp64 exp via 64-entry table + degree-5 poly; error ~2^-52.
// Result rounded once to float == correctly-rounded expf w.p. 1-2^-27/call.
// ---------------------------------------------------------------------------
__device__ __forceinline__ double exp_pd(double x) {
    double t = x * 92.332482616893658071;                // 64*log2(e)
    int ni = __double2int_rn(t);
    double nd = (double)ni;
    double r = fma(nd, -1.0830424693267559625e-02, x);   // ln2_hi/64
    r = fma(nd, -2.9815858269852932813e-12, r);          // ln2_lo/64
    double q = 8.3333333333333333333e-03;                // 1/120
    q = fma(q, r, 4.1666666666666666667e-02);            // 1/24
    q = fma(q, r, 1.6666666666666666667e-01);            // 1/6
    q = fma(q, r, 0.5);
    q = fma(q, r, 1.0);
    q = q * r;                                           // expm1(r)
    double T = g_exp_tab[ni & 63];
    T = __longlong_as_double(__double_as_longlong(T) +
                             ((long long)(ni >> 6) << 52));
    return fma(T, q, T);
}

__device__ __forceinline__ float softmax1_exact(float c0, float c1) {
    if (c1 >= c0) {
        float e0 = (float)exp_pd((double)__fsub_rn(c0, c1));
        return __fdiv_rn(1.0f, __fadd_rn(e0, 1.0f));
    } else {
        float e1 = (float)exp_pd((double)__fsub_rn(c1, c0));
        return __fdiv_rn(e1, __fadd_rn(1.0f, e1));
    }
}

__device__ __forceinline__ unsigned char bin_of(float c0, float c1, float u) {
    float s = 0.0f;
    if (u > 0.0f) {
        float pf = 1.0f / (1.0f + __expf(c0 - c1));  // rel err ~1e-6
        float sf = sqrtf(pf * u);
        if (sf >= 0.299f) s = sf;                     // guard band
    }
    if (s <= 0.0f) return 0;
    int bin = (int)(__float_as_uint(s) >> 16) - BIN_OFF;
    return (unsigned char)min(max(bin, 1), 255);
}

// ---------------------------------------------------------------------------
// K1: approx scores -> u8 bins (2 priors/thread, vector loads) + histogram;
//     block (0,0) also fills the exp table.
// ---------------------------------------------------------------------------
__global__ void k_scores(const float* __restrict__ conf,
                         const float* __restrict__ iou) {
    __shared__ unsigned sh[NBINS];
    int b = blockIdx.y;
    int t = threadIdx.x;
    if (blockIdx.x == 0 && blockIdx.y == 0 && t < 64)
        g_exp_tab[t] = exp2((double)t * 0.015625);
    sh[t] = 0;
    __syncthreads();
    int h = blockIdx.x * 256 + t;           // half-index (2 priors each)
    if (h < NPRI / 2) {
        const float4* cb = (const float4*)(conf + (size_t)b * NPRI * 2);
        const float2* ib = (const float2*)(iou + (size_t)b * NPRI);
        float4 c = cb[h];
        float2 uv = ib[h];
        float u0 = fminf(fmaxf(uv.x, 0.0f), 1.0f);
        float u1 = fminf(fmaxf(uv.y, 0.0f), 1.0f);
        unsigned char b0 = bin_of(c.x, c.y, u0);
        unsigned char b1 = bin_of(c.z, c.w, u1);
        ((unsigned short*)g_bins)[(size_t)b * (NPRI / 2) + h] =
            (unsigned short)(b0 | ((unsigned)b1 << 8));
        if (b0) atomicAdd(&sh[b0], 1u);
        if (b1) atomicAdd(&sh[b1], 1u);
    }
    __syncthreads();
    unsigned v = sh[t];
    if (v) atomicAdd(&g_hist[b * NBINS + t], v);
}

// ---------------------------------------------------------------------------
// K2: fused pivot (recomputed per block, deterministic) + compaction
//     (block-local) + dense exact rescore -> final sort keys in g_sel.
// ---------------------------------------------------------------------------
__global__ void k_compact(const float* __restrict__ conf,
                          const float* __restrict__ iou) {
    __shared__ unsigned s_wt[8];
    __shared__ int s_pivot;
    __shared__ int s_cnt;
    __shared__ int s_base;
    __shared__ int s_idx[512];
    int b = blockIdx.y;
    int t = threadIdx.x;
    int lane = t & 31, w = t >> 5;

    unsigned hh = g_hist[b * NBINS + t];
    unsigned v = hh;
#pragma unroll
    for (int o = 1; o < 32; o <<= 1) {
        unsigned u = __shfl_up_sync(0xffffffffu, v, o);
        if (lane >= o) v += u;
    }
    if (lane == 31) s_wt[w] = v;
    if (t == 0) s_cnt = 0;
    __syncthreads();
    if (t < 8) {
        unsigned x = s_wt[t];
#pragma unroll
        for (int o = 1; o < 8; o <<= 1) {
            unsigned u = __shfl_up_sync(0xffu, x, o);
            if (t >= o) x += u;
        }
        s_wt[t] = x;
    }
    __syncthreads();
    unsigned pre = v + (w ? s_wt[w - 1] : 0);   // inclusive prefix
    unsigned total = s_wt[7];
    unsigned Ct = total - pre + hh;             // suffix sum from bin t
    bool qual = (Ct >= TARGET) && (t == 255 || (Ct - hh) < TARGET);
    if (qual) s_pivot = t;
    if (t == 0 && total < TARGET) s_pivot = 0;
    __syncthreads();
    int pivot = s_pivot;

    int h = blockIdx.x * 256 + t;
    if (h < NPRI / 2) {
        unsigned short bb =
            ((const unsigned short*)g_bins)[(size_t)b * (NPRI / 2) + h];
        int b0 = bb & 0xFF, b1 = bb >> 8;
        if (b0 && b0 >= pivot) s_idx[atomicAdd(&s_cnt, 1)] = 2 * h;
        if (b1 && b1 >= pivot) s_idx[atomicAdd(&s_cnt, 1)] = 2 * h + 1;
    }
    __syncthreads();
    int cnt = s_cnt;
    if (t == 0 && cnt > 0) s_base = atomicAdd(&g_selcnt[b], cnt);
    __syncthreads();

    for (int k = t; k < cnt; k += 256) {
        int idx = s_idx[k];
        size_t e = (size_t)b * NPRI + (size_t)idx;
        float2 c = ((const float2*)conf)[e];
        float u = iou[e];
        u = fminf(fmaxf(u, 0.0f), 1.0f);
        float p = softmax1_exact(c.x, c.y);
        float s = __fsqrt_rn(__fmul_rn(p, u));
        unsigned long long key = 0ULL;
        if (s >= 0.3f)
            key = ((unsigned long long)__float_as_uint(s) << 32) |
                  (unsigned)(0x7FFFFFFF - idx);
        int pos = s_base + k;
        if (pos < CAP) g_sel[b * CAP + pos] = key;
    }
}

// ---------------------------------------------------------------------------
// K3: per-(batch,chunk) bitonic sort desc of 2048 keys (1 pair/thread/pass).
// ---------------------------------------------------------------------------
__global__ void k_sortchunk() {
    __shared__ unsigned long long keys[2048];
    int b = blockIdx.y, c = blockIdx.x;
    int tid = threadIdx.x;
    int m = g_selcnt[b];
    if (m > CAP) m = CAP;
    int base = c * 2048;
    for (int i = tid; i < 2048; i += 1024)
        keys[i] = (base + i < m) ? g_sel[b * CAP + base + i] : 0ULL;
    for (int k = 2; k <= 2048; k <<= 1) {
        for (int j = k >> 1; j > 0; j >>= 1) {
            __syncthreads();
            int i = ((tid & ~(j - 1)) << 1) | (tid & (j - 1));
            int l = i + j;
            unsigned long long a = keys[i], bb = keys[l];
            bool up = ((i & k) == 0);
            if (up ? (a < bb) : (a > bb)) { keys[i] = bb; keys[l] = a; }
        }
    }
    __syncthreads();
    for (int i = tid; i < 2048; i += 1024)
        g_sel[b * CAP + base + i] = keys[i];
}

// ---------------------------------------------------------------------------
// K4: single-kernel two-stage top-2048 merge of the 4 sorted chunks.
// Stage1: (c0,c1)->K[0..2048), (c2,c3)->K[4096..6144) in parallel halves.
// Stage2: those two -> g_top. M[i]=max(A[i],B[2047-i]) is bitonic and holds
// the top-2048; 11-pass desc bitonic merge sorts it.
// ---------------------------------------------------------------------------
__global__ void k_merge() {
    extern __shared__ unsigned long long K[];   // 8192 ull = 64KB
    int b = blockIdx.x;
    int tid = threadIdx.x;
    for (int i = tid; i < 8192; i += 1024)
        K[i] = g_sel[(size_t)b * CAP + i];
    __syncthreads();
    // stage 1 max-combine (both halves)
    for (int p = tid; p < 2048; p += 1024) {
        int hf = p >> 10;              // 0 or 1
        int q = p & 1023;
        int base = hf * 4096;
        // two indices per thread (q and q+1024) to cover 2048 per half
        for (int s = 0; s < 2; s++) {
            int i = q + s * 1024;
            unsigned long long a = K[base + i];
            unsigned long long bb = K[base + 2048 + 2047 - i];
            K[base + i] = (a < bb) ? bb : a;
        }
        break;  // p-loop runs once per thread (tid<1024); structure kept simple
    }
    for (int j = 1024; j > 0; j >>= 1) {
        __syncthreads();
        // 2048 compare-exchanges per pass: 1024 per half
        int q = tid;
        int i = ((q & ~(j - 1)) << 1) | (q & (j - 1));
#pragma unroll
        for (int hf = 0; hf < 2; hf++) {
            int base = hf * 4096;
            unsigned long long a = K[base + i], bb = K[base + i + j];
            if (a < bb) { K[base + i] = bb; K[base + i + j] = a; }
        }
    }
    __syncthreads();
    // stage 2 max-combine
    for (int i = tid; i < 2048; i += 1024) {
        unsigned long long a = K[i], bb = K[4096 + 2047 - i];
        K[i] = (a < bb) ? bb : a;
    }
    for (int j = 1024; j > 0; j >>= 1) {
        __syncthreads();
        int i = ((tid & ~(j - 1)) << 1) | (tid & (j - 1));
        unsigned long long a = K[i], bb = K[i + j];
        if (a < bb) { K[i] = bb; K[i + j] = a; }
    }
    __syncthreads();
    for (int i = tid; i < 2048; i += 1024)
        g_top[(size_t)b * 2048 + i] = K[i];
}

__constant__ float PW[10] = {
    (float)(10.0/1920.0),(float)(16.0/1920.0),(float)(24.0/1920.0),
    (float)(32.0/1920.0),(float)(48.0/1920.0),
    (float)(64.0/1920.0),(float)(96.0/1920.0),
    (float)(128.0/1920.0),(float)(192.0/1920.0),(float)(256.0/1920.0)};
__constant__ float PH[10] = {
    (float)(10.0/1080.0),(float)(16.0/1080.0),(float)(24.0/1080.0),
    (float)(32.0/1080.0),(float)(48.0/1080.0),
    (float)(64.0/1080.0),(float)(96.0/1080.0),
    (float)(128.0/1080.0),(float)(192.0/1080.0),(float)(256.0/1080.0)};

__device__ __forceinline__ void prior_of(int idx, float& pcx, float& pcy,
                                         float& pw, float& ph) {
    int off, fw, step, nm, msoff;
    if (idx < 97200)       { off = 0;      fw = 240; step = 8;  nm = 3; msoff = 0; }
    else if (idx < 113520) { off = 97200;  fw = 120; step = 16; nm = 2; msoff = 3; }
    else if (idx < 117600) { off = 113520; fw = 60;  step = 32; nm = 2; msoff = 5; }
    else                   { off = 117600; fw = 30;  step = 64; nm = 3; msoff = 7; }
    int r = idx - off;
    int cell = r / nm;
    int mi = r - cell * nm;
    int row = cell / fw;
    int col = cell - row * fw;
    double tx = ((double)col + 0.5) * (double)step;
    double ty = ((double)row + 0.5) * (double)step;
    pcx = (float)(tx * (1.0 / 1920.0));
    pcy = (float)(ty * (1.0 / 1080.0));
    pw = PW[msoff + mi];
    ph = PH[msoff + mi];
}

// ---------------------------------------------------------------------------
// K5: full-chip decode of top-2000 rows: out cols 0..13 + box SoA for NMS
// ---------------------------------------------------------------------------
__global__ void k_decode(const float* __restrict__ loc,
                         float* __restrict__ out) {
    int row = blockIdx.x * blockDim.x + threadIdx.x;
    if (row >= NBATCH * TOPK) return;
    int b = row / TOPK;
    int r = row - b * TOPK;
    unsigned long long kk = g_top[b * 2048 + r];
    int idx = 0x7FFFFFFF - (int)(unsigned)(kk & 0xFFFFFFFFu);
    if (idx < 0 || idx >= NPRI) idx = 0;

    float pcx, pcy, pw, ph;
    prior_of(idx, pcx, pcy, pw, ph);
    const float* lp = loc + ((size_t)b * NPRI + (size_t)idx) * 14;
    float l[14];
#pragma unroll
    for (int c = 0; c < 14; c++) l[c] = lp[c];

    float cx = __fadd_rn(pcx, __fmul_rn(__fmul_rn(l[0], 0.1f), pw));
    float cy = __fadd_rn(pcy, __fmul_rn(__fmul_rn(l[1], 0.1f), ph));
    float w  = __fmul_rn(pw, (float)exp_pd((double)__fmul_rn(l[2], 0.1f)));
    float h  = __fmul_rn(ph, (float)exp_pd((double)__fmul_rn(l[3], 0.2f)));
    float x1 = __fsub_rn(cx, __fmul_rn(w, 0.5f));
    float y1 = __fsub_rn(cy, __fmul_rn(h, 0.5f));
    float x2 = __fadd_rn(x1, w);
    float y2 = __fadd_rn(y1, h);

    float* op = out + (size_t)row * 15;
    float X1 = __fmul_rn(x1, 1920.0f), Y1 = __fmul_rn(y1, 1080.0f);
    float X2 = __fmul_rn(x2, 1920.0f), Y2 = __fmul_rn(y2, 1080.0f);
    op[0] = X1; op[1] = Y1; op[2] = X2; op[3] = Y2;
#pragma unroll
    for (int k = 0; k < 5; k++) {
        float lx = __fadd_rn(pcx, __fmul_rn(__fmul_rn(l[4 + 2 * k], 0.1f), pw));
        float ly = __fadd_rn(pcy, __fmul_rn(__fmul_rn(l[5 + 2 * k], 0.1f), ph));
        op[4 + 2 * k] = __fmul_rn(lx, 1920.0f);
        op[5 + 2 * k] = __fmul_rn(ly, 1080.0f);
    }
    g_boxes[b * 8192 + 0 * 2048 + r] = X1;
    g_boxes[b * 8192 + 1 * 2048 + r] = Y1;
    g_boxes[b * 8192 + 2 * 2048 + r] = X2;
    g_boxes[b * 8192 + 3 * 2048 + r] = Y2;
}

// ---------------------------------------------------------------------------
// K6a: suppression bitmask build. Triangular grid: 528 tiles/batch (jt>=it).
// ---------------------------------------------------------------------------
__global__ void k_mask() {
    int p = blockIdx.x, b = blockIdx.y;
    int it = 0, rem = p;
    while (rem >= 32 - it) { rem -= 32 - it; it++; }
    int jt = it + rem;
    __shared__ float cx1[64], cy1[64], cx2[64], cy2[64], ca[64];
    int t = threadIdx.x;
    int j0 = jt * 64;
    {
        float x1 = g_boxes[b * 8192 + 0 * 2048 + j0 + t];
        float y1 = g_boxes[b * 8192 + 1 * 2048 + j0 + t];
        float x2 = g_boxes[b * 8192 + 2 * 2048 + j0 + t];
        float y2 = g_boxes[b * 8192 + 3 * 2048 + j0 + t];
        cx1[t] = x1; cy1[t] = y1; cx2[t] = x2; cy2[t] = y2;
        ca[t] = __fmul_rn(fmaxf(__fsub_rn(x2, x1), 0.0f),
                          fmaxf(__fsub_rn(y2, y1), 0.0f));
    }
    __syncthreads();
    int i = it * 64 + t;
    float xi1 = g_boxes[b * 8192 + 0 * 2048 + i];
    float yi1 = g_boxes[b * 8192 + 1 * 2048 + i];
    float xi2 = g_boxes[b * 8192 + 2 * 2048 + i];
    float yi2 = g_boxes[b * 8192 + 3 * 2048 + i];
    float ai = __fmul_rn(fmaxf(__fsub_rn(xi2, xi1), 0.0f),
                         fmaxf(__fsub_rn(yi2, yi1), 0.0f));
    unsigned long long word = 0ULL;
    int jj0 = (jt == it) ? (t + 1) : 0;
    for (int jj = jj0; jj < 64; jj++) {
        float lx = fmaxf(xi1, cx1[jj]), ly = fmaxf(yi1, cy1[jj]);
        float rx = fminf(xi2, cx2[jj]), ry = fminf(yi2, cy2[jj]);
        float iw = fmaxf(__fsub_rn(rx, lx), 0.0f);
        float ih = fmaxf(__fsub_rn(ry, ly), 0.0f);
        float inter = __fmul_rn(iw, ih);
        if (inter > 0.0f) {  // division only when boxes overlap
            float denom = __fadd_rn(
                __fsub_rn(__fadd_rn(ai, ca[jj]), inter), 1e-9f);
            if (__fdiv_rn(inter, denom) > 0.3f) word |= (1ULL << jj);
        }
    }
    g_mask[((size_t)b * 2048 + i) * 32 + jt] = word;
}

// ---------------------------------------------------------------------------
// K6b: per-batch serial bitmask scan with smem staging + early exit once the
//      750th keep is reached (later keeps cannot affect the output: their
//      scores are zeroed by the cumsum cap either way, and removed-bits are
//      final once a row is processed). Then cumsum -> out col 14.
//      Also zeroes g_hist[b] / g_selcnt[b] for the next run.
// ---------------------------------------------------------------------------
__global__ void k_serial(float* __restrict__ out) {
    extern __shared__ unsigned long long sbuf[];   // 2 * 128 * 32 ull = 64KB
    __shared__ unsigned long long initm[32];
    __shared__ unsigned long long keepm[32];
    __shared__ float ss[2048];
    __shared__ int wtot[33];
    __shared__ int s_kept, s_done;
    int b = blockIdx.x;
    int tid = threadIdx.x;
    int warp = tid >> 5, lane = tid & 31;

    for (int r = tid; r < 2048; r += 1024) {
        unsigned long long kk = g_top[b * 2048 + r];
        float sc = __uint_as_float((unsigned)(kk >> 32));
        ss[r] = (r < TOPK) ? sc : 0.0f;
    }
    if (tid < NBINS) g_hist[b * NBINS + tid] = 0;
    if (tid == 0) { g_selcnt[b] = 0; s_kept = 0; s_done = 0; }
    __syncthreads();

    unsigned lo = __ballot_sync(0xffffffffu, ss[warp * 64 + lane] > 0.0f);
    unsigned hi = __ballot_sync(0xffffffffu, ss[warp * 64 + 32 + lane] > 0.0f);
    if (lane == 0) initm[warp] = ((unsigned long long)hi << 32) | lo;

    const unsigned long long* mrow = g_mask + (size_t)b * 2048 * 32;
    for (int k = tid; k < 4096; k += 1024) sbuf[k] = mrow[k];
    __syncthreads();

    unsigned long long removed = ~initm[lane];  // bit set = inactive
    int done_chunks = 16;
    for (int c = 0; c < 16; c++) {
        int pb = (c & 1) * 4096;
        if (warp != 0 && c + 1 < 16) {
            int nb = ((c + 1) & 1) * 4096;
            const unsigned long long* src = mrow + (size_t)(c + 1) * 4096;
            for (int k = tid - 32; k < 4096; k += 992)
                sbuf[nb + k] = src[k];
        }
        if (warp == 0) {
            unsigned long long rm_w = 0;
#pragma unroll 8
            for (int il = 0; il < 128; il++) {
                int i = c * 128 + il;
                int w = i >> 6, bit = i & 63;
                if (bit == 0) rm_w = __shfl_sync(0xffffffffu, removed, w);
                unsigned long long own = sbuf[pb + il * 32 + lane];
                unsigned long long bc  = sbuf[pb + il * 32 + w];
                // msk = all-ones iff bit of rm_w is CLEAR (row active)
                unsigned long long msk = ~(unsigned long long)(
                    ((long long)(rm_w << (63 - bit))) >> 63);
                removed |= own & msk;
                rm_w |= bc & msk;
            }
            // words 2c, 2c+1 are now final; update kept count
            unsigned long long r0 = __shfl_sync(0xffffffffu, removed, 2 * c);
            unsigned long long r1 = __shfl_sync(0xffffffffu, removed, 2 * c + 1);
            if (lane == 0) {
                s_kept += __popcll(~r0) + __popcll(~r1);
                if (s_kept >= KEEPK && s_done == 0) s_done = c + 1;
            }
        }
        __syncthreads();
        if (s_done) { done_chunks = s_done; break; }
    }
    if (warp == 0) {
        int wlim = 2 * done_chunks;
        keepm[lane] = (lane < wlim) ? ~removed : 0ULL;
    }
    __syncthreads();

    int e0 = 2 * tid, e1 = 2 * tid + 1;
    int a0 = (int)((keepm[e0 >> 6] >> (e0 & 63)) & 1ULL);
    int a1 = (int)((keepm[e1 >> 6] >> (e1 & 63)) & 1ULL);
    int ps = a0 + a1;
    int v = ps;
#pragma unroll
    for (int o = 1; o < 32; o <<= 1) {
        int u = __shfl_up_sync(0xffffffffu, v, o);
        if (lane >= o) v += u;
    }
    if (lane == 31) wtot[warp] = v;
    __syncthreads();
    if (warp == 0) {
        int w = wtot[lane];
#pragma unroll
        for (int o = 1; o < 32; o <<= 1) {
            int u = __shfl_up_sync(0xffffffffu, w, o);
            if (lane >= o) w += u;
        }
        wtot[lane] = w;
    }
    __syncthreads();
    int base = (warp ? wtot[warp - 1] : 0) + v - ps;
    int c0 = base + a0;
    int c1 = c0 + a1;
    if (e0 < TOPK)
        out[((size_t)b * TOPK + e0) * 15 + 14] =
            ss[e0] * ((a0 && c0 <= KEEPK) ? 1.0f : 0.0f);
    if (e1 < TOPK)
        out[((size_t)b * TOPK + e1) * 15 + 14] =
            ss[e1] * ((a1 && c1 <= KEEPK) ? 1.0f : 0.0f);
}

// ---------------------------------------------------------------------------
extern "C" void kernel_launch(void* const* d_in, const int* in_sizes, int n_in,
                              void* d_out, int out_size) {
    const float* loc = nullptr;
    const float* conf = nullptr;
    const float* iou = nullptr;
    for (int i = 0; i < n_in; i++) {
        if (in_sizes[i] == NBATCH * NPRI * 14) loc = (const float*)d_in[i];
        else if (in_sizes[i] == NBATCH * NPRI * 2) conf = (const float*)d_in[i];
        else if (in_sizes[i] == NBATCH * NPRI) iou = (const float*)d_in[i];
    }
    float* out = (float*)d_out;

    dim3 ghalf((NPRI / 2 + 255) / 256, NBATCH);
    k_scores<<<ghalf, 256>>>(conf, iou);
    k_compact<<<ghalf, 256>>>(conf, iou);

    k_sortchunk<<<dim3(4, NBATCH), 1024>>>();

    cudaFuncSetAttribute(k_merge, cudaFuncAttributeMaxDynamicSharedMemorySize,
                         65536);
    k_merge<<<NBATCH, 1024, 65536>>>();

    k_decode<<<(NBATCH * TOPK + 127) / 128, 128>>>(loc, out);

    k_mask<<<dim3(528, NBATCH), 64>>>();

    cudaFuncSetAttribute(k_serial, cudaFuncAttributeMaxDynamicSharedMemorySize,
                         65536);
    k_serial<<<NBATCH, 1024, 65536>>>(out);
}

// round 15
// speedup vs baseline: 15.3307x; 1.0339x over previous
#include <cuda_runtime.h>
#include <cuda_bf16.h>
#include <math.h>
#include <stdint.h>

#define NBATCH 16
#define NPRI   119130
#define TOPK   2000
#define KEEPK  750
#define CAP    8192
#define NBINS  256
#define BIN_OFF 16024   // (__float_as_uint(0.299f)>>16) == 16025 -> bin 1
#define TARGET 2300     // pivot margin over TOPK (absorbs 1e-6 approx error)

// Level layout (IMG 1920x1080, steps {8,16,32,64}):
// L0: off 0      cnt 97200  fw 240 step 8  nms 3  sizes {10,16,24}
// L1: off 97200  cnt 16320  fw 120 step 16 nms 2  sizes {32,48}
// L2: off 113520 cnt 4080   fw 60  step 32 nms 2  sizes {64,96}
// L3: off 117600 cnt 1530   fw 30  step 64 nms 3  sizes {128,192,256}

__device__ unsigned char      g_bins[NBATCH * NPRI];   // 0 = not candidate
__device__ unsigned int       g_hist[NBATCH * NBINS];  // zeroed by k_serial
__device__ int                g_selcnt[NBATCH];        // zeroed by k_serial
__device__ unsigned long long g_sel[NBATCH * CAP];
__device__ unsigned long long g_top[NBATCH * 2048];
__device__ float              g_boxes[NBATCH * 4 * 2048];
// suppression bitmask: lower-tri words never written, stay 0 (static init)
__device__ unsigned long long g_mask[(size_t)NBATCH * 2048 * 32];
__device__ double             g_exp_tab[64];   // 2^(j/64)

// ---------------------------------------------------------------------------
// Fast fp64 exp via 64-entry table + degree-5 poly; error ~2^-52.
// Used ONLY for selection scores (ordering must match CPU reference bitwise).
// ---------------------------------------------------------------------------
__device__ __forceinline__ double exp_pd(double x) {
    double t = x * 92.332482616893658071;                // 64*log2(e)
    int ni = __double2int_rn(t);
    double nd = (double)ni;
    double r = fma(nd, -1.0830424693267559625e-02, x);   // ln2_hi/64
    r = fma(nd, -2.9815858269852932813e-12, r);          // ln2_lo/64
    double q = 8.3333333333333333333e-03;                // 1/120
    q = fma(q, r, 4.1666666666666666667e-02);            // 1/24
    q = fma(q, r, 1.6666666666666666667e-01);            // 1/6
    q = fma(q, r, 0.5);
    q = fma(q, r, 1.0);
    q = q * r;                                           // expm1(r)
    double T = g_exp_tab[ni & 63];
    T = __longlong_as_double(__double_as_longlong(T) +
                             ((long long)(ni >> 6) << 52));
    return fma(T, q, T);
}

__device__ __forceinline__ float softmax1_exact(float c0, float c1) {
    if (c1 >= c0) {
        float e0 = (float)exp_pd((double)__fsub_rn(c0, c1));
        return __fdiv_rn(1.0f, __fadd_rn(e0, 1.0f));
    } else {
        float e1 = (float)exp_pd((double)__fsub_rn(c1, c0));
        return __fdiv_rn(e1, __fadd_rn(1.0f, e1));
    }
}

__device__ __forceinline__ unsigned char bin_of(float c0, float c1, float u) {
    float s = 0.0f;
    if (u > 0.0f) {
        float pf = 1.0f / (1.0f + __expf(c0 - c1));  // rel err ~1e-6
        float sf = sqrtf(pf * u);
        if (sf >= 0.299f) s = sf;                     // guard band
    }
    if (s <= 0.0f) return 0;
    int bin = (int)(__float_as_uint(s) >> 16) - BIN_OFF;
    return (unsigned char)min(max(bin, 1), 255);
}

// ---------------------------------------------------------------------------
// K1: approx scores -> u8 bins (2 priors/thread, vector loads) + histogram;
//     block (0,0) also fills the exp table.
// ---------------------------------------------------------------------------
__global__ void k_scores(const float* __restrict__ conf,
                         const float* __restrict__ iou) {
    __shared__ unsigned sh[NBINS];
    int b = blockIdx.y;
    int t = threadIdx.x;
    if (blockIdx.x == 0 && blockIdx.y == 0 && t < 64)
        g_exp_tab[t] = exp2((double)t * 0.015625);
    sh[t] = 0;
    __syncthreads();
    int h = blockIdx.x * 256 + t;           // half-index (2 priors each)
    if (h < NPRI / 2) {
        const float4* cb = (const float4*)(conf + (size_t)b * NPRI * 2);
        const float2* ib = (const float2*)(iou + (size_t)b * NPRI);
        float4 c = cb[h];
        float2 uv = ib[h];
        float u0 = fminf(fmaxf(uv.x, 0.0f), 1.0f);
        float u1 = fminf(fmaxf(uv.y, 0.0f), 1.0f);
        unsigned char b0 = bin_of(c.x, c.y, u0);
        unsigned char b1 = bin_of(c.z, c.w, u1);
        ((unsigned short*)g_bins)[(size_t)b * (NPRI / 2) + h] =
            (unsigned short)(b0 | ((unsigned)b1 << 8));
        if (b0) atomicAdd(&sh[b0], 1u);
        if (b1) atomicAdd(&sh[b1], 1u);
    }
    __syncthreads();
    unsigned v = sh[t];
    if (v) atomicAdd(&g_hist[b * NBINS + t], v);
}

// ---------------------------------------------------------------------------
// K2: fused pivot (recomputed per block, deterministic) + compaction
//     (block-local) + dense exact rescore -> final sort keys in g_sel.
// ---------------------------------------------------------------------------
__global__ void k_compact(const float* __restrict__ conf,
                          const float* __restrict__ iou) {
    __shared__ unsigned s_wt[8];
    __shared__ int s_pivot;
    __shared__ int s_cnt;
    __shared__ int s_base;
    __shared__ int s_idx[512];
    int b = blockIdx.y;
    int t = threadIdx.x;
    int lane = t & 31, w = t >> 5;

    unsigned hh = g_hist[b * NBINS + t];
    unsigned v = hh;
#pragma unroll
    for (int o = 1; o < 32; o <<= 1) {
        unsigned u = __shfl_up_sync(0xffffffffu, v, o);
        if (lane >= o) v += u;
    }
    if (lane == 31) s_wt[w] = v;
    if (t == 0) s_cnt = 0;
    __syncthreads();
    if (t < 8) {
        unsigned x = s_wt[t];
#pragma unroll
        for (int o = 1; o < 8; o <<= 1) {
            unsigned u = __shfl_up_sync(0xffu, x, o);
            if (t >= o) x += u;
        }
        s_wt[t] = x;
    }
    __syncthreads();
    unsigned pre = v + (w ? s_wt[w - 1] : 0);   // inclusive prefix
    unsigned total = s_wt[7];
    unsigned Ct = total - pre + hh;             // suffix sum from bin t
    bool qual = (Ct >= TARGET) && (t == 255 || (Ct - hh) < TARGET);
    if (qual) s_pivot = t;
    if (t == 0 && total < TARGET) s_pivot = 0;
    __syncthreads();
    int pivot = s_pivot;

    int h = blockIdx.x * 256 + t;
    if (h < NPRI / 2) {
        unsigned short bb =
            ((const unsigned short*)g_bins)[(size_t)b * (NPRI / 2) + h];
        int b0 = bb & 0xFF, b1 = bb >> 8;
        if (b0 && b0 >= pivot) s_idx[atomicAdd(&s_cnt, 1)] = 2 * h;
        if (b1 && b1 >= pivot) s_idx[atomicAdd(&s_cnt, 1)] = 2 * h + 1;
    }
    __syncthreads();
    int cnt = s_cnt;
    if (t == 0 && cnt > 0) s_base = atomicAdd(&g_selcnt[b], cnt);
    __syncthreads();

    for (int k = t; k < cnt; k += 256) {
        int idx = s_idx[k];
        size_t e = (size_t)b * NPRI + (size_t)idx;
        float2 c = ((const float2*)conf)[e];
        float u = iou[e];
        u = fminf(fmaxf(u, 0.0f), 1.0f);
        float p = softmax1_exact(c.x, c.y);
        float s = __fsqrt_rn(__fmul_rn(p, u));
        unsigned long long key = 0ULL;
        if (s >= 0.3f)
            key = ((unsigned long long)__float_as_uint(s) << 32) |
                  (unsigned)(0x7FFFFFFF - idx);
        int pos = s_base + k;
        if (pos < CAP) g_sel[b * CAP + pos] = key;
    }
}

// ---------------------------------------------------------------------------
// K3: per-(batch,chunk) bitonic sort desc of 2048 keys (1 pair/thread/pass).
//     Chunks fully inside padding skip the sort and just write zeros.
// ---------------------------------------------------------------------------
__global__ void k_sortchunk() {
    __shared__ unsigned long long keys[2048];
    int b = blockIdx.y, c = blockIdx.x;
    int tid = threadIdx.x;
    int m = g_selcnt[b];
    if (m > CAP) m = CAP;
    int base = c * 2048;
    if (base >= m) {   // all padding: just materialize zeros
        for (int i = tid; i < 2048; i += 1024)
            g_sel[b * CAP + base + i] = 0ULL;
        return;
    }
    for (int i = tid; i < 2048; i += 1024)
        keys[i] = (base + i < m) ? g_sel[b * CAP + base + i] : 0ULL;
    for (int k = 2; k <= 2048; k <<= 1) {
        for (int j = k >> 1; j > 0; j >>= 1) {
            __syncthreads();
            int i = ((tid & ~(j - 1)) << 1) | (tid & (j - 1));
            int l = i + j;
            unsigned long long a = keys[i], bb = keys[l];
            bool up = ((i & k) == 0);
            if (up ? (a < bb) : (a > bb)) { keys[i] = bb; keys[l] = a; }
        }
    }
    __syncthreads();
    for (int i = tid; i < 2048; i += 1024)
        g_sel[b * CAP + base + i] = keys[i];
}

// ---------------------------------------------------------------------------
// K4: merge-path top-2048 of the 4 sorted chunks (one kernel, 2 stages).
// corank: i = number of A-elements among the first d0 merged outputs for a
// DESCENDING merge with A-wins-ties. Advance i while A[i] >= B[d0-i-1]
// (on tie A[i] precedes B[d0-i-1], so i grows). Consistent with emit's
// "take A when a >= bb".
// ---------------------------------------------------------------------------
__device__ __forceinline__ int corank(const unsigned long long* A,
                                      const unsigned long long* B, int d0) {
    int lo = d0 > 2048 ? d0 - 2048 : 0;
    int hi = d0 < 2048 ? d0 : 2048;
    while (lo < hi) {
        int i = (lo + hi) >> 1;
        if (A[i] >= B[d0 - i - 1]) lo = i + 1; else hi = i;
    }
    return lo;
}

__global__ void k_merge() {
    extern __shared__ unsigned long long K[];   // 8192 in + 4096 mid = 96KB
    int b = blockIdx.x;
    int tid = threadIdx.x;
    for (int i = tid; i < 8192; i += 1024)
        K[i] = g_sel[(size_t)b * CAP + i];
    __syncthreads();
    unsigned long long* M = K + 8192;
    {   // stage 1: top-2048 of (c0,c1) -> M[0..2048), (c2,c3) -> M[2048..4096)
        int half = tid >> 9;
        int lt = tid & 511;
        const unsigned long long* A = K + half * 4096;
        const unsigned long long* B = A + 2048;
        unsigned long long* O = M + half * 2048;
        int d0 = lt * 4;
        int i = corank(A, B, d0);
        int j = d0 - i;
#pragma unroll
        for (int k = 0; k < 4; k++) {
            unsigned long long a = (i < 2048) ? A[i] : 0ULL;
            unsigned long long bb = (j < 2048) ? B[j] : 0ULL;
            bool ta = (j >= 2048) || ((i < 2048) && a >= bb);
            O[d0 + k] = ta ? a : bb;
            if (ta) i++; else j++;
        }
    }
    __syncthreads();
    {   // stage 2: top-2048 of (M0, M1) -> g_top
        const unsigned long long* A = M;
        const unsigned long long* B = M + 2048;
        int d0 = tid * 2;
        int i = corank(A, B, d0);
        int j = d0 - i;
        unsigned long long o[2];
#pragma unroll
        for (int k = 0; k < 2; k++) {
            unsigned long long a = (i < 2048) ? A[i] : 0ULL;
            unsigned long long bb = (j < 2048) ? B[j] : 0ULL;
            bool ta = (j >= 2048) || ((i < 2048) && a >= bb);
            o[k] = ta ? a : bb;
            if (ta) i++; else j++;
        }
        g_top[(size_t)b * 2048 + d0] = o[0];
        g_top[(size_t)b * 2048 + d0 + 1] = o[1];
    }
}

__constant__ float PW[10] = {
    (float)(10.0/1920.0),(float)(16.0/1920.0),(float)(24.0/1920.0),
    (float)(32.0/1920.0),(float)(48.0/1920.0),
    (float)(64.0/1920.0),(float)(96.0/1920.0),
    (float)(128.0/1920.0),(float)(192.0/1920.0),(float)(256.0/1920.0)};
__constant__ float PH[10] = {
    (float)(10.0/1080.0),(float)(16.0/1080.0),(float)(24.0/1080.0),
    (float)(32.0/1080.0),(float)(48.0/1080.0),
    (float)(64.0/1080.0),(float)(96.0/1080.0),
    (float)(128.0/1080.0),(float)(192.0/1080.0),(float)(256.0/1080.0)};

__device__ __forceinline__ void prior_of(int idx, float& pcx, float& pcy,
                                         float& pw, float& ph) {
    int off, fw, step, nm, msoff;
    if (idx < 97200)       { off = 0;      fw = 240; step = 8;  nm = 3; msoff = 0; }
    else if (idx < 113520) { off = 97200;  fw = 120; step = 16; nm = 2; msoff = 3; }
    else if (idx < 117600) { off = 113520; fw = 60;  step = 32; nm = 2; msoff = 5; }
    else                   { off = 117600; fw = 30;  step = 64; nm = 3; msoff = 7; }
    int r = idx - off;
    int cell = r / nm;
    int mi = r - cell * nm;
    int row = cell / fw;
    int col = cell - row * fw;
    double tx = ((double)col + 0.5) * (double)step;
    double ty = ((double)row + 0.5) * (double)step;
    pcx = (float)(tx * (1.0 / 1920.0));
    pcy = (float)(ty * (1.0 / 1080.0));
    pw = PW[msoff + mi];
    ph = PH[msoff + mi];
}

// ---------------------------------------------------------------------------
// K5: decode, 2 threads per row (part0: box + exps; part1: landmarks).
// Decode exp is fp32 __expf (~2ulp): cols 0-13 well within tolerance; only
// near-threshold NMS IoU decisions can flip (col-14-only effect, ~1e-6 rel).
// ---------------------------------------------------------------------------
__global__ void k_decode(const float* __restrict__ loc,
                         float* __restrict__ out) {
    int t2 = blockIdx.x * blockDim.x + threadIdx.x;
    int row = t2 >> 1, part = t2 & 1;
    if (row >= NBATCH * TOPK) return;
    int b = row / TOPK;
    int r = row - b * TOPK;
    unsigned long long kk = g_top[b * 2048 + r];
    int idx = 0x7FFFFFFF - (int)(unsigned)(kk & 0xFFFFFFFFu);
    if (idx < 0 || idx >= NPRI) idx = 0;

    float pcx, pcy, pw, ph;
    prior_of(idx, pcx, pcy, pw, ph);
    const float2* lp = (const float2*)(loc + ((size_t)b * NPRI + (size_t)idx) * 14);
    float* op = out + (size_t)row * 15;

    if (part == 0) {
        float2 l01 = lp[0], l23 = lp[1];
        float cx = __fadd_rn(pcx, __fmul_rn(__fmul_rn(l01.x, 0.1f), pw));
        float cy = __fadd_rn(pcy, __fmul_rn(__fmul_rn(l01.y, 0.1f), ph));
        float w  = __fmul_rn(pw, __expf(__fmul_rn(l23.x, 0.1f)));
        float h  = __fmul_rn(ph, __expf(__fmul_rn(l23.y, 0.2f)));
        float x1 = __fsub_rn(cx, __fmul_rn(w, 0.5f));
        float y1 = __fsub_rn(cy, __fmul_rn(h, 0.5f));
        float x2 = __fadd_rn(x1, w);
        float y2 = __fadd_rn(y1, h);
        float X1 = __fmul_rn(x1, 1920.0f), Y1 = __fmul_rn(y1, 1080.0f);
        float X2 = __fmul_rn(x2, 1920.0f), Y2 = __fmul_rn(y2, 1080.0f);
        op[0] = X1; op[1] = Y1; op[2] = X2; op[3] = Y2;
        g_boxes[b * 8192 + 0 * 2048 + r] = X1;
        g_boxes[b * 8192 + 1 * 2048 + r] = Y1;
        g_boxes[b * 8192 + 2 * 2048 + r] = X2;
        g_boxes[b * 8192 + 3 * 2048 + r] = Y2;
    } else {
        float2 lm[5];
#pragma unroll
        for (int k = 0; k < 5; k++) lm[k] = lp[2 + k];
#pragma unroll
        for (int k = 0; k < 5; k++) {
            float lx = __fadd_rn(pcx, __fmul_rn(__fmul_rn(lm[k].x, 0.1f), pw));
            float ly = __fadd_rn(pcy, __fmul_rn(__fmul_rn(lm[k].y, 0.1f), ph));
            op[4 + 2 * k] = __fmul_rn(lx, 1920.0f);
            op[5 + 2 * k] = __fmul_rn(ly, 1080.0f);
        }
    }
}

// ---------------------------------------------------------------------------
// K6a: suppression bitmask build. Triangular grid: 528 tiles/batch (jt>=it).
// ---------------------------------------------------------------------------
__global__ void k_mask() {
    int p = blockIdx.x, b = blockIdx.y;
    int it = 0, rem = p;
    while (rem >= 32 - it) { rem -= 32 - it; it++; }
    int jt = it + rem;
    __shared__ float cx1[64], cy1[64], cx2[64], cy2[64], ca[64];
    int t = threadIdx.x;
    int j0 = jt * 64;
    {
        float x1 = g_boxes[b * 8192 + 0 * 2048 + j0 + t];
        float y1 = g_boxes[b * 8192 + 1 * 2048 + j0 + t];
        float x2 = g_boxes[b * 8192 + 2 * 2048 + j0 + t];
        float y2 = g_boxes[b * 8192 + 3 * 2048 + j0 + t];
        cx1[t] = x1; cy1[t] = y1; cx2[t] = x2; cy2[t] = y2;
        ca[t] = __fmul_rn(fmaxf(__fsub_rn(x2, x1), 0.0f),
                          fmaxf(__fsub_rn(y2, y1), 0.0f));
    }
    __syncthreads();
    int i = it * 64 + t;
    float xi1 = g_boxes[b * 8192 + 0 * 2048 + i];
    float yi1 = g_boxes[b * 8192 + 1 * 2048 + i];
    float xi2 = g_boxes[b * 8192 + 2 * 2048 + i];
    float yi2 = g_boxes[b * 8192 + 3 * 2048 + i];
    float ai = __fmul_rn(fmaxf(__fsub_rn(xi2, xi1), 0.0f),
                         fmaxf(__fsub_rn(yi2, yi1), 0.0f));
    unsigned long long word = 0ULL;
    int jj0 = (jt == it) ? (t + 1) : 0;
    for (int jj = jj0; jj < 64; jj++) {
        float lx = fmaxf(xi1, cx1[jj]), ly = fmaxf(yi1, cy1[jj]);
        float rx = fminf(xi2, cx2[jj]), ry = fminf(yi2, cy2[jj]);
        float iw = fmaxf(__fsub_rn(rx, lx), 0.0f);
        float ih = fmaxf(__fsub_rn(ry, ly), 0.0f);
        float inter = __fmul_rn(iw, ih);
        if (inter > 0.0f) {  // division only when boxes overlap
            float denom = __fadd_rn(
                __fsub_rn(__fadd_rn(ai, ca[jj]), inter), 1e-9f);
            if (__fdiv_rn(inter, denom) > 0.3f) word |= (1ULL << jj);
        }
    }
    g_mask[((size_t)b * 2048 + i) * 32 + jt] = word;
}

// ---------------------------------------------------------------------------
// K6b: per-batch serial bitmask scan with smem staging + early exit once the
//      750th keep is reached. Then cumsum -> out col 14. Also zeroes
//      g_hist[b] / g_selcnt[b] for the next run.
// ---------------------------------------------------------------------------
__global__ void k_serial(float* __restrict__ out) {
    extern __shared__ unsigned long long sbuf[];   // 2 * 128 * 32 ull = 64KB
    __shared__ unsigned long long initm[32];
    __shared__ unsigned long long keepm[32];
    __shared__ float ss[2048];
    __shared__ int wtot[33];
    __shared__ int s_kept, s_done;
    int b = blockIdx.x;
    int tid = threadIdx.x;
    int warp = tid >> 5, lane = tid & 31;

    for (int r = tid; r < 2048; r += 1024) {
        unsigned long long kk = g_top[b * 2048 + r];
        float sc = __uint_as_float((unsigned)(kk >> 32));
        ss[r] = (r < TOPK) ? sc : 0.0f;
    }
    if (tid < NBINS) g_hist[b * NBINS + tid] = 0;
    if (tid == 0) { g_selcnt[b] = 0; s_kept = 0; s_done = 0; }
    __syncthreads();

    unsigned lo = __ballot_sync(0xffffffffu, ss[warp * 64 + lane] > 0.0f);
    unsigned hi = __ballot_sync(0xffffffffu, ss[warp * 64 + 32 + lane] > 0.0f);
    if (lane == 0) initm[warp] = ((unsigned long long)hi << 32) | lo;

    const unsigned long long* mrow = g_mask + (size_t)b * 2048 * 32;
    for (int k = tid; k < 4096; k += 1024) sbuf[k] = mrow[k];
    __syncthreads();

    unsigned long long removed = ~initm[lane];  // bit set = inactive
    int done_chunks = 16;
    for (int c = 0; c < 16; c++) {
        int pb = (c & 1) * 4096;
        if (warp != 0 && c + 1 < 16) {
            int nb = ((c + 1) & 1) * 4096;
            const unsigned long long* src = mrow + (size_t)(c + 1) * 4096;
            for (int k = tid - 32; k < 4096; k += 992)
                sbuf[nb + k] = src[k];
        }
        if (warp == 0) {
            unsigned long long rm_w = 0;
#pragma unroll 8
            for (int il = 0; il < 128; il++) {
                int i = c * 128 + il;
                int w = i >> 6, bit = i & 63;
                if (bit == 0) rm_w = __shfl_sync(0xffffffffu, removed, w);
                unsigned long long own = sbuf[pb + il * 32 + lane];
                unsigned long long bc  = sbuf[pb + il * 32 + w];
                unsigned long long msk = ~(unsigned long long)(
                    ((long long)(rm_w << (63 - bit))) >> 63);
                removed |= own & msk;
                rm_w |= bc & msk;
            }
            unsigned long long r0 = __shfl_sync(0xffffffffu, removed, 2 * c);
            unsigned long long r1 = __shfl_sync(0xffffffffu, removed, 2 * c + 1);
            if (lane == 0) {
                s_kept += __popcll(~r0) + __popcll(~r1);
                if (s_kept >= KEEPK && s_done == 0) s_done = c + 1;
            }
        }
        __syncthreads();
        if (s_done) { done_chunks = s_done; break; }
    }
    if (warp == 0) {
        int wlim = 2 * done_chunks;
        keepm[lane] = (lane < wlim) ? ~removed : 0ULL;
    }
    __syncthreads();

    int e0 = 2 * tid, e1 = 2 * tid + 1;
    int a0 = (int)((keepm[e0 >> 6] >> (e0 & 63)) & 1ULL);
    int a1 = (int)((keepm[e1 >> 6] >> (e1 & 63)) & 1ULL);
    int ps = a0 + a1;
    int v = ps;
#pragma unroll
    for (int o = 1; o < 32; o <<= 1) {
        int u = __shfl_up_sync(0xffffffffu, v, o);
        if (lane >= o) v += u;
    }
    if (lane == 31) wtot[warp] = v;
    __syncthreads();
    if (warp == 0) {
        int w = wtot[lane];
#pragma unroll
        for (int o = 1; o < 32; o <<= 1) {
            int u = __shfl_up_sync(0xffffffffu, w, o);
            if (lane >= o) w += u;
        }
        wtot[lane] = w;
    }
    __syncthreads();
    int base = (warp ? wtot[warp - 1] : 0) + v - ps;
    int c0 = base + a0;
    int c1 = c0 + a1;
    if (e0 < TOPK)
        out[((size_t)b * TOPK + e0) * 15 + 14] =
            ss[e0] * ((a0 && c0 <= KEEPK) ? 1.0f : 0.0f);
    if (e1 < TOPK)
        out[((size_t)b * TOPK + e1) * 15 + 14] =
            ss[e1] * ((a1 && c1 <= KEEPK) ? 1.0f : 0.0f);
}

// ---------------------------------------------------------------------------
extern "C" void kernel_launch(void* const* d_in, const int* in_sizes, int n_in,
                              void* d_out, int out_size) {
    const float* loc = nullptr;
    const float* conf = nullptr;
    const float* iou = nullptr;
    for (int i = 0; i < n_in; i++) {
        if (in_sizes[i] == NBATCH * NPRI * 14) loc = (const float*)d_in[i];
        else if (in_sizes[i] == NBATCH * NPRI * 2) conf = (const float*)d_in[i];
        else if (in_sizes[i] == NBATCH * NPRI) iou = (const float*)d_in[i];
    }
    float* out = (float*)d_out;

    dim3 ghalf((NPRI / 2 + 255) / 256, NBATCH);
    k_scores<<<ghalf, 256>>>(conf, iou);
    k_compact<<<ghalf, 256>>>(conf, iou);

    k_sortchunk<<<dim3(4, NBATCH), 1024>>>();

    cudaFuncSetAttribute(k_merge, cudaFuncAttributeMaxDynamicSharedMemorySize,
                         98304);
    k_merge<<<NBATCH, 1024, 98304>>>();

    k_decode<<<(NBATCH * TOPK * 2 + 255) / 256, 256>>>(loc, out);

    k_mask<<<dim3(528, NBATCH), 64>>>();

    cudaFuncSetAttribute(k_serial, cudaFuncAttributeMaxDynamicSharedMemorySize,
                         65536);
    k_serial<<<NBATCH, 1024, 65536>>>(out);
}

// round 17
// speedup vs baseline: 15.6958x; 1.0238x over previous
#include <cuda_runtime.h>
#include <cuda_bf16.h>
#include <math.h>
#include <stdint.h>

#define NBATCH 16
#define NPRI   119130
#define TOPK   2000
#define KEEPK  750
#define CAP    8192
#define NBINS  256
#define BIN_OFF 16024   // (__float_as_uint(0.299f)>>16) == 16025 -> bin 1
#define TARGET 2300     // pivot margin over TOPK (absorbs 1e-6 approx error)

// Level layout (IMG 1920x1080, steps {8,16,32,64}):
// L0: off 0      cnt 97200  fw 240 step 8  nms 3  sizes {10,16,24}
// L1: off 97200  cnt 16320  fw 120 step 16 nms 2  sizes {32,48}
// L2: off 113520 cnt 4080   fw 60  step 32 nms 2  sizes {64,96}
// L3: off 117600 cnt 1530   fw 30  step 64 nms 3  sizes {128,192,256}

__device__ unsigned char      g_bins[NBATCH * NPRI];   // 0 = not candidate
__device__ unsigned int       g_hist[NBATCH * NBINS];  // zeroed by k_serial
__device__ int                g_selcnt[NBATCH];        // zeroed by k_serial
__device__ unsigned long long g_sel[NBATCH * CAP];
__device__ unsigned long long g_top[NBATCH * 2048];
__device__ float              g_boxes[NBATCH * 4 * 2048];
// suppression bitmask: lower-tri words never written, stay 0 (static init)
__device__ unsigned long long g_mask[(size_t)NBATCH * 2048 * 32];
__device__ double             g_exp_tab[64];   // 2^(j/64)

// ---------------------------------------------------------------------------
// Fast fp64 exp via 64-entry table + degree-5 poly; error ~2^-52.
// Used ONLY for selection scores (ordering must match CPU reference bitwise).
// ---------------------------------------------------------------------------
__device__ __forceinline__ double exp_pd(double x) {
    double t = x * 92.332482616893658071;                // 64*log2(e)
    int ni = __double2int_rn(t);
    double nd = (double)ni;
    double r = fma(nd, -1.0830424693267559625e-02, x);   // ln2_hi/64
    r = fma(nd, -2.9815858269852932813e-12, r);          // ln2_lo/64
    double q = 8.3333333333333333333e-03;                // 1/120
    q = fma(q, r, 4.1666666666666666667e-02);            // 1/24
    q = fma(q, r, 1.6666666666666666667e-01);            // 1/6
    q = fma(q, r, 0.5);
    q = fma(q, r, 1.0);
    q = q * r;                                           // expm1(r)
    double T = g_exp_tab[ni & 63];
    T = __longlong_as_double(__double_as_longlong(T) +
                             ((long long)(ni >> 6) << 52));
    return fma(T, q, T);
}

__device__ __forceinline__ float softmax1_exact(float c0, float c1) {
    if (c1 >= c0) {
        float e0 = (float)exp_pd((double)__fsub_rn(c0, c1));
        return __fdiv_rn(1.0f, __fadd_rn(e0, 1.0f));
    } else {
        float e1 = (float)exp_pd((double)__fsub_rn(c1, c0));
        return __fdiv_rn(e1, __fadd_rn(1.0f, e1));
    }
}

__device__ __forceinline__ unsigned char bin_of(float c0, float c1, float u) {
    float s = 0.0f;
    if (u > 0.0f) {
        float pf = 1.0f / (1.0f + __expf(c0 - c1));  // rel err ~1e-6
        float sf = sqrtf(pf * u);
        if (sf >= 0.299f) s = sf;                     // guard band
    }
    if (s <= 0.0f) return 0;
    int bin = (int)(__float_as_uint(s) >> 16) - BIN_OFF;
    return (unsigned char)min(max(bin, 1), 255);
}

// ---------------------------------------------------------------------------
// K1: approx scores -> u8 bins (2 priors/thread, vector loads) + histogram;
//     block (0,0) also fills the exp table.
// ---------------------------------------------------------------------------
__global__ void k_scores(const float* __restrict__ conf,
                         const float* __restrict__ iou) {
    __shared__ unsigned sh[NBINS];
    int b = blockIdx.y;
    int t = threadIdx.x;
    if (blockIdx.x == 0 && blockIdx.y == 0 && t < 64)
        g_exp_tab[t] = exp2((double)t * 0.015625);
    sh[t] = 0;
    __syncthreads();
    int h = blockIdx.x * 256 + t;           // half-index (2 priors each)
    if (h < NPRI / 2) {
        const float4* cb = (const float4*)(conf + (size_t)b * NPRI * 2);
        const float2* ib = (const float2*)(iou + (size_t)b * NPRI);
        float4 c = cb[h];
        float2 uv = ib[h];
        float u0 = fminf(fmaxf(uv.x, 0.0f), 1.0f);
        float u1 = fminf(fmaxf(uv.y, 0.0f), 1.0f);
        unsigned char b0 = bin_of(c.x, c.y, u0);
        unsigned char b1 = bin_of(c.z, c.w, u1);
        ((unsigned short*)g_bins)[(size_t)b * (NPRI / 2) + h] =
            (unsigned short)(b0 | ((unsigned)b1 << 8));
        if (b0) atomicAdd(&sh[b0], 1u);
        if (b1) atomicAdd(&sh[b1], 1u);
    }
    __syncthreads();
    unsigned v = sh[t];
    if (v) atomicAdd(&g_hist[b * NBINS + t], v);
}

// ---------------------------------------------------------------------------
// K2: fused pivot (recomputed per block, deterministic) + compaction
//     (block-local) + dense exact rescore -> final sort keys in g_sel.
// ---------------------------------------------------------------------------
__global__ void k_compact(const float* __restrict__ conf,
                          const float* __restrict__ iou) {
    __shared__ unsigned s_wt[8];
    __shared__ int s_pivot;
    __shared__ int s_cnt;
    __shared__ int s_base;
    __shared__ int s_idx[512];
    int b = blockIdx.y;
    int t = threadIdx.x;
    int lane = t & 31, w = t >> 5;

    unsigned hh = g_hist[b * NBINS + t];
    unsigned v = hh;
#pragma unroll
    for (int o = 1; o < 32; o <<= 1) {
        unsigned u = __shfl_up_sync(0xffffffffu, v, o);
        if (lane >= o) v += u;
    }
    if (lane == 31) s_wt[w] = v;
    if (t == 0) s_cnt = 0;
    __syncthreads();
    if (t < 8) {
        unsigned x = s_wt[t];
#pragma unroll
        for (int o = 1; o < 8; o <<= 1) {
            unsigned u = __shfl_up_sync(0xffu, x, o);
            if (t >= o) x += u;
        }
        s_wt[t] = x;
    }
    __syncthreads();
    unsigned pre = v + (w ? s_wt[w - 1] : 0);   // inclusive prefix
    unsigned total = s_wt[7];
    unsigned Ct = total - pre + hh;             // suffix sum from bin t
    bool qual = (Ct >= TARGET) && (t == 255 || (Ct - hh) < TARGET);
    if (qual) s_pivot = t;
    if (t == 0 && total < TARGET) s_pivot = 0;
    __syncthreads();
    int pivot = s_pivot;

    int h = blockIdx.x * 256 + t;
    if (h < NPRI / 2) {
        unsigned short bb =
            ((const unsigned short*)g_bins)[(size_t)b * (NPRI / 2) + h];
        int b0 = bb & 0xFF, b1 = bb >> 8;
        if (b0 && b0 >= pivot) s_idx[atomicAdd(&s_cnt, 1)] = 2 * h;
        if (b1 && b1 >= pivot) s_idx[atomicAdd(&s_cnt, 1)] = 2 * h + 1;
    }
    __syncthreads();
    int cnt = s_cnt;
    if (t == 0 && cnt > 0) s_base = atomicAdd(&g_selcnt[b], cnt);
    __syncthreads();

    for (int k = t; k < cnt; k += 256) {
        int idx = s_idx[k];
        size_t e = (size_t)b * NPRI + (size_t)idx;
        float2 c = ((const float2*)conf)[e];
        float u = iou[e];
        u = fminf(fmaxf(u, 0.0f), 1.0f);
        float p = softmax1_exact(c.x, c.y);
        float s = __fsqrt_rn(__fmul_rn(p, u));
        unsigned long long key = 0ULL;
        if (s >= 0.3f)
            key = ((unsigned long long)__float_as_uint(s) << 32) |
                  (unsigned)(0x7FFFFFFF - idx);
        int pos = s_base + k;
        if (pos < CAP) g_sel[b * CAP + pos] = key;
    }
}

// ---------------------------------------------------------------------------
// K3: per-(batch,chunk) bitonic sort desc of 2048 keys (1 pair/thread/pass).
//     Chunks fully inside padding skip the sort and just write zeros.
// ---------------------------------------------------------------------------
__global__ void k_sortchunk() {
    __shared__ unsigned long long keys[2048];
    int b = blockIdx.y, c = blockIdx.x;
    int tid = threadIdx.x;
    int m = g_selcnt[b];
    if (m > CAP) m = CAP;
    int base = c * 2048;
    if (base >= m) {   // all padding: just materialize zeros
        for (int i = tid; i < 2048; i += 1024)
            g_sel[b * CAP + base + i] = 0ULL;
        return;
    }
    for (int i = tid; i < 2048; i += 1024)
        keys[i] = (base + i < m) ? g_sel[b * CAP + base + i] : 0ULL;
    for (int k = 2; k <= 2048; k <<= 1) {
        for (int j = k >> 1; j > 0; j >>= 1) {
            __syncthreads();
            int i = ((tid & ~(j - 1)) << 1) | (tid & (j - 1));
            int l = i + j;
            unsigned long long a = keys[i], bb = keys[l];
            bool up = ((i & k) == 0);
            if (up ? (a < bb) : (a > bb)) { keys[i] = bb; keys[l] = a; }
        }
    }
    __syncthreads();
    for (int i = tid; i < 2048; i += 1024)
        g_sel[b * CAP + base + i] = keys[i];
}

// ---------------------------------------------------------------------------
// K4: merge-path top-2048 of the sorted chunks, ADAPTIVE on m = selcnt:
//  m <= 2048 : g_top = chunk0 (already final: real keys > 0-padding keys)
//  m <= 4096 : one merge-path stage of (c0,c1) -> g_top (c2,c3 all zeros)
//  else      : full two-stage path (exact worst case)
// All paths produce bit-identical g_top.
// corank: descending merge, A wins ties; advance i while A[i] >= B[d0-i-1].
// ---------------------------------------------------------------------------
__device__ __forceinline__ int corank(const unsigned long long* A,
                                      const unsigned long long* B, int d0) {
    int lo = d0 > 2048 ? d0 - 2048 : 0;
    int hi = d0 < 2048 ? d0 : 2048;
    while (lo < hi) {
        int i = (lo + hi) >> 1;
        if (A[i] >= B[d0 - i - 1]) lo = i + 1; else hi = i;
    }
    return lo;
}

__global__ void k_merge() {
    extern __shared__ unsigned long long K[];   // up to 8192+4096 ull = 96KB
    int b = blockIdx.x;
    int tid = threadIdx.x;
    int m = g_selcnt[b];
    if (m > CAP) m = CAP;

    if (m <= 2048) {          // chunk0 already the final top-2048
        for (int i = tid; i < 2048; i += 1024)
            g_top[(size_t)b * 2048 + i] = g_sel[(size_t)b * CAP + i];
        return;
    }

    if (m <= 4096) {          // single stage: merge (c0, c1) -> g_top
        for (int i = tid; i < 4096; i += 1024)
            K[i] = g_sel[(size_t)b * CAP + i];
        __syncthreads();
        const unsigned long long* A = K;
        const unsigned long long* B = K + 2048;
        int d0 = tid * 2;
        int i = corank(A, B, d0);
        int j = d0 - i;
        unsigned long long o[2];
#pragma unroll
        for (int k = 0; k < 2; k++) {
            unsigned long long a = (i < 2048) ? A[i] : 0ULL;
            unsigned long long bb = (j < 2048) ? B[j] : 0ULL;
            bool ta = (j >= 2048) || ((i < 2048) && a >= bb);
            o[k] = ta ? a : bb;
            if (ta) i++; else j++;
        }
        g_top[(size_t)b * 2048 + d0] = o[0];
        g_top[(size_t)b * 2048 + d0 + 1] = o[1];
        return;
    }

    // full two-stage path
    for (int i = tid; i < 8192; i += 1024)
        K[i] = g_sel[(size_t)b * CAP + i];
    __syncthreads();
    unsigned long long* M = K + 8192;
    {   // stage 1: top-2048 of (c0,c1) -> M[0..2048), (c2,c3) -> M[2048..4096)
        int half = tid >> 9;
        int lt = tid & 511;
        const unsigned long long* A = K + half * 4096;
        const unsigned long long* B = A + 2048;
        unsigned long long* O = M + half * 2048;
        int d0 = lt * 4;
        int i = corank(A, B, d0);
        int j = d0 - i;
#pragma unroll
        for (int k = 0; k < 4; k++) {
            unsigned long long a = (i < 2048) ? A[i] : 0ULL;
            unsigned long long bb = (j < 2048) ? B[j] : 0ULL;
            bool ta = (j >= 2048) || ((i < 2048) && a >= bb);
            O[d0 + k] = ta ? a : bb;
            if (ta) i++; else j++;
        }
    }
    __syncthreads();
    {   // stage 2: top-2048 of (M0, M1) -> g_top
        const unsigned long long* A = M;
        const unsigned long long* B = M + 2048;
        int d0 = tid * 2;
        int i = corank(A, B, d0);
        int j = d0 - i;
        unsigned long long o[2];
#pragma unroll
        for (int k = 0; k < 2; k++) {
            unsigned long long a = (i < 2048) ? A[i] : 0ULL;
            unsigned long long bb = (j < 2048) ? B[j] : 0ULL;
            bool ta = (j >= 2048) || ((i < 2048) && a >= bb);
            o[k] = ta ? a : bb;
            if (ta) i++; else j++;
        }
        g_top[(size_t)b * 2048 + d0] = o[0];
        g_top[(size_t)b * 2048 + d0 + 1] = o[1];
    }
}

__constant__ float PW[10] = {
    (float)(10.0/1920.0),(float)(16.0/1920.0),(float)(24.0/1920.0),
    (float)(32.0/1920.0),(float)(48.0/1920.0),
    (float)(64.0/1920.0),(float)(96.0/1920.0),
    (float)(128.0/1920.0),(float)(192.0/1920.0),(float)(256.0/1920.0)};
__constant__ float PH[10] = {
    (float)(10.0/1080.0),(float)(16.0/1080.0),(float)(24.0/1080.0),
    (float)(32.0/1080.0),(float)(48.0/1080.0),
    (float)(64.0/1080.0),(float)(96.0/1080.0),
    (float)(128.0/1080.0),(float)(192.0/1080.0),(float)(256.0/1080.0)};

__device__ __forceinline__ void prior_of(int idx, float& pcx, float& pcy,
                                         float& pw, float& ph) {
    int off, fw, step, nm, msoff;
    if (idx < 97200)       { off = 0;      fw = 240; step = 8;  nm = 3; msoff = 0; }
    else if (idx < 113520) { off = 97200;  fw = 120; step = 16; nm = 2; msoff = 3; }
    else if (idx < 117600) { off = 113520; fw = 60;  step = 32; nm = 2; msoff = 5; }
    else                   { off = 117600; fw = 30;  step = 64; nm = 3; msoff = 7; }
    int r = idx - off;
    int cell = r / nm;
    int mi = r - cell * nm;
    int row = cell / fw;
    int col = cell - row * fw;
    double tx = ((double)col + 0.5) * (double)step;
    double ty = ((double)row + 0.5) * (double)step;
    pcx = (float)(tx * (1.0 / 1920.0));
    pcy = (float)(ty * (1.0 / 1080.0));
    pw = PW[msoff + mi];
    ph = PH[msoff + mi];
}

// ---------------------------------------------------------------------------
// K5: decode, 2 threads per row (part0: box + exps; part1: landmarks).
// Decode exp is fp32 __expf (~2ulp): cols 0-13 well within tolerance; only
// near-threshold NMS IoU decisions can flip (col-14-only effect, ~1e-6 rel).
// ---------------------------------------------------------------------------
__global__ void k_decode(const float* __restrict__ loc,
                         float* __restrict__ out) {
    int t2 = blockIdx.x * blockDim.x + threadIdx.x;
    int row = t2 >> 1, part = t2 & 1;
    if (row >= NBATCH * TOPK) return;
    int b = row / TOPK;
    int r = row - b * TOPK;
    unsigned long long kk = g_top[b * 2048 + r];
    int idx = 0x7FFFFFFF - (int)(unsigned)(kk & 0xFFFFFFFFu);
    if (idx < 0 || idx >= NPRI) idx = 0;

    float pcx, pcy, pw, ph;
    prior_of(idx, pcx, pcy, pw, ph);
    const float2* lp = (const float2*)(loc + ((size_t)b * NPRI + (size_t)idx) * 14);
    float* op = out + (size_t)row * 15;

    if (part == 0) {
        float2 l01 = lp[0], l23 = lp[1];
        float cx = __fadd_rn(pcx, __fmul_rn(__fmul_rn(l01.x, 0.1f), pw));
        float cy = __fadd_rn(pcy, __fmul_rn(__fmul_rn(l01.y, 0.1f), ph));
        float w  = __fmul_rn(pw, __expf(__fmul_rn(l23.x, 0.1f)));
        float h  = __fmul_rn(ph, __expf(__fmul_rn(l23.y, 0.2f)));
        float x1 = __fsub_rn(cx, __fmul_rn(w, 0.5f));
        float y1 = __fsub_rn(cy, __fmul_rn(h, 0.5f));
        float x2 = __fadd_rn(x1, w);
        float y2 = __fadd_rn(y1, h);
        float X1 = __fmul_rn(x1, 1920.0f), Y1 = __fmul_rn(y1, 1080.0f);
        float X2 = __fmul_rn(x2, 1920.0f), Y2 = __fmul_rn(y2, 1080.0f);
        op[0] = X1; op[1] = Y1; op[2] = X2; op[3] = Y2;
        g_boxes[b * 8192 + 0 * 2048 + r] = X1;
        g_boxes[b * 8192 + 1 * 2048 + r] = Y1;
        g_boxes[b * 8192 + 2 * 2048 + r] = X2;
        g_boxes[b * 8192 + 3 * 2048 + r] = Y2;
    } else {
        float2 lm[5];
#pragma unroll
        for (int k = 0; k < 5; k++) lm[k] = lp[2 + k];
#pragma unroll
        for (int k = 0; k < 5; k++) {
            float lx = __fadd_rn(pcx, __fmul_rn(__fmul_rn(lm[k].x, 0.1f), pw));
            float ly = __fadd_rn(pcy, __fmul_rn(__fmul_rn(lm[k].y, 0.1f), ph));
            op[4 + 2 * k] = __fmul_rn(lx, 1920.0f);
            op[5 + 2 * k] = __fmul_rn(ly, 1080.0f);
        }
    }
}

// ---------------------------------------------------------------------------
// K6a: suppression bitmask build. Triangular grid: 528 tiles/batch (jt>=it).
// ---------------------------------------------------------------------------
__global__ void k_mask() {
    int p = blockIdx.x, b = blockIdx.y;
    int it = 0, rem = p;
    while (rem >= 32 - it) { rem -= 32 - it; it++; }
    int jt = it + rem;
    __shared__ float cx1[64], cy1[64], cx2[64], cy2[64], ca[64];
    int t = threadIdx.x;
    int j0 = jt * 64;
    {
        float x1 = g_boxes[b * 8192 + 0 * 2048 + j0 + t];
        float y1 = g_boxes[b * 8192 + 1 * 2048 + j0 + t];
        float x2 = g_boxes[b * 8192 + 2 * 2048 + j0 + t];
        float y2 = g_boxes[b * 8192 + 3 * 2048 + j0 + t];
        cx1[t] = x1; cy1[t] = y1; cx2[t] = x2; cy2[t] = y2;
        ca[t] = __fmul_rn(fmaxf(__fsub_rn(x2, x1), 0.0f),
                          fmaxf(__fsub_rn(y2, y1), 0.0f));
    }
    __syncthreads();
    int i = it * 64 + t;
    float xi1 = g_boxes[b * 8192 + 0 * 2048 + i];
    float yi1 = g_boxes[b * 8192 + 1 * 2048 + i];
    float xi2 = g_boxes[b * 8192 + 2 * 2048 + i];
    float yi2 = g_boxes[b * 8192 + 3 * 2048 + i];
    float ai = __fmul_rn(fmaxf(__fsub_rn(xi2, xi1), 0.0f),
                         fmaxf(__fsub_rn(yi2, yi1), 0.0f));
    unsigned long long word = 0ULL;
    int jj0 = (jt == it) ? (t + 1) : 0;
    for (int jj = jj0; jj < 64; jj++) {
        float lx = fmaxf(xi1, cx1[jj]), ly = fmaxf(yi1, cy1[jj]);
        float rx = fminf(xi2, cx2[jj]), ry = fminf(yi2, cy2[jj]);
        float iw = fmaxf(__fsub_rn(rx, lx), 0.0f);
        float ih = fmaxf(__fsub_rn(ry, ly), 0.0f);
        float inter = __fmul_rn(iw, ih);
        if (inter > 0.0f) {  // division only when boxes overlap
            float denom = __fadd_rn(
                __fsub_rn(__fadd_rn(ai, ca[jj]), inter), 1e-9f);
            if (__fdiv_rn(inter, denom) > 0.3f) word |= (1ULL << jj);
        }
    }
    g_mask[((size_t)b * 2048 + i) * 32 + jt] = word;
}

// ---------------------------------------------------------------------------
// K6b: per-batch serial bitmask scan with smem staging + early exit once the
//      750th keep is reached. Then cumsum -> out col 14. Also zeroes
//      g_hist[b] / g_selcnt[b] for the next run.
// ---------------------------------------------------------------------------
__global__ void k_serial(float* __restrict__ out) {
    extern __shared__ unsigned long long sbuf[];   // 2 * 128 * 32 ull = 64KB
    __shared__ unsigned long long initm[32];
    __shared__ unsigned long long keepm[32];
    __shared__ float ss[2048];
    __shared__ int wtot[33];
    __shared__ int s_kept, s_done;
    int b = blockIdx.x;
    int tid = threadIdx.x;
    int warp = tid >> 5, lane = tid & 31;

    for (int r = tid; r < 2048; r += 1024) {
        unsigned long long kk = g_top[b * 2048 + r];
        float sc = __uint_as_float((unsigned)(kk >> 32));
        ss[r] = (r < TOPK) ? sc : 0.0f;
    }
    if (tid < NBINS) g_hist[b * NBINS + tid] = 0;
    if (tid == 0) { g_selcnt[b] = 0; s_kept = 0; s_done = 0; }
    __syncthreads();

    unsigned lo = __ballot_sync(0xffffffffu, ss[warp * 64 + lane] > 0.0f);
    unsigned hi = __ballot_sync(0xffffffffu, ss[warp * 64 + 32 + lane] > 0.0f);
    if (lane == 0) initm[warp] = ((unsigned long long)hi << 32) | lo;

    const unsigned long long* mrow = g_mask + (size_t)b * 2048 * 32;
    for (int k = tid; k < 4096; k += 1024) sbuf[k] = mrow[k];
    __syncthreads();

    unsigned long long removed = ~initm[lane];  // bit set = inactive
    int done_chunks = 16;
    for (int c = 0; c < 16; c++) {
        int pb = (c & 1) * 4096;
        if (warp != 0 && c + 1 < 16) {
            int nb = ((c + 1) & 1) * 4096;
            const unsigned long long* src = mrow + (size_t)(c + 1) * 4096;
            for (int k = tid - 32; k < 4096; k += 992)
                sbuf[nb + k] = src[k];
        }
        if (warp == 0) {
            unsigned long long rm_w = 0;
#pragma unroll 8
            for (int il = 0; il < 128; il++) {
                int i = c * 128 + il;
                int w = i >> 6, bit = i & 63;
                if (bit == 0) rm_w = __shfl_sync(0xffffffffu, removed, w);
                unsigned long long own = sbuf[pb + il * 32 + lane];
                unsigned long long bc  = sbuf[pb + il * 32 + w];
                unsigned long long msk = ~(unsigned long long)(
                    ((long long)(rm_w << (63 - bit))) >> 63);
                removed |= own & msk;
                rm_w |= bc & msk;
            }
            unsigned long long r0 = __shfl_sync(0xffffffffu, removed, 2 * c);
            unsigned long long r1 = __shfl_sync(0xffffffffu, removed, 2 * c + 1);
            if (lane == 0) {
                s_kept += __popcll(~r0) + __popcll(~r1);
                if (s_kept >= KEEPK && s_done == 0) s_done = c + 1;
            }
        }
        __syncthreads();
        if (s_done) { done_chunks = s_done; break; }
    }
    if (warp == 0) {
        int wlim = 2 * done_chunks;
        keepm[lane] = (lane < wlim) ? ~removed : 0ULL;
    }
    __syncthreads();

    int e0 = 2 * tid, e1 = 2 * tid + 1;
    int a0 = (int)((keepm[e0 >> 6] >> (e0 & 63)) & 1ULL);
    int a1 = (int)((keepm[e1 >> 6] >> (e1 & 63)) & 1ULL);
    int ps = a0 + a1;
    int v = ps;
#pragma unroll
    for (int o = 1; o < 32; o <<= 1) {
        int u = __shfl_up_sync(0xffffffffu, v, o);
        if (lane >= o) v += u;
    }
    if (lane == 31) wtot[warp] = v;
    __syncthreads();
    if (warp == 0) {
        int w = wtot[lane];
#pragma unroll
        for (int o = 1; o < 32; o <<= 1) {
            int u = __shfl_up_sync(0xffffffffu, w, o);
            if (lane >= o) w += u;
        }
        wtot[lane] = w;
    }
    __syncthreads();
    int base = (warp ? wtot[warp - 1] : 0) + v - ps;
    int c0 = base + a0;
    int c1 = c0 + a1;
    if (e0 < TOPK)
        out[((size_t)b * TOPK + e0) * 15 + 14] =
            ss[e0] * ((a0 && c0 <= KEEPK) ? 1.0f : 0.0f);
    if (e1 < TOPK)
        out[((size_t)b * TOPK + e1) * 15 + 14] =
            ss[e1] * ((a1 && c1 <= KEEPK) ? 1.0f : 0.0f);
}

// ---------------------------------------------------------------------------
extern "C" void kernel_launch(void* const* d_in, const int* in_sizes, int n_in,
                              void* d_out, int out_size) {
    const float* loc = nullptr;
    const float* conf = nullptr;
    const float* iou = nullptr;
    for (int i = 0; i < n_in; i++) {
        if (in_sizes[i] == NBATCH * NPRI * 14) loc = (const float*)d_in[i];
        else if (in_sizes[i] == NBATCH * NPRI * 2) conf = (const float*)d_in[i];
        else if (in_sizes[i] == NBATCH * NPRI) iou = (const float*)d_in[i];
    }
    float* out = (float*)d_out;

    dim3 ghalf((NPRI / 2 + 255) / 256, NBATCH);
    k_scores<<<ghalf, 256>>>(conf, iou);
    k_compact<<<ghalf, 256>>>(conf, iou);

    k_sortchunk<<<dim3(4, NBATCH), 1024>>>();

    cudaFuncSetAttribute(k_merge, cudaFuncAttributeMaxDynamicSharedMemorySize,
                         98304);
    k_merge<<<NBATCH, 1024, 98304>>>();

    k_decode<<<(NBATCH * TOPK * 2 + 255) / 256, 256>>>(loc, out);

    k_mask<<<dim3(528, NBATCH), 64>>>();

    cudaFuncSetAttribute(k_serial, cudaFuncAttributeMaxDynamicSharedMemorySize,
                         65536);
    k_serial<<<NBATCH, 1024, 65536>>>(out);
}